// round 10
// baseline (speedup 1.0000x reference)
#include <cuda_runtime.h>
#include <cuda_bf16.h>
#include <math.h>

#define Bb   4
#define Nn   2048
#define Ss   256
#define Cc   64
#define Hh   4
#define Dd   64
#define Ff   1024
#define ROWS (Bb*Nn)          // 8192

// ---------------- scratch (static device memory; no allocations) -------------
__device__ float g_sn[ROWS*Ss];
__device__ float g_vn[ROWS*Cc*3];
__device__ float g_q[ROWS*Ss];
__device__ float g_k[ROWS*Ss];
__device__ float g_vp[ROWS*Ss];
__device__ float g_vmix[ROWS*Cc*3];
__device__ __nv_bfloat16 g_probs[(size_t)Bb*Hh*Nn*Nn];   // 134 MB unnormalized probs
__device__ float g_linv[(size_t)Bb*Hh*Nn];
__device__ float g_attnmean[(size_t)Bb*Nn*Nn];            // 67 MB
__device__ float g_sattn[ROWS*Ss];
__device__ float g_vattn[ROWS*Cc*3];
__device__ float g_ffn[ROWS*Ff];

// ---------------- eq layernorm ----------------------------------------------
__global__ void __launch_bounds__(256) eqln_kernel(
    const float* __restrict__ sin, const float* __restrict__ vin,
    const float* __restrict__ g, const float* __restrict__ be,
    const float* __restrict__ vsc,
    float* __restrict__ sn, float* __restrict__ vn)
{
    long long row = blockIdx.x;
    int tid = threadIdx.x;
    __shared__ float redA[8], redB[8], norms[64], st[3];

    float x = sin[row*Ss + tid];
    float s1 = x, s2 = x*x;
    #pragma unroll
    for (int o = 16; o; o >>= 1) {
        s1 += __shfl_xor_sync(0xffffffffu, s1, o);
        s2 += __shfl_xor_sync(0xffffffffu, s2, o);
    }
    if ((tid & 31) == 0) { redA[tid>>5] = s1; redB[tid>>5] = s2; }

    if (tid < 64) {
        const float* vp = vin + row*192 + tid*3;
        float a = vp[0], b2 = vp[1], c = vp[2];
        norms[tid] = sqrtf(a*a + b2*b2 + c*c);
    }
    __syncthreads();
    if (tid == 0) {
        float A = 0.f, Bs2 = 0.f;
        #pragma unroll
        for (int w = 0; w < 8; w++) { A += redA[w]; Bs2 += redB[w]; }
        float mu  = A * (1.f/256.f);
        float var = Bs2 * (1.f/256.f) - mu*mu;
        st[0] = mu; st[1] = rsqrtf(var + 1e-5f);
        float t = 0.f;
        for (int c = 0; c < 64; c++) t += norms[c];
        st[2] = t * (1.f/64.f);
    }
    __syncthreads();
    sn[row*Ss + tid] = (x - st[0]) * st[1] * g[tid] + be[tid];
    if (tid < 192) {
        int c = tid / 3;
        vn[row*192 + tid] = vin[row*192 + tid] / (norms[c] + 1e-5f) * st[2] * vsc[c];
    }
}

// ---------------- tf32 tensor-core GEMM: 128x64 CTA, mma.m16n8k8 -------------
// C[m,n] = epi( A[m,:] @ W[:,n] + bias[n] (+ res[m,n]) )
// Requirements: M % 128 == 0, N % 64 == 0, K % 32 == 0.
#define TCK 32
#define AS_LD 132      // [k][m] pad
#define BS_LD 68       // [k][n] pad
#define GEMM_TC_SMEM ((2*TCK*AS_LD + 2*TCK*BS_LD)*4)

__device__ __forceinline__ unsigned f2tf(float x) {
    unsigned r;
    asm("cvt.rna.tf32.f32 %0, %1;" : "=r"(r) : "f"(x));
    return r;
}

__device__ __forceinline__ void mma_tf32(float* c,
    unsigned a0, unsigned a1, unsigned a2, unsigned a3,
    unsigned b0, unsigned b1)
{
    asm volatile(
        "mma.sync.aligned.m16n8k8.row.col.f32.tf32.tf32.f32 "
        "{%0,%1,%2,%3}, {%4,%5,%6,%7}, {%8,%9}, {%0,%1,%2,%3};\n"
        : "+f"(c[0]), "+f"(c[1]), "+f"(c[2]), "+f"(c[3])
        : "r"(a0), "r"(a1), "r"(a2), "r"(a3), "r"(b0), "r"(b1));
}

__global__ void __launch_bounds__(256) gemm_tc_kernel(
    const float* __restrict__ A, const float* __restrict__ W,
    const float* __restrict__ bias, const float* __restrict__ res,
    float* __restrict__ Cout,
    int M, int N, int K, int epi,
    long long sA, long long sW, long long sC)
{
    extern __shared__ float sm_g[];
    float* As = sm_g;                    // [2][TCK][AS_LD]
    float* Bs = sm_g + 2*TCK*AS_LD;      // [2][TCK][BS_LD]

    long long bz = blockIdx.z;
    A += bz * sA; W += bz * sW; Cout += bz * sC;
    const float* resp = res ? res + bz * sC : (const float*)0;

    const int tid = threadIdx.x;
    const int lane = tid & 31, wid = tid >> 5;
    const int wm = (wid >> 1) * 32;      // warp row offset in tile
    const int wn = (wid & 1) * 32;      // warp col offset in tile
    const int m0 = blockIdx.y * 128, n0 = blockIdx.x * 64;
    const int gr = lane >> 2, gc = lane & 3;

    // loader decomposition
    const int arow = tid >> 3;           // 0..31 (+32*i)
    const int aq   = (tid & 7) * 4;      // k quad
    const int wk   = tid >> 4;           // 0..15 (+16*i)
    const int wq   = (tid & 15) * 4;     // n quad

    const float* Aptr = A + (long long)(m0 + arow)*K + aq;
    const float* Wptr = W + (long long)wk*N + n0 + wq;
    const long long aRowStride32 = (long long)32*K;

    float4 ra[4], rw[2];
    #pragma unroll
    for (int i = 0; i < 4; i++) ra[i] = *(const float4*)(Aptr + i*aRowStride32);
    #pragma unroll
    for (int i = 0; i < 2; i++) rw[i] = *(const float4*)(Wptr + (long long)i*16*N);

    // store chunk 0 (tf32-converted)
    #pragma unroll
    for (int i = 0; i < 4; i++) {
        int m = arow + i*32;
        As[(aq+0)*AS_LD + m] = __uint_as_float(f2tf(ra[i].x));
        As[(aq+1)*AS_LD + m] = __uint_as_float(f2tf(ra[i].y));
        As[(aq+2)*AS_LD + m] = __uint_as_float(f2tf(ra[i].z));
        As[(aq+3)*AS_LD + m] = __uint_as_float(f2tf(ra[i].w));
    }
    #pragma unroll
    for (int i = 0; i < 2; i++) {
        int k = wk + i*16;
        float4 cv;
        cv.x = __uint_as_float(f2tf(rw[i].x));
        cv.y = __uint_as_float(f2tf(rw[i].y));
        cv.z = __uint_as_float(f2tf(rw[i].z));
        cv.w = __uint_as_float(f2tf(rw[i].w));
        *(float4*)&Bs[k*BS_LD + wq] = cv;
    }
    __syncthreads();

    float acc[2][4][4];
    #pragma unroll
    for (int mt = 0; mt < 2; mt++)
        #pragma unroll
        for (int nt = 0; nt < 4; nt++)
            #pragma unroll
            for (int j = 0; j < 4; j++) acc[mt][nt][j] = 0.f;

    int buf = 0;
    for (int k0 = 0; k0 < K; k0 += TCK) {
        const bool has_next = (k0 + TCK) < K;
        if (has_next) {
            #pragma unroll
            for (int i = 0; i < 4; i++) ra[i] = *(const float4*)(Aptr + i*aRowStride32 + k0 + TCK);
            #pragma unroll
            for (int i = 0; i < 2; i++) rw[i] = *(const float4*)(Wptr + (long long)(k0 + TCK + i*16)*N);
        }

        const float* Ab = As + buf*TCK*AS_LD;
        const float* Bb2 = Bs + buf*TCK*BS_LD;
        #pragma unroll
        for (int kk = 0; kk < TCK; kk += 8) {
            unsigned af[2][4];
            #pragma unroll
            for (int mt = 0; mt < 2; mt++) {
                int rb = wm + mt*16 + gr;
                af[mt][0] = __float_as_uint(Ab[(kk+gc  )*AS_LD + rb    ]);
                af[mt][1] = __float_as_uint(Ab[(kk+gc  )*AS_LD + rb + 8]);
                af[mt][2] = __float_as_uint(Ab[(kk+gc+4)*AS_LD + rb    ]);
                af[mt][3] = __float_as_uint(Ab[(kk+gc+4)*AS_LD + rb + 8]);
            }
            #pragma unroll
            for (int nt = 0; nt < 4; nt++) {
                int cb = wn + nt*8 + gr;
                unsigned b0 = __float_as_uint(Bb2[(kk+gc  )*BS_LD + cb]);
                unsigned b1 = __float_as_uint(Bb2[(kk+gc+4)*BS_LD + cb]);
                mma_tf32(acc[0][nt], af[0][0], af[0][1], af[0][2], af[0][3], b0, b1);
                mma_tf32(acc[1][nt], af[1][0], af[1][1], af[1][2], af[1][3], b0, b1);
            }
        }

        if (has_next) {
            int nb = buf ^ 1;
            float* An = As + nb*TCK*AS_LD;
            float* Bn = Bs + nb*TCK*BS_LD;
            #pragma unroll
            for (int i = 0; i < 4; i++) {
                int m = arow + i*32;
                An[(aq+0)*AS_LD + m] = __uint_as_float(f2tf(ra[i].x));
                An[(aq+1)*AS_LD + m] = __uint_as_float(f2tf(ra[i].y));
                An[(aq+2)*AS_LD + m] = __uint_as_float(f2tf(ra[i].z));
                An[(aq+3)*AS_LD + m] = __uint_as_float(f2tf(ra[i].w));
            }
            #pragma unroll
            for (int i = 0; i < 2; i++) {
                int k = wk + i*16;
                float4 cv;
                cv.x = __uint_as_float(f2tf(rw[i].x));
                cv.y = __uint_as_float(f2tf(rw[i].y));
                cv.z = __uint_as_float(f2tf(rw[i].z));
                cv.w = __uint_as_float(f2tf(rw[i].w));
                *(float4*)&Bn[k*BS_LD + wq] = cv;
            }
        }
        __syncthreads();
        buf ^= 1;
    }

    // ---- epilogue: C fragment rows (gr, gr+8), cols 2*gc, 2*gc+1 ----
    #pragma unroll
    for (int mt = 0; mt < 2; mt++) {
        #pragma unroll
        for (int nt = 0; nt < 4; nt++) {
            int col = n0 + wn + nt*8 + gc*2;
            float b0 = 0.f, b1 = 0.f;
            if (bias) { b0 = bias[col]; b1 = bias[col+1]; }
            #pragma unroll
            for (int half = 0; half < 2; half++) {
                int m = m0 + wm + mt*16 + gr + half*8;
                long long off = (long long)m*N + col;
                float c0 = acc[mt][nt][half*2+0] + b0;
                float c1 = acc[mt][nt][half*2+1] + b1;
                if (epi == 1) {
                    c0 = 0.5f*c0*(1.0f + erff(c0*0.70710678118654752f));
                    c1 = 0.5f*c1*(1.0f + erff(c1*0.70710678118654752f));
                } else if (epi == 2) {
                    float2 rr = *(const float2*)(resp + off);
                    c0 += rr.x; c1 += rr.y;
                }
                float2 o; o.x = c0; o.y = c1;
                *(float2*)(Cout + off) = o;
            }
        }
    }
}

// ---------------- small per-row channel mixes -------------------------------
__global__ void __launch_bounds__(192) vmix_kernel(
    const float* __restrict__ vn, const float* __restrict__ Wvv, float* __restrict__ out)
{
    long long row = blockIdx.x;
    int tid = threadIdx.x;
    __shared__ float vrow[192];
    vrow[tid] = vn[row*192 + tid];
    __syncthreads();
    int x = tid >> 6, e = tid & 63;
    float acc = 0.f;
    #pragma unroll 8
    for (int c = 0; c < 64; c++) acc += vrow[c*3 + x] * Wvv[c*64 + e];
    out[row*192 + e*3 + x] = acc;
}

__global__ void __launch_bounds__(192) vout_kernel(
    const float* __restrict__ vattn, const float* __restrict__ Wvo,
    const float* __restrict__ vin, float* __restrict__ outv)
{
    long long row = blockIdx.x;
    int tid = threadIdx.x;
    __shared__ float vrow[192];
    vrow[tid] = vattn[row*192 + tid];
    __syncthreads();
    int x = tid >> 6, e = tid & 63;
    float acc = 0.f;
    #pragma unroll 8
    for (int c = 0; c < 64; c++) acc += vrow[c*3 + x] * Wvo[c*64 + e];
    outv[row*192 + e*3 + x] = vin[row*192 + e*3 + x] + acc;
}

__global__ void __launch_bounds__(256) vffn_kernel(
    const float* __restrict__ vn, const float* __restrict__ Wfv1,
    const float* __restrict__ Wfv2, float* __restrict__ outv)
{
    long long row = blockIdx.x;
    int tid = threadIdx.x;
    __shared__ float vrow[192];
    __shared__ float t[3][256];
    if (tid < 192) vrow[tid] = vn[row*192 + tid];
    __syncthreads();
    #pragma unroll
    for (int x = 0; x < 3; x++) {
        float acc = 0.f;
        #pragma unroll 8
        for (int c = 0; c < 64; c++) acc += vrow[c*3 + x] * Wfv1[c*256 + tid];
        t[x][tid] = acc;
    }
    __syncthreads();
    if (tid < 192) {
        int x = tid >> 6, c = tid & 63;
        float acc = 0.f;
        #pragma unroll 8
        for (int h = 0; h < 256; h++) acc += t[x][h] * Wfv2[h*64 + c];
        outv[row*192 + c*3 + x] += acc;
    }
}

// ---------------- fused single-pass attention --------------------------------
#define QT_LD 68
#define KT_LD 36
#define PS_LD 33
#define ATTN_SMEM_FLOATS (256*QT_LD + 256*KT_LD + 8192 + 4*64*PS_LD + 256 + 128 + 256)

__global__ void __launch_bounds__(512) attn_kernel(
    const float* __restrict__ qg, const float* __restrict__ kg,
    const float* __restrict__ vg, const float* __restrict__ pos,
    const float* __restrict__ wdist, const float* __restrict__ bdist,
    __nv_bfloat16* __restrict__ probsG, float* __restrict__ linvG,
    float* __restrict__ sattn)
{
    extern __shared__ float sm[];
    float* qT     = sm;                       // [256][68]
    float* kT     = qT + 256*QT_LD;           // [256][36]
    float* v_s    = kT + 256*KT_LD;           // [32][256]
    float* ps     = v_s + 8192;               // [4*64][33]
    float* posi   = ps + 4*64*PS_LD;          // [64][4]
    float* posm   = posi + 256;               // [32][4]
    float* linv_s = posm + 128;               // [4][64]

    const int b  = blockIdx.y;
    const int n0 = blockIdx.x * 64;
    const int tid = threadIdx.x;
    const int lane = tid & 31, wrp = tid >> 5;
    const long long bofs = (long long)b * Nn;

    const int h   = tid >> 7;
    const int r   = tid & 127;
    const int ti  = r >> 3, tm = r & 7;
    const int i0q = ti*4, m0q = tm*4;
    const int cv0 = (wrp & 7)*32 + (lane & 3)*8;
    const int i0p = (wrp >> 3)*32 + (lane >> 2)*4;
    const int hp  = (wrp & 7) >> 1;

    for (int idx = tid; idx < 16384; idx += 512) {
        int i = idx >> 8, d = idx & 255;
        qT[d*QT_LD + i] = qg[(bofs + n0 + i)*Ss + d];
    }
    if (tid < 64) {
        const float* pp = pos + (bofs + n0 + tid)*3;
        float a = pp[0], b2 = pp[1], c = pp[2];
        posi[tid*4+0]=a; posi[tid*4+1]=b2; posi[tid*4+2]=c; posi[tid*4+3]=a*a+b2*b2+c*c;
    }
    __syncthreads();

    float4 pi[4];
    #pragma unroll
    for (int ii = 0; ii < 4; ii++) pi[ii] = ((const float4*)posi)[i0q+ii];
    const float wh = wdist[h], bh = bdist[h];

    float accS[32];
    #pragma unroll
    for (int t = 0; t < 32; t++) accS[t] = 0.f;
    float rs[4] = {0.f, 0.f, 0.f, 0.f};

    __nv_bfloat16* pgbase = probsG + ((size_t)(b*4 + h)*Nn + n0)*Nn;
    const float* qb = qT + (h*64)*QT_LD + i0q;
    const float* kb = kT + (h*64)*KT_LD + m0q;

    for (int mt = 0; mt < 64; mt++) {
        const int m0g = mt*32;
        __syncthreads();
        for (int idx = tid; idx < 8192; idx += 512) {
            int m = idx >> 8, d = idx & 255;
            long long grow = (bofs + m0g + m)*Ss + d;
            kT[d*KT_LD + m] = kg[grow];
            v_s[idx] = vg[grow];
        }
        if (tid < 32) {
            const float* pp = pos + (bofs + m0g + tid)*3;
            float a = pp[0], b2 = pp[1], c = pp[2];
            posm[tid*4+0]=a; posm[tid*4+1]=b2; posm[tid*4+2]=c; posm[tid*4+3]=a*a+b2*b2+c*c;
        }
        __syncthreads();

        float acc[4][4];
        #pragma unroll
        for (int i = 0; i < 4; i++)
            #pragma unroll
            for (int j = 0; j < 4; j++) acc[i][j] = 0.f;

        #pragma unroll 16
        for (int d = 0; d < 64; d++) {
            float4 qv = *(const float4*)(qb + d*QT_LD);
            float4 kv = *(const float4*)(kb + d*KT_LD);
            float qa[4] = {qv.x, qv.y, qv.z, qv.w};
            float ka[4] = {kv.x, kv.y, kv.z, kv.w};
            #pragma unroll
            for (int i = 0; i < 4; i++)
                #pragma unroll
                for (int j = 0; j < 4; j++)
                    acc[i][j] += qa[i]*ka[j];
        }

        float4 pmv[4];
        #pragma unroll
        for (int mj = 0; mj < 4; mj++) pmv[mj] = ((const float4*)posm)[m0q+mj];

        #pragma unroll
        for (int ii = 0; ii < 4; ii++) {
            float pv[4];
            #pragma unroll
            for (int mj = 0; mj < 4; mj++) {
                float d2 = pi[ii].w + pmv[mj].w
                         - 2.f*(pi[ii].x*pmv[mj].x + pi[ii].y*pmv[mj].y + pi[ii].z*pmv[mj].z);
                float dist = sqrtf(fmaxf(d2, 1e-12f));
                float sx = dist*wh + bh;
                float sg = __fdividef(1.f, 1.f + __expf(sx));
                float p  = __expf(acc[ii][mj]*0.125f) * sg;
                pv[mj] = p;
                rs[ii] += p;
                ps[(h*64 + i0q + ii)*PS_LD + m0q + mj] = p;
            }
            __nv_bfloat162 p01 = __floats2bfloat162_rn(pv[0], pv[1]);
            __nv_bfloat162 p23 = __floats2bfloat162_rn(pv[2], pv[3]);
            float2 packed = make_float2(__uint_as_float(*(unsigned int*)&p01),
                                        __uint_as_float(*(unsigned int*)&p23));
            __stcs(reinterpret_cast<float2*>(pgbase + (size_t)(i0q+ii)*Nn + m0g + m0q), packed);
        }
        __syncthreads();

        #pragma unroll 4
        for (int j = 0; j < 32; j++) {
            float4 v0 = *(const float4*)(v_s + j*256 + cv0);
            float4 v1 = *(const float4*)(v_s + j*256 + cv0 + 4);
            float pj[4];
            #pragma unroll
            for (int ii = 0; ii < 4; ii++)
                pj[ii] = ps[(hp*64 + i0p + ii)*PS_LD + j];
            #pragma unroll
            for (int ii = 0; ii < 4; ii++) {
                accS[ii*8+0] += pj[ii]*v0.x; accS[ii*8+1] += pj[ii]*v0.y;
                accS[ii*8+2] += pj[ii]*v0.z; accS[ii*8+3] += pj[ii]*v0.w;
                accS[ii*8+4] += pj[ii]*v1.x; accS[ii*8+5] += pj[ii]*v1.y;
                accS[ii*8+6] += pj[ii]*v1.z; accS[ii*8+7] += pj[ii]*v1.w;
            }
        }
    }

    #pragma unroll
    for (int ii = 0; ii < 4; ii++) {
        float v = rs[ii];
        v += __shfl_xor_sync(0xffffffffu, v, 1);
        v += __shfl_xor_sync(0xffffffffu, v, 2);
        v += __shfl_xor_sync(0xffffffffu, v, 4);
        rs[ii] = v;
    }
    if ((lane & 7) == 0) {
        #pragma unroll
        for (int ii = 0; ii < 4; ii++) {
            float inv = __fdividef(1.f, rs[ii]);
            linv_s[h*64 + i0q + ii] = inv;
            linvG[(size_t)(b*4 + h)*Nn + n0 + i0q + ii] = inv;
        }
    }
    __syncthreads();

    #pragma unroll
    for (int ii = 0; ii < 4; ii++) {
        int i = i0p + ii;
        float li = linv_s[hp*64 + i];
        float4 o0 = make_float4(accS[ii*8+0]*li, accS[ii*8+1]*li, accS[ii*8+2]*li, accS[ii*8+3]*li);
        float4 o1 = make_float4(accS[ii*8+4]*li, accS[ii*8+5]*li, accS[ii*8+6]*li, accS[ii*8+7]*li);
        float* op = sattn + (bofs + n0 + i)*Ss + cv0;
        *(float4*)op = o0;
        *(float4*)(op+4) = o1;
    }
}

// ---------------- attn_mean from bf16 probs + linv ---------------------------
__global__ void __launch_bounds__(512) mean_kernel(
    const __nv_bfloat16* __restrict__ pg, const float* __restrict__ linvG,
    float* __restrict__ am)
{
    const int i = blockIdx.x;
    const int b = blockIdx.y;
    const size_t pstride = (size_t)Nn*Nn;
    const __nv_bfloat16* base = pg + (size_t)b*4*pstride + (size_t)i*Nn;
    const float l0 = 0.25f * linvG[(size_t)(b*4+0)*Nn + i];
    const float l1 = 0.25f * linvG[(size_t)(b*4+1)*Nn + i];
    const float l2 = 0.25f * linvG[(size_t)(b*4+2)*Nn + i];
    const float l3 = 0.25f * linvG[(size_t)(b*4+3)*Nn + i];
    const int j = threadIdx.x * 4;

    float4 o;
    #pragma unroll
    for (int t = 0; t < 2; t++) {
        __nv_bfloat162 a0 = *(const __nv_bfloat162*)(base + j + 2*t);
        __nv_bfloat162 a1 = *(const __nv_bfloat162*)(base + pstride   + j + 2*t);
        __nv_bfloat162 a2 = *(const __nv_bfloat162*)(base + 2*pstride + j + 2*t);
        __nv_bfloat162 a3 = *(const __nv_bfloat162*)(base + 3*pstride + j + 2*t);
        float lo = l0*__low2float(a0)  + l1*__low2float(a1)  + l2*__low2float(a2)  + l3*__low2float(a3);
        float hi = l0*__high2float(a0) + l1*__high2float(a1) + l2*__high2float(a2) + l3*__high2float(a3);
        if (t == 0) { o.x = lo; o.y = hi; } else { o.z = lo; o.w = hi; }
    }
    *reinterpret_cast<float4*>(am + ((size_t)b*Nn + i)*Nn + j) = o;
}

// ---------------- launch ------------------------------------------------------
extern "C" void kernel_launch(void* const* d_in, const int* in_sizes, int n_in,
                              void* d_out, int out_size)
{
    const float* s_in  = (const float*)d_in[0];
    const float* v_in  = (const float*)d_in[1];
    const float* pos   = (const float*)d_in[2];
    const float* Wq    = (const float*)d_in[3];
    const float* bq    = (const float*)d_in[4];
    const float* Wk    = (const float*)d_in[5];
    const float* bk    = (const float*)d_in[6];
    const float* Wv    = (const float*)d_in[7];
    const float* bv    = (const float*)d_in[8];
    const float* Wo    = (const float*)d_in[9];
    const float* bo    = (const float*)d_in[10];
    const float* wdist = (const float*)d_in[11];
    const float* bdist = (const float*)d_in[12];
    const float* Wvv   = (const float*)d_in[13];
    const float* Wvo   = (const float*)d_in[14];
    const float* g1    = (const float*)d_in[15];
    const float* be1   = (const float*)d_in[16];
    const float* vs1   = (const float*)d_in[17];
    const float* g2    = (const float*)d_in[18];
    const float* be2   = (const float*)d_in[19];
    const float* vs2   = (const float*)d_in[20];
    const float* Wf1   = (const float*)d_in[21];
    const float* bf1   = (const float*)d_in[22];
    const float* Wf2   = (const float*)d_in[23];
    const float* bf2   = (const float*)d_in[24];
    const float* Wfv1  = (const float*)d_in[25];
    const float* Wfv2  = (const float*)d_in[26];

    float* out_s = (float*)d_out;
    float* out_v = out_s + (size_t)ROWS*Ss;

    void *p_sn, *p_vn, *p_q, *p_k, *p_vp, *p_vmix, *p_pb, *p_li, *p_am, *p_sa, *p_va, *p_ffn;
    cudaGetSymbolAddress(&p_sn, g_sn);
    cudaGetSymbolAddress(&p_vn, g_vn);
    cudaGetSymbolAddress(&p_q,  g_q);
    cudaGetSymbolAddress(&p_k,  g_k);
    cudaGetSymbolAddress(&p_vp, g_vp);
    cudaGetSymbolAddress(&p_vmix, g_vmix);
    cudaGetSymbolAddress(&p_pb, g_probs);
    cudaGetSymbolAddress(&p_li, g_linv);
    cudaGetSymbolAddress(&p_am, g_attnmean);
    cudaGetSymbolAddress(&p_sa, g_sattn);
    cudaGetSymbolAddress(&p_va, g_vattn);
    cudaGetSymbolAddress(&p_ffn, g_ffn);
    float* sn   = (float*)p_sn;   float* vn   = (float*)p_vn;
    float* q    = (float*)p_q;    float* k    = (float*)p_k;
    float* vp   = (float*)p_vp;   float* vmix = (float*)p_vmix;
    __nv_bfloat16* pb = (__nv_bfloat16*)p_pb;
    float* li   = (float*)p_li;   float* am   = (float*)p_am;
    float* sa   = (float*)p_sa;   float* va   = (float*)p_va;
    float* ffn  = (float*)p_ffn;

    const int attn_smem = ATTN_SMEM_FLOATS * 4;
    cudaFuncSetAttribute(attn_kernel, cudaFuncAttributeMaxDynamicSharedMemorySize, attn_smem);
    cudaFuncSetAttribute(gemm_tc_kernel, cudaFuncAttributeMaxDynamicSharedMemorySize, GEMM_TC_SMEM);

    // 1) eq-LN #1
    eqln_kernel<<<ROWS, 256>>>(s_in, v_in, g1, be1, vs1, sn, vn);

    // 2) QKV projections (tf32 tensor cores)
    dim3 gproj(Ss/64, ROWS/128, 1);
    gemm_tc_kernel<<<gproj, 256, GEMM_TC_SMEM>>>(sn, Wq, bq, nullptr, q,  ROWS, Ss, Ss, 0, 0, 0, 0);
    gemm_tc_kernel<<<gproj, 256, GEMM_TC_SMEM>>>(sn, Wk, bk, nullptr, k,  ROWS, Ss, Ss, 0, 0, 0, 0);
    gemm_tc_kernel<<<gproj, 256, GEMM_TC_SMEM>>>(sn, Wv, bv, nullptr, vp, ROWS, Ss, Ss, 0, 0, 0, 0);

    // 3) vector channel mix (vn @ Wvv)
    vmix_kernel<<<ROWS, 192>>>(vn, Wvv, vmix);

    // 4) fused single-pass attention -> sattn, bf16 probs, linv
    attn_kernel<<<dim3(Nn/64, Bb), 512, attn_smem>>>(q, k, vp, pos, wdist, bdist, pb, li, sa);

    // 5) attn_mean from probs + linv
    mean_kernel<<<dim3(Nn, Bb), 512>>>(pb, li, am);

    // 6) out_s = s_in + sattn @ Wo + bo
    gemm_tc_kernel<<<gproj, 256, GEMM_TC_SMEM>>>(sa, Wo, bo, s_in, out_s, ROWS, Ss, Ss, 2, 0, 0, 0);

    // 7) v_attn_raw = attn_mean @ vmix  (batched over B)
    gemm_tc_kernel<<<dim3(192/64, Nn/128, Bb), 256, GEMM_TC_SMEM>>>(
        am, vmix, nullptr, nullptr, va,
        Nn, 192, Nn, 0,
        (long long)Nn*Nn, (long long)Nn*192, (long long)Nn*192);

    // 8) out_v = v_in + v_attn_raw @ Wvo
    vout_kernel<<<ROWS, 192>>>(va, Wvo, v_in, out_v);

    // 9) eq-LN #2
    eqln_kernel<<<ROWS, 256>>>(out_s, out_v, g2, be2, vs2, sn, vn);

    // 10) FFN
    gemm_tc_kernel<<<dim3(Ff/64, ROWS/128, 1), 256, GEMM_TC_SMEM>>>(sn, Wf1, bf1, nullptr, ffn, ROWS, Ff, Ss, 1, 0, 0, 0);
    gemm_tc_kernel<<<dim3(Ss/64, ROWS/128, 1), 256, GEMM_TC_SMEM>>>(ffn, Wf2, bf2, out_s, out_s, ROWS, Ss, Ff, 2, 0, 0, 0);

    // 11) vector FFN
    vffn_kernel<<<ROWS, 256>>>(vn, Wfv1, Wfv2, out_v);
}

// round 11
// speedup vs baseline: 1.3504x; 1.3504x over previous
#include <cuda_runtime.h>
#include <cuda_bf16.h>
#include <math.h>

#define Bb   4
#define Nn   2048
#define Ss   256
#define Cc   64
#define Hh   4
#define Dd   64
#define Ff   1024
#define ROWS (Bb*Nn)          // 8192

// ---------------- scratch (static device memory; no allocations) -------------
__device__ float g_sn[ROWS*Ss];
__device__ float g_vn[ROWS*Cc*3];
__device__ float g_q[ROWS*Ss];
__device__ float g_k[ROWS*Ss];
__device__ float g_vp[ROWS*Ss];
__device__ float g_vmix[ROWS*Cc*3];
__device__ __nv_bfloat16 g_probs[(size_t)Bb*Hh*Nn*Nn];   // 134 MB unnormalized probs
__device__ float g_linv[(size_t)Bb*Hh*Nn];
__device__ float g_sattn[ROWS*Ss];
__device__ float g_vattn[ROWS*Cc*3];
__device__ float g_ffn[ROWS*Ff];

// ---------------- eq layernorm ----------------------------------------------
__global__ void __launch_bounds__(256) eqln_kernel(
    const float* __restrict__ sin, const float* __restrict__ vin,
    const float* __restrict__ g, const float* __restrict__ be,
    const float* __restrict__ vsc,
    float* __restrict__ sn, float* __restrict__ vn)
{
    long long row = blockIdx.x;
    int tid = threadIdx.x;
    __shared__ float redA[8], redB[8], norms[64], st[3];

    float x = sin[row*Ss + tid];
    float s1 = x, s2 = x*x;
    #pragma unroll
    for (int o = 16; o; o >>= 1) {
        s1 += __shfl_xor_sync(0xffffffffu, s1, o);
        s2 += __shfl_xor_sync(0xffffffffu, s2, o);
    }
    if ((tid & 31) == 0) { redA[tid>>5] = s1; redB[tid>>5] = s2; }

    if (tid < 64) {
        const float* vp = vin + row*192 + tid*3;
        float a = vp[0], b2 = vp[1], c = vp[2];
        norms[tid] = sqrtf(a*a + b2*b2 + c*c);
    }
    __syncthreads();
    if (tid == 0) {
        float A = 0.f, Bs2 = 0.f;
        #pragma unroll
        for (int w = 0; w < 8; w++) { A += redA[w]; Bs2 += redB[w]; }
        float mu  = A * (1.f/256.f);
        float var = Bs2 * (1.f/256.f) - mu*mu;
        st[0] = mu; st[1] = rsqrtf(var + 1e-5f);
        float t = 0.f;
        for (int c = 0; c < 64; c++) t += norms[c];
        st[2] = t * (1.f/64.f);
    }
    __syncthreads();
    sn[row*Ss + tid] = (x - st[0]) * st[1] * g[tid] + be[tid];
    if (tid < 192) {
        int c = tid / 3;
        vn[row*192 + tid] = vin[row*192 + tid] / (norms[c] + 1e-5f) * st[2] * vsc[c];
    }
}

// ---------------- fp32 SIMT GEMM (R9): 128x64 CTA tile, 8x4 per thread -------
#define GBM 128
#define GBN 64
#define GBK 16

__global__ void __launch_bounds__(256) gemm_kernel(
    const float* __restrict__ A, const float* __restrict__ W,
    const float* __restrict__ bias, const float* __restrict__ res,
    float* __restrict__ Cout,
    int M, int N, int K, int epi,
    long long sA, long long sW, long long sC)
{
    long long bz = blockIdx.z;
    A += bz * sA; W += bz * sW; Cout += bz * sC;
    const float* resp = res ? res + bz * sC : (const float*)0;

    __shared__ float As[2][GBK][GBM+4];
    __shared__ float Bs[2][GBK][GBN+4];

    const int tid = threadIdx.x;
    const int tx = tid & 15, ty = tid >> 4;
    const int m0 = blockIdx.y * GBM, n0 = blockIdx.x * GBN;

    const int arow = tid >> 2;
    const int akk  = (tid & 3) * 4;
    const int brow = tid >> 4;
    const int bn4  = (tid & 15) * 4;

    const float* Aptr = A + (long long)(m0 + arow)*K + akk;
    const float* Wptr = W + (long long)brow*N + n0 + bn4;
    const long long a64 = (long long)64*K;

    float4 ra0 = *(const float4*)(Aptr);
    float4 ra1 = *(const float4*)(Aptr + a64);
    float4 rb  = *(const float4*)(Wptr);

    As[0][akk+0][arow] = ra0.x; As[0][akk+1][arow] = ra0.y;
    As[0][akk+2][arow] = ra0.z; As[0][akk+3][arow] = ra0.w;
    As[0][akk+0][arow+64] = ra1.x; As[0][akk+1][arow+64] = ra1.y;
    As[0][akk+2][arow+64] = ra1.z; As[0][akk+3][arow+64] = ra1.w;
    *(float4*)&Bs[0][brow][bn4] = rb;
    __syncthreads();

    float acc[8][4];
    #pragma unroll
    for (int i = 0; i < 8; i++)
        #pragma unroll
        for (int j = 0; j < 4; j++) acc[i][j] = 0.f;

    int buf = 0;
    for (int k0 = 0; k0 < K; k0 += GBK) {
        const bool has_next = (k0 + GBK) < K;
        if (has_next) {
            ra0 = *(const float4*)(Aptr + k0 + GBK);
            ra1 = *(const float4*)(Aptr + a64 + k0 + GBK);
            rb  = *(const float4*)(Wptr + (long long)(k0 + GBK)*N);
        }
        #pragma unroll
        for (int k = 0; k < GBK; k++) {
            float4 af0 = *(const float4*)&As[buf][k][ty*8];
            float4 af1 = *(const float4*)&As[buf][k][ty*8+4];
            float4 bf  = *(const float4*)&Bs[buf][k][tx*4];
            float a[8] = {af0.x,af0.y,af0.z,af0.w,af1.x,af1.y,af1.z,af1.w};
            float b[4] = {bf.x,bf.y,bf.z,bf.w};
            #pragma unroll
            for (int i = 0; i < 8; i++)
                #pragma unroll
                for (int j = 0; j < 4; j++)
                    acc[i][j] += a[i]*b[j];
        }
        if (has_next) {
            int nb = buf ^ 1;
            As[nb][akk+0][arow] = ra0.x; As[nb][akk+1][arow] = ra0.y;
            As[nb][akk+2][arow] = ra0.z; As[nb][akk+3][arow] = ra0.w;
            As[nb][akk+0][arow+64] = ra1.x; As[nb][akk+1][arow+64] = ra1.y;
            As[nb][akk+2][arow+64] = ra1.z; As[nb][akk+3][arow+64] = ra1.w;
            *(float4*)&Bs[nb][brow][bn4] = rb;
        }
        __syncthreads();
        buf ^= 1;
    }

    float bv[4];
    if (bias) {
        #pragma unroll
        for (int j = 0; j < 4; j++) bv[j] = bias[n0 + tx*4 + j];
    } else {
        #pragma unroll
        for (int j = 0; j < 4; j++) bv[j] = 0.f;
    }
    #pragma unroll
    for (int i = 0; i < 8; i++) {
        int m = m0 + ty*8 + i;
        long long off = (long long)m*N + n0 + tx*4;
        float4 o;
        float c0 = acc[i][0]+bv[0], c1 = acc[i][1]+bv[1];
        float c2 = acc[i][2]+bv[2], c3 = acc[i][3]+bv[3];
        if (epi == 1) {
            c0 = 0.5f*c0*(1.0f + erff(c0*0.70710678118654752f));
            c1 = 0.5f*c1*(1.0f + erff(c1*0.70710678118654752f));
            c2 = 0.5f*c2*(1.0f + erff(c2*0.70710678118654752f));
            c3 = 0.5f*c3*(1.0f + erff(c3*0.70710678118654752f));
        } else if (epi == 2) {
            float4 rr = *(const float4*)(resp + off);
            c0 += rr.x; c1 += rr.y; c2 += rr.z; c3 += rr.w;
        }
        o.x = c0; o.y = c1; o.z = c2; o.w = c3;
        *(float4*)(Cout + off) = o;
    }
}

// ---------------- tf32 tensor-core GEMM (QKV/Wo shapes) ----------------------
#define TCK 32
#define AS_LD 132
#define BS_LD 68
#define GEMM_TC_SMEM ((2*TCK*AS_LD + 2*TCK*BS_LD)*4)

__device__ __forceinline__ unsigned f2tf(float x) {
    unsigned r;
    asm("cvt.rna.tf32.f32 %0, %1;" : "=r"(r) : "f"(x));
    return r;
}

__device__ __forceinline__ void mma_tf32(float* c,
    unsigned a0, unsigned a1, unsigned a2, unsigned a3,
    unsigned b0, unsigned b1)
{
    asm volatile(
        "mma.sync.aligned.m16n8k8.row.col.f32.tf32.tf32.f32 "
        "{%0,%1,%2,%3}, {%4,%5,%6,%7}, {%8,%9}, {%0,%1,%2,%3};\n"
        : "+f"(c[0]), "+f"(c[1]), "+f"(c[2]), "+f"(c[3])
        : "r"(a0), "r"(a1), "r"(a2), "r"(a3), "r"(b0), "r"(b1));
}

__global__ void __launch_bounds__(256) gemm_tc_kernel(
    const float* __restrict__ A, const float* __restrict__ W,
    const float* __restrict__ bias, const float* __restrict__ res,
    float* __restrict__ Cout,
    int M, int N, int K, int epi)
{
    extern __shared__ float sm_g[];
    float* As = sm_g;
    float* Bs = sm_g + 2*TCK*AS_LD;

    const float* resp = res;

    const int tid = threadIdx.x;
    const int lane = tid & 31, wid = tid >> 5;
    const int wm = (wid >> 1) * 32;
    const int wn = (wid & 1) * 32;
    const int m0 = blockIdx.y * 128, n0 = blockIdx.x * 64;
    const int gr = lane >> 2, gc = lane & 3;

    const int arow = tid >> 3;
    const int aq   = (tid & 7) * 4;
    const int wk   = tid >> 4;
    const int wq   = (tid & 15) * 4;

    const float* Aptr = A + (long long)(m0 + arow)*K + aq;
    const float* Wptr = W + (long long)wk*N + n0 + wq;
    const long long aRowStride32 = (long long)32*K;

    float4 ra[4], rw[2];
    #pragma unroll
    for (int i = 0; i < 4; i++) ra[i] = *(const float4*)(Aptr + i*aRowStride32);
    #pragma unroll
    for (int i = 0; i < 2; i++) rw[i] = *(const float4*)(Wptr + (long long)i*16*N);

    #pragma unroll
    for (int i = 0; i < 4; i++) {
        int m = arow + i*32;
        As[(aq+0)*AS_LD + m] = __uint_as_float(f2tf(ra[i].x));
        As[(aq+1)*AS_LD + m] = __uint_as_float(f2tf(ra[i].y));
        As[(aq+2)*AS_LD + m] = __uint_as_float(f2tf(ra[i].z));
        As[(aq+3)*AS_LD + m] = __uint_as_float(f2tf(ra[i].w));
    }
    #pragma unroll
    for (int i = 0; i < 2; i++) {
        int k = wk + i*16;
        float4 cv;
        cv.x = __uint_as_float(f2tf(rw[i].x));
        cv.y = __uint_as_float(f2tf(rw[i].y));
        cv.z = __uint_as_float(f2tf(rw[i].z));
        cv.w = __uint_as_float(f2tf(rw[i].w));
        *(float4*)&Bs[k*BS_LD + wq] = cv;
    }
    __syncthreads();

    float acc[2][4][4];
    #pragma unroll
    for (int mt = 0; mt < 2; mt++)
        #pragma unroll
        for (int nt = 0; nt < 4; nt++)
            #pragma unroll
            for (int j = 0; j < 4; j++) acc[mt][nt][j] = 0.f;

    int buf = 0;
    for (int k0 = 0; k0 < K; k0 += TCK) {
        const bool has_next = (k0 + TCK) < K;
        if (has_next) {
            #pragma unroll
            for (int i = 0; i < 4; i++) ra[i] = *(const float4*)(Aptr + i*aRowStride32 + k0 + TCK);
            #pragma unroll
            for (int i = 0; i < 2; i++) rw[i] = *(const float4*)(Wptr + (long long)(k0 + TCK + i*16)*N);
        }

        const float* Ab = As + buf*TCK*AS_LD;
        const float* Bb2 = Bs + buf*TCK*BS_LD;
        #pragma unroll
        for (int kk = 0; kk < TCK; kk += 8) {
            unsigned af[2][4];
            #pragma unroll
            for (int mt = 0; mt < 2; mt++) {
                int rb = wm + mt*16 + gr;
                af[mt][0] = __float_as_uint(Ab[(kk+gc  )*AS_LD + rb    ]);
                af[mt][1] = __float_as_uint(Ab[(kk+gc  )*AS_LD + rb + 8]);
                af[mt][2] = __float_as_uint(Ab[(kk+gc+4)*AS_LD + rb    ]);
                af[mt][3] = __float_as_uint(Ab[(kk+gc+4)*AS_LD + rb + 8]);
            }
            #pragma unroll
            for (int nt = 0; nt < 4; nt++) {
                int cb = wn + nt*8 + gr;
                unsigned b0 = __float_as_uint(Bb2[(kk+gc  )*BS_LD + cb]);
                unsigned b1 = __float_as_uint(Bb2[(kk+gc+4)*BS_LD + cb]);
                mma_tf32(acc[0][nt], af[0][0], af[0][1], af[0][2], af[0][3], b0, b1);
                mma_tf32(acc[1][nt], af[1][0], af[1][1], af[1][2], af[1][3], b0, b1);
            }
        }

        if (has_next) {
            int nb = buf ^ 1;
            float* An = As + nb*TCK*AS_LD;
            float* Bn = Bs + nb*TCK*BS_LD;
            #pragma unroll
            for (int i = 0; i < 4; i++) {
                int m = arow + i*32;
                An[(aq+0)*AS_LD + m] = __uint_as_float(f2tf(ra[i].x));
                An[(aq+1)*AS_LD + m] = __uint_as_float(f2tf(ra[i].y));
                An[(aq+2)*AS_LD + m] = __uint_as_float(f2tf(ra[i].z));
                An[(aq+3)*AS_LD + m] = __uint_as_float(f2tf(ra[i].w));
            }
            #pragma unroll
            for (int i = 0; i < 2; i++) {
                int k = wk + i*16;
                float4 cv;
                cv.x = __uint_as_float(f2tf(rw[i].x));
                cv.y = __uint_as_float(f2tf(rw[i].y));
                cv.z = __uint_as_float(f2tf(rw[i].z));
                cv.w = __uint_as_float(f2tf(rw[i].w));
                *(float4*)&Bn[k*BS_LD + wq] = cv;
            }
        }
        __syncthreads();
        buf ^= 1;
    }

    #pragma unroll
    for (int mt = 0; mt < 2; mt++) {
        #pragma unroll
        for (int nt = 0; nt < 4; nt++) {
            int col = n0 + wn + nt*8 + gc*2;
            float b0 = 0.f, b1 = 0.f;
            if (bias) { b0 = bias[col]; b1 = bias[col+1]; }
            #pragma unroll
            for (int half = 0; half < 2; half++) {
                int m = m0 + wm + mt*16 + gr + half*8;
                long long off = (long long)m*N + col;
                float c0 = acc[mt][nt][half*2+0] + b0;
                float c1 = acc[mt][nt][half*2+1] + b1;
                if (epi == 2) {
                    float2 rr = *(const float2*)(resp + off);
                    c0 += rr.x; c1 += rr.y;
                }
                float2 o; o.x = c0; o.y = c1;
                *(float2*)(Cout + off) = o;
            }
        }
    }
}

// ---------------- fused vattn: (0.25*sum_h linv*probs) @ vmix, tf32 MMA ------
// CTA: 64 rows x 192 cols, 8 warps (2 m-blocks x 4 n-blocks of 48).
#define VAT_AS_LD 68
#define VAT_BS_LD 196
#define VATTN_SMEM ((2*TCK*VAT_AS_LD + 2*TCK*VAT_BS_LD + 256)*4)

__global__ void __launch_bounds__(256) vattn_tc_kernel(
    const __nv_bfloat16* __restrict__ pg, const float* __restrict__ linvG,
    const float* __restrict__ vmix, float* __restrict__ va)
{
    extern __shared__ float sv[];
    float* As = sv;                               // [2][32][68]
    float* Bs = sv + 2*TCK*VAT_AS_LD;             // [2][32][196]
    float* linv_s = Bs + 2*TCK*VAT_BS_LD;         // [4][64]

    const int b  = blockIdx.y;
    const int i0 = blockIdx.x * 64;
    const int tid = threadIdx.x;
    const int lane = tid & 31, wid = tid >> 5;
    const int wm = (wid >> 2) * 32;               // 0 / 32
    const int wn = (wid & 3) * 48;                // 0 / 48 / 96 / 144
    const int gr = lane >> 2, gc = lane & 3;

    const size_t pstride = (size_t)Nn * Nn;
    const __nv_bfloat16* pb = pg + (size_t)b*4*pstride + (size_t)i0*Nn;
    const float* vb = vmix + (size_t)b*Nn*192;

    {
        int hh = tid >> 6, ii = tid & 63;
        linv_s[hh*64 + ii] = 0.25f * linvG[(size_t)(b*4 + hh)*Nn + i0 + ii];
    }
    __syncthreads();

    // A loader: row = tid>>2 (0..63), kq = (tid&3)*8
    const int arow = tid >> 2;
    const int akq  = (tid & 3) * 8;
    float lr[4];
    #pragma unroll
    for (int h = 0; h < 4; h++) lr[h] = linv_s[h*64 + arow];
    const __nv_bfloat16* arp = pb + (size_t)arow*Nn + akq;

    // B loader: 6 float4 per thread per chunk
    int bk[6], bc[6];
    #pragma unroll
    for (int t = 0; t < 6; t++) {
        int idx = tid + t*256;
        bk[t] = idx / 48;
        bc[t] = (idx - bk[t]*48) * 4;
    }

    uint4 pa[4];
    float4 pbv[6];
    #pragma unroll
    for (int h = 0; h < 4; h++) pa[h] = *(const uint4*)(arp + h*pstride);
    #pragma unroll
    for (int t = 0; t < 6; t++) pbv[t] = *(const float4*)(vb + (size_t)bk[t]*192 + bc[t]);

    // store chunk 0
    {
        float f[8] = {0,0,0,0,0,0,0,0};
        #pragma unroll
        for (int h = 0; h < 4; h++) {
            const __nv_bfloat162* pp2 = (const __nv_bfloat162*)&pa[h];
            float lh = lr[h];
            #pragma unroll
            for (int t = 0; t < 4; t++) {
                float2 xy = __bfloat1622float2(pp2[t]);
                f[t*2+0] += lh*xy.x; f[t*2+1] += lh*xy.y;
            }
        }
        #pragma unroll
        for (int j = 0; j < 8; j++)
            As[(akq+j)*VAT_AS_LD + arow] = __uint_as_float(f2tf(f[j]));
        #pragma unroll
        for (int t = 0; t < 6; t++) {
            float4 cv;
            cv.x = __uint_as_float(f2tf(pbv[t].x));
            cv.y = __uint_as_float(f2tf(pbv[t].y));
            cv.z = __uint_as_float(f2tf(pbv[t].z));
            cv.w = __uint_as_float(f2tf(pbv[t].w));
            *(float4*)&Bs[bk[t]*VAT_BS_LD + bc[t]] = cv;
        }
    }
    __syncthreads();

    float acc[2][6][4];
    #pragma unroll
    for (int mt = 0; mt < 2; mt++)
        #pragma unroll
        for (int nt = 0; nt < 6; nt++)
            #pragma unroll
            for (int j = 0; j < 4; j++) acc[mt][nt][j] = 0.f;

    int buf = 0;
    for (int k0 = 0; k0 < Nn; k0 += TCK) {
        const bool has_next = (k0 + TCK) < Nn;
        if (has_next) {
            #pragma unroll
            for (int h = 0; h < 4; h++) pa[h] = *(const uint4*)(arp + h*pstride + k0 + TCK);
            #pragma unroll
            for (int t = 0; t < 6; t++)
                pbv[t] = *(const float4*)(vb + (size_t)(k0 + TCK + bk[t])*192 + bc[t]);
        }

        const float* Ab  = As + buf*TCK*VAT_AS_LD;
        const float* Bb2 = Bs + buf*TCK*VAT_BS_LD;
        #pragma unroll
        for (int kk = 0; kk < TCK; kk += 8) {
            unsigned af[2][4];
            #pragma unroll
            for (int mt = 0; mt < 2; mt++) {
                int rb = wm + mt*16 + gr;
                af[mt][0] = __float_as_uint(Ab[(kk+gc  )*VAT_AS_LD + rb    ]);
                af[mt][1] = __float_as_uint(Ab[(kk+gc  )*VAT_AS_LD + rb + 8]);
                af[mt][2] = __float_as_uint(Ab[(kk+gc+4)*VAT_AS_LD + rb    ]);
                af[mt][3] = __float_as_uint(Ab[(kk+gc+4)*VAT_AS_LD + rb + 8]);
            }
            #pragma unroll
            for (int nt = 0; nt < 6; nt++) {
                int cb = wn + nt*8 + gr;
                unsigned b0 = __float_as_uint(Bb2[(kk+gc  )*VAT_BS_LD + cb]);
                unsigned b1 = __float_as_uint(Bb2[(kk+gc+4)*VAT_BS_LD + cb]);
                mma_tf32(acc[0][nt], af[0][0], af[0][1], af[0][2], af[0][3], b0, b1);
                mma_tf32(acc[1][nt], af[1][0], af[1][1], af[1][2], af[1][3], b0, b1);
            }
        }

        if (has_next) {
            int nb = buf ^ 1;
            float* An = As + nb*TCK*VAT_AS_LD;
            float* Bn = Bs + nb*TCK*VAT_BS_LD;
            float f[8] = {0,0,0,0,0,0,0,0};
            #pragma unroll
            for (int h = 0; h < 4; h++) {
                const __nv_bfloat162* pp2 = (const __nv_bfloat162*)&pa[h];
                float lh = lr[h];
                #pragma unroll
                for (int t = 0; t < 4; t++) {
                    float2 xy = __bfloat1622float2(pp2[t]);
                    f[t*2+0] += lh*xy.x; f[t*2+1] += lh*xy.y;
                }
            }
            #pragma unroll
            for (int j = 0; j < 8; j++)
                An[(akq+j)*VAT_AS_LD + arow] = __uint_as_float(f2tf(f[j]));
            #pragma unroll
            for (int t = 0; t < 6; t++) {
                float4 cv;
                cv.x = __uint_as_float(f2tf(pbv[t].x));
                cv.y = __uint_as_float(f2tf(pbv[t].y));
                cv.z = __uint_as_float(f2tf(pbv[t].z));
                cv.w = __uint_as_float(f2tf(pbv[t].w));
                *(float4*)&Bn[bk[t]*VAT_BS_LD + bc[t]] = cv;
            }
        }
        __syncthreads();
        buf ^= 1;
    }

    // epilogue -> va[(b*Nn + i0 + m)*192 + col]
    #pragma unroll
    for (int mt = 0; mt < 2; mt++) {
        #pragma unroll
        for (int nt = 0; nt < 6; nt++) {
            int col = wn + nt*8 + gc*2;
            #pragma unroll
            for (int half = 0; half < 2; half++) {
                int m = wm + mt*16 + gr + half*8;
                float2 o;
                o.x = acc[mt][nt][half*2+0];
                o.y = acc[mt][nt][half*2+1];
                *(float2*)(va + ((size_t)b*Nn + i0 + m)*192 + col) = o;
            }
        }
    }
}

// ---------------- small per-row channel mixes -------------------------------
__global__ void __launch_bounds__(192) vmix_kernel(
    const float* __restrict__ vn, const float* __restrict__ Wvv, float* __restrict__ out)
{
    long long row = blockIdx.x;
    int tid = threadIdx.x;
    __shared__ float vrow[192];
    vrow[tid] = vn[row*192 + tid];
    __syncthreads();
    int x = tid >> 6, e = tid & 63;
    float acc = 0.f;
    #pragma unroll 8
    for (int c = 0; c < 64; c++) acc += vrow[c*3 + x] * Wvv[c*64 + e];
    out[row*192 + e*3 + x] = acc;
}

__global__ void __launch_bounds__(192) vout_kernel(
    const float* __restrict__ vattn, const float* __restrict__ Wvo,
    const float* __restrict__ vin, float* __restrict__ outv)
{
    long long row = blockIdx.x;
    int tid = threadIdx.x;
    __shared__ float vrow[192];
    vrow[tid] = vattn[row*192 + tid];
    __syncthreads();
    int x = tid >> 6, e = tid & 63;
    float acc = 0.f;
    #pragma unroll 8
    for (int c = 0; c < 64; c++) acc += vrow[c*3 + x] * Wvo[c*64 + e];
    outv[row*192 + e*3 + x] = vin[row*192 + e*3 + x] + acc;
}

__global__ void __launch_bounds__(256) vffn_kernel(
    const float* __restrict__ vn, const float* __restrict__ Wfv1,
    const float* __restrict__ Wfv2, float* __restrict__ outv)
{
    long long row = blockIdx.x;
    int tid = threadIdx.x;
    __shared__ float vrow[192];
    __shared__ float t[3][256];
    if (tid < 192) vrow[tid] = vn[row*192 + tid];
    __syncthreads();
    #pragma unroll
    for (int x = 0; x < 3; x++) {
        float acc = 0.f;
        #pragma unroll 8
        for (int c = 0; c < 64; c++) acc += vrow[c*3 + x] * Wfv1[c*256 + tid];
        t[x][tid] = acc;
    }
    __syncthreads();
    if (tid < 192) {
        int x = tid >> 6, c = tid & 63;
        float acc = 0.f;
        #pragma unroll 8
        for (int h = 0; h < 256; h++) acc += t[x][h] * Wfv2[h*64 + c];
        outv[row*192 + c*3 + x] += acc;
    }
}

// ---------------- fused single-pass attention --------------------------------
#define QT_LD 68
#define KT_LD 36
#define PS_LD 33
#define ATTN_SMEM_FLOATS (256*QT_LD + 256*KT_LD + 8192 + 4*64*PS_LD + 256 + 128 + 256)

__global__ void __launch_bounds__(512) attn_kernel(
    const float* __restrict__ qg, const float* __restrict__ kg,
    const float* __restrict__ vg, const float* __restrict__ pos,
    const float* __restrict__ wdist, const float* __restrict__ bdist,
    __nv_bfloat16* __restrict__ probsG, float* __restrict__ linvG,
    float* __restrict__ sattn)
{
    extern __shared__ float sm[];
    float* qT     = sm;                       // [256][68]
    float* kT     = qT + 256*QT_LD;           // [256][36]
    float* v_s    = kT + 256*KT_LD;           // [32][256]
    float* ps     = v_s + 8192;               // [4*64][33]
    float* posi   = ps + 4*64*PS_LD;          // [64][4]
    float* posm   = posi + 256;               // [32][4]
    float* linv_s = posm + 128;               // [4][64]

    const int b  = blockIdx.y;
    const int n0 = blockIdx.x * 64;
    const int tid = threadIdx.x;
    const int lane = tid & 31, wrp = tid >> 5;
    const long long bofs = (long long)b * Nn;

    const int h   = tid >> 7;
    const int r   = tid & 127;
    const int ti  = r >> 3, tm = r & 7;
    const int i0q = ti*4, m0q = tm*4;
    const int cv0 = (wrp & 7)*32 + (lane & 3)*8;
    const int i0p = (wrp >> 3)*32 + (lane >> 2)*4;
    const int hp  = (wrp & 7) >> 1;

    for (int idx = tid; idx < 16384; idx += 512) {
        int i = idx >> 8, d = idx & 255;
        qT[d*QT_LD + i] = qg[(bofs + n0 + i)*Ss + d];
    }
    if (tid < 64) {
        const float* pp = pos + (bofs + n0 + tid)*3;
        float a = pp[0], b2 = pp[1], c = pp[2];
        posi[tid*4+0]=a; posi[tid*4+1]=b2; posi[tid*4+2]=c; posi[tid*4+3]=a*a+b2*b2+c*c;
    }
    __syncthreads();

    float4 pi[4];
    #pragma unroll
    for (int ii = 0; ii < 4; ii++) pi[ii] = ((const float4*)posi)[i0q+ii];
    const float wh = wdist[h], bh = bdist[h];

    float accS[32];
    #pragma unroll
    for (int t = 0; t < 32; t++) accS[t] = 0.f;
    float rs[4] = {0.f, 0.f, 0.f, 0.f};

    __nv_bfloat16* pgbase = probsG + ((size_t)(b*4 + h)*Nn + n0)*Nn;
    const float* qb = qT + (h*64)*QT_LD + i0q;
    const float* kb = kT + (h*64)*KT_LD + m0q;

    for (int mt = 0; mt < 64; mt++) {
        const int m0g = mt*32;
        __syncthreads();
        for (int idx = tid; idx < 8192; idx += 512) {
            int m = idx >> 8, d = idx & 255;
            long long grow = (bofs + m0g + m)*Ss + d;
            kT[d*KT_LD + m] = kg[grow];
            v_s[idx] = vg[grow];
        }
        if (tid < 32) {
            const float* pp = pos + (bofs + m0g + tid)*3;
            float a = pp[0], b2 = pp[1], c = pp[2];
            posm[tid*4+0]=a; posm[tid*4+1]=b2; posm[tid*4+2]=c; posm[tid*4+3]=a*a+b2*b2+c*c;
        }
        __syncthreads();

        float acc[4][4];
        #pragma unroll
        for (int i = 0; i < 4; i++)
            #pragma unroll
            for (int j = 0; j < 4; j++) acc[i][j] = 0.f;

        #pragma unroll 16
        for (int d = 0; d < 64; d++) {
            float4 qv = *(const float4*)(qb + d*QT_LD);
            float4 kv = *(const float4*)(kb + d*KT_LD);
            float qa[4] = {qv.x, qv.y, qv.z, qv.w};
            float ka[4] = {kv.x, kv.y, kv.z, kv.w};
            #pragma unroll
            for (int i = 0; i < 4; i++)
                #pragma unroll
                for (int j = 0; j < 4; j++)
                    acc[i][j] += qa[i]*ka[j];
        }

        float4 pmv[4];
        #pragma unroll
        for (int mj = 0; mj < 4; mj++) pmv[mj] = ((const float4*)posm)[m0q+mj];

        #pragma unroll
        for (int ii = 0; ii < 4; ii++) {
            float pv[4];
            #pragma unroll
            for (int mj = 0; mj < 4; mj++) {
                float d2 = pi[ii].w + pmv[mj].w
                         - 2.f*(pi[ii].x*pmv[mj].x + pi[ii].y*pmv[mj].y + pi[ii].z*pmv[mj].z);
                float d2c = fmaxf(d2, 1e-12f);
                float dist = d2c * rsqrtf(d2c);
                float sx = dist*wh + bh;
                float sg = __fdividef(1.f, 1.f + __expf(sx));
                float p  = __expf(acc[ii][mj]*0.125f) * sg;
                pv[mj] = p;
                rs[ii] += p;
                ps[(h*64 + i0q + ii)*PS_LD + m0q + mj] = p;
            }
            __nv_bfloat162 p01 = __floats2bfloat162_rn(pv[0], pv[1]);
            __nv_bfloat162 p23 = __floats2bfloat162_rn(pv[2], pv[3]);
            float2 packed = make_float2(__uint_as_float(*(unsigned int*)&p01),
                                        __uint_as_float(*(unsigned int*)&p23));
            __stcs(reinterpret_cast<float2*>(pgbase + (size_t)(i0q+ii)*Nn + m0g + m0q), packed);
        }
        __syncthreads();

        #pragma unroll 4
        for (int j = 0; j < 32; j++) {
            float4 v0 = *(const float4*)(v_s + j*256 + cv0);
            float4 v1 = *(const float4*)(v_s + j*256 + cv0 + 4);
            float pj[4];
            #pragma unroll
            for (int ii = 0; ii < 4; ii++)
                pj[ii] = ps[(hp*64 + i0p + ii)*PS_LD + j];
            #pragma unroll
            for (int ii = 0; ii < 4; ii++) {
                accS[ii*8+0] += pj[ii]*v0.x; accS[ii*8+1] += pj[ii]*v0.y;
                accS[ii*8+2] += pj[ii]*v0.z; accS[ii*8+3] += pj[ii]*v0.w;
                accS[ii*8+4] += pj[ii]*v1.x; accS[ii*8+5] += pj[ii]*v1.y;
                accS[ii*8+6] += pj[ii]*v1.z; accS[ii*8+7] += pj[ii]*v1.w;
            }
        }
    }

    #pragma unroll
    for (int ii = 0; ii < 4; ii++) {
        float v = rs[ii];
        v += __shfl_xor_sync(0xffffffffu, v, 1);
        v += __shfl_xor_sync(0xffffffffu, v, 2);
        v += __shfl_xor_sync(0xffffffffu, v, 4);
        rs[ii] = v;
    }
    if ((lane & 7) == 0) {
        #pragma unroll
        for (int ii = 0; ii < 4; ii++) {
            float inv = __fdividef(1.f, rs[ii]);
            linv_s[h*64 + i0q + ii] = inv;
            linvG[(size_t)(b*4 + h)*Nn + n0 + i0q + ii] = inv;
        }
    }
    __syncthreads();

    #pragma unroll
    for (int ii = 0; ii < 4; ii++) {
        int i = i0p + ii;
        float li = linv_s[hp*64 + i];
        float4 o0 = make_float4(accS[ii*8+0]*li, accS[ii*8+1]*li, accS[ii*8+2]*li, accS[ii*8+3]*li);
        float4 o1 = make_float4(accS[ii*8+4]*li, accS[ii*8+5]*li, accS[ii*8+6]*li, accS[ii*8+7]*li);
        float* op = sattn + (bofs + n0 + i)*Ss + cv0;
        *(float4*)op = o0;
        *(float4*)(op+4) = o1;
    }
}

// ---------------- launch ------------------------------------------------------
extern "C" void kernel_launch(void* const* d_in, const int* in_sizes, int n_in,
                              void* d_out, int out_size)
{
    const float* s_in  = (const float*)d_in[0];
    const float* v_in  = (const float*)d_in[1];
    const float* pos   = (const float*)d_in[2];
    const float* Wq    = (const float*)d_in[3];
    const float* bq    = (const float*)d_in[4];
    const float* Wk    = (const float*)d_in[5];
    const float* bk    = (const float*)d_in[6];
    const float* Wv    = (const float*)d_in[7];
    const float* bv    = (const float*)d_in[8];
    const float* Wo    = (const float*)d_in[9];
    const float* bo    = (const float*)d_in[10];
    const float* wdist = (const float*)d_in[11];
    const float* bdist = (const float*)d_in[12];
    const float* Wvv   = (const float*)d_in[13];
    const float* Wvo   = (const float*)d_in[14];
    const float* g1    = (const float*)d_in[15];
    const float* be1   = (const float*)d_in[16];
    const float* vs1   = (const float*)d_in[17];
    const float* g2    = (const float*)d_in[18];
    const float* be2   = (const float*)d_in[19];
    const float* vs2   = (const float*)d_in[20];
    const float* Wf1   = (const float*)d_in[21];
    const float* bf1   = (const float*)d_in[22];
    const float* Wf2   = (const float*)d_in[23];
    const float* bf2   = (const float*)d_in[24];
    const float* Wfv1  = (const float*)d_in[25];
    const float* Wfv2  = (const float*)d_in[26];

    float* out_s = (float*)d_out;
    float* out_v = out_s + (size_t)ROWS*Ss;

    void *p_sn, *p_vn, *p_q, *p_k, *p_vp, *p_vmix, *p_pb, *p_li, *p_sa, *p_va, *p_ffn;
    cudaGetSymbolAddress(&p_sn, g_sn);
    cudaGetSymbolAddress(&p_vn, g_vn);
    cudaGetSymbolAddress(&p_q,  g_q);
    cudaGetSymbolAddress(&p_k,  g_k);
    cudaGetSymbolAddress(&p_vp, g_vp);
    cudaGetSymbolAddress(&p_vmix, g_vmix);
    cudaGetSymbolAddress(&p_pb, g_probs);
    cudaGetSymbolAddress(&p_li, g_linv);
    cudaGetSymbolAddress(&p_sa, g_sattn);
    cudaGetSymbolAddress(&p_va, g_vattn);
    cudaGetSymbolAddress(&p_ffn, g_ffn);
    float* sn   = (float*)p_sn;   float* vn   = (float*)p_vn;
    float* q    = (float*)p_q;    float* k    = (float*)p_k;
    float* vp   = (float*)p_vp;   float* vmix = (float*)p_vmix;
    __nv_bfloat16* pb = (__nv_bfloat16*)p_pb;
    float* li   = (float*)p_li;
    float* sa   = (float*)p_sa;   float* va   = (float*)p_va;
    float* ffn  = (float*)p_ffn;

    const int attn_smem = ATTN_SMEM_FLOATS * 4;
    cudaFuncSetAttribute(attn_kernel, cudaFuncAttributeMaxDynamicSharedMemorySize, attn_smem);
    cudaFuncSetAttribute(gemm_tc_kernel, cudaFuncAttributeMaxDynamicSharedMemorySize, GEMM_TC_SMEM);
    cudaFuncSetAttribute(vattn_tc_kernel, cudaFuncAttributeMaxDynamicSharedMemorySize, VATTN_SMEM);

    // 1) eq-LN #1
    eqln_kernel<<<ROWS, 256>>>(s_in, v_in, g1, be1, vs1, sn, vn);

    // 2) QKV projections (tf32 tensor cores — measured faster on this shape)
    dim3 gproj(Ss/64, ROWS/128, 1);
    gemm_tc_kernel<<<gproj, 256, GEMM_TC_SMEM>>>(sn, Wq, bq, nullptr, q,  ROWS, Ss, Ss, 0);
    gemm_tc_kernel<<<gproj, 256, GEMM_TC_SMEM>>>(sn, Wk, bk, nullptr, k,  ROWS, Ss, Ss, 0);
    gemm_tc_kernel<<<gproj, 256, GEMM_TC_SMEM>>>(sn, Wv, bv, nullptr, vp, ROWS, Ss, Ss, 0);

    // 3) vector channel mix (vn @ Wvv)
    vmix_kernel<<<ROWS, 192>>>(vn, Wvv, vmix);

    // 4) fused single-pass attention -> sattn, bf16 probs, linv
    attn_kernel<<<dim3(Nn/64, Bb), 512, attn_smem>>>(q, k, vp, pos, wdist, bdist, pb, li, sa);

    // 5) fused v_attn = (0.25*sum_h linv*probs) @ vmix  (tf32 MMA, reads bf16 probs)
    vattn_tc_kernel<<<dim3(Nn/64, Bb), 256, VATTN_SMEM>>>(pb, li, vmix, va);

    // 6) out_s = s_in + sattn @ Wo + bo
    gemm_tc_kernel<<<gproj, 256, GEMM_TC_SMEM>>>(sa, Wo, bo, s_in, out_s, ROWS, Ss, Ss, 2);

    // 7) out_v = v_in + v_attn @ Wvo
    vout_kernel<<<ROWS, 192>>>(va, Wvo, v_in, out_v);

    // 8) eq-LN #2
    eqln_kernel<<<ROWS, 256>>>(out_s, out_v, g2, be2, vs2, sn, vn);

    // 9) FFN (fp32 SIMT GEMM — R9 known-good for these shapes)
    gemm_kernel<<<dim3(Ff/GBN, ROWS/GBM, 1), 256>>>(sn, Wf1, bf1, nullptr, ffn, ROWS, Ff, Ss, 1, 0, 0, 0);
    gemm_kernel<<<dim3(Ss/GBN, ROWS/GBM, 1), 256>>>(ffn, Wf2, bf2, out_s, out_s, ROWS, Ss, Ff, 2, 0, 0, 0);

    // 10) vector FFN
    vffn_kernel<<<ROWS, 256>>>(vn, Wfv1, Wfv2, out_v);
}

// round 12
// speedup vs baseline: 1.7968x; 1.3306x over previous
#include <cuda_runtime.h>
#include <cuda_bf16.h>
#include <math.h>

#define Bb   4
#define Nn   2048
#define Ss   256
#define Cc   64
#define Hh   4
#define Dd   64
#define Ff   1024
#define ROWS (Bb*Nn)          // 8192

// ---------------- scratch (static device memory; no allocations) -------------
__device__ float g_sn[ROWS*Ss];
__device__ float g_vn[ROWS*Cc*3];
__device__ float g_q[ROWS*Ss];
__device__ float g_k[ROWS*Ss];
__device__ float g_vp[ROWS*Ss];
__device__ float g_vmix[ROWS*Cc*3];
__device__ __nv_bfloat16 g_probs[(size_t)Bb*Hh*Nn*Nn];   // 134 MB unnormalized probs
__device__ float g_linv[(size_t)Bb*Hh*Nn];
__device__ float g_sattn[ROWS*Ss];
__device__ float g_vattn[ROWS*Cc*3];
__device__ float g_ffn[ROWS*Ff];

// ---------------- eq layernorm ----------------------------------------------
__global__ void __launch_bounds__(256) eqln_kernel(
    const float* __restrict__ sin, const float* __restrict__ vin,
    const float* __restrict__ g, const float* __restrict__ be,
    const float* __restrict__ vsc,
    float* __restrict__ sn, float* __restrict__ vn)
{
    long long row = blockIdx.x;
    int tid = threadIdx.x;
    __shared__ float redA[8], redB[8], norms[64], st[3];

    float x = sin[row*Ss + tid];
    float s1 = x, s2 = x*x;
    #pragma unroll
    for (int o = 16; o; o >>= 1) {
        s1 += __shfl_xor_sync(0xffffffffu, s1, o);
        s2 += __shfl_xor_sync(0xffffffffu, s2, o);
    }
    if ((tid & 31) == 0) { redA[tid>>5] = s1; redB[tid>>5] = s2; }

    if (tid < 64) {
        const float* vp = vin + row*192 + tid*3;
        float a = vp[0], b2 = vp[1], c = vp[2];
        norms[tid] = sqrtf(a*a + b2*b2 + c*c);
    }
    __syncthreads();
    if (tid == 0) {
        float A = 0.f, Bs2 = 0.f;
        #pragma unroll
        for (int w = 0; w < 8; w++) { A += redA[w]; Bs2 += redB[w]; }
        float mu  = A * (1.f/256.f);
        float var = Bs2 * (1.f/256.f) - mu*mu;
        st[0] = mu; st[1] = rsqrtf(var + 1e-5f);
        float t = 0.f;
        for (int c = 0; c < 64; c++) t += norms[c];
        st[2] = t * (1.f/64.f);
    }
    __syncthreads();
    sn[row*Ss + tid] = (x - st[0]) * st[1] * g[tid] + be[tid];
    if (tid < 192) {
        int c = tid / 3;
        vn[row*192 + tid] = vin[row*192 + tid] / (norms[c] + 1e-5f) * st[2] * vsc[c];
    }
}

// ---------------- fp32 SIMT GEMM (R9): 128x64 CTA tile, 8x4 per thread -------
#define GBM 128
#define GBN 64
#define GBK 16

__global__ void __launch_bounds__(256) gemm_kernel(
    const float* __restrict__ A, const float* __restrict__ W,
    const float* __restrict__ bias, const float* __restrict__ res,
    float* __restrict__ Cout,
    int M, int N, int K, int epi,
    long long sA, long long sW, long long sC)
{
    long long bz = blockIdx.z;
    A += bz * sA; W += bz * sW; Cout += bz * sC;
    const float* resp = res ? res + bz * sC : (const float*)0;

    __shared__ float As[2][GBK][GBM+4];
    __shared__ float Bs[2][GBK][GBN+4];

    const int tid = threadIdx.x;
    const int tx = tid & 15, ty = tid >> 4;
    const int m0 = blockIdx.y * GBM, n0 = blockIdx.x * GBN;

    const int arow = tid >> 2;
    const int akk  = (tid & 3) * 4;
    const int brow = tid >> 4;
    const int bn4  = (tid & 15) * 4;

    const float* Aptr = A + (long long)(m0 + arow)*K + akk;
    const float* Wptr = W + (long long)brow*N + n0 + bn4;
    const long long a64 = (long long)64*K;

    float4 ra0 = *(const float4*)(Aptr);
    float4 ra1 = *(const float4*)(Aptr + a64);
    float4 rb  = *(const float4*)(Wptr);

    As[0][akk+0][arow] = ra0.x; As[0][akk+1][arow] = ra0.y;
    As[0][akk+2][arow] = ra0.z; As[0][akk+3][arow] = ra0.w;
    As[0][akk+0][arow+64] = ra1.x; As[0][akk+1][arow+64] = ra1.y;
    As[0][akk+2][arow+64] = ra1.z; As[0][akk+3][arow+64] = ra1.w;
    *(float4*)&Bs[0][brow][bn4] = rb;
    __syncthreads();

    float acc[8][4];
    #pragma unroll
    for (int i = 0; i < 8; i++)
        #pragma unroll
        for (int j = 0; j < 4; j++) acc[i][j] = 0.f;

    int buf = 0;
    for (int k0 = 0; k0 < K; k0 += GBK) {
        const bool has_next = (k0 + GBK) < K;
        if (has_next) {
            ra0 = *(const float4*)(Aptr + k0 + GBK);
            ra1 = *(const float4*)(Aptr + a64 + k0 + GBK);
            rb  = *(const float4*)(Wptr + (long long)(k0 + GBK)*N);
        }
        #pragma unroll
        for (int k = 0; k < GBK; k++) {
            float4 af0 = *(const float4*)&As[buf][k][ty*8];
            float4 af1 = *(const float4*)&As[buf][k][ty*8+4];
            float4 bf  = *(const float4*)&Bs[buf][k][tx*4];
            float a[8] = {af0.x,af0.y,af0.z,af0.w,af1.x,af1.y,af1.z,af1.w};
            float b[4] = {bf.x,bf.y,bf.z,bf.w};
            #pragma unroll
            for (int i = 0; i < 8; i++)
                #pragma unroll
                for (int j = 0; j < 4; j++)
                    acc[i][j] += a[i]*b[j];
        }
        if (has_next) {
            int nb = buf ^ 1;
            As[nb][akk+0][arow] = ra0.x; As[nb][akk+1][arow] = ra0.y;
            As[nb][akk+2][arow] = ra0.z; As[nb][akk+3][arow] = ra0.w;
            As[nb][akk+0][arow+64] = ra1.x; As[nb][akk+1][arow+64] = ra1.y;
            As[nb][akk+2][arow+64] = ra1.z; As[nb][akk+3][arow+64] = ra1.w;
            *(float4*)&Bs[nb][brow][bn4] = rb;
        }
        __syncthreads();
        buf ^= 1;
    }

    float bv[4];
    if (bias) {
        #pragma unroll
        for (int j = 0; j < 4; j++) bv[j] = bias[n0 + tx*4 + j];
    } else {
        #pragma unroll
        for (int j = 0; j < 4; j++) bv[j] = 0.f;
    }
    #pragma unroll
    for (int i = 0; i < 8; i++) {
        int m = m0 + ty*8 + i;
        long long off = (long long)m*N + n0 + tx*4;
        float4 o;
        float c0 = acc[i][0]+bv[0], c1 = acc[i][1]+bv[1];
        float c2 = acc[i][2]+bv[2], c3 = acc[i][3]+bv[3];
        if (epi == 1) {
            c0 = 0.5f*c0*(1.0f + erff(c0*0.70710678118654752f));
            c1 = 0.5f*c1*(1.0f + erff(c1*0.70710678118654752f));
            c2 = 0.5f*c2*(1.0f + erff(c2*0.70710678118654752f));
            c3 = 0.5f*c3*(1.0f + erff(c3*0.70710678118654752f));
        } else if (epi == 2) {
            float4 rr = *(const float4*)(resp + off);
            c0 += rr.x; c1 += rr.y; c2 += rr.z; c3 += rr.w;
        }
        o.x = c0; o.y = c1; o.z = c2; o.w = c3;
        *(float4*)(Cout + off) = o;
    }
}

// ---------------- tf32 tensor-core GEMM (QKV/Wo shapes) ----------------------
#define TCK 32
#define AS_LD 132
#define BS_LD 68
#define GEMM_TC_SMEM ((2*TCK*AS_LD + 2*TCK*BS_LD)*4)

__device__ __forceinline__ unsigned f2tf(float x) {
    unsigned r;
    asm("cvt.rna.tf32.f32 %0, %1;" : "=r"(r) : "f"(x));
    return r;
}
__device__ __forceinline__ float f2tff(float x) { return __uint_as_float(f2tf(x)); }

__device__ __forceinline__ void mma_tf32(float* c,
    unsigned a0, unsigned a1, unsigned a2, unsigned a3,
    unsigned b0, unsigned b1)
{
    asm volatile(
        "mma.sync.aligned.m16n8k8.row.col.f32.tf32.tf32.f32 "
        "{%0,%1,%2,%3}, {%4,%5,%6,%7}, {%8,%9}, {%0,%1,%2,%3};\n"
        : "+f"(c[0]), "+f"(c[1]), "+f"(c[2]), "+f"(c[3])
        : "r"(a0), "r"(a1), "r"(a2), "r"(a3), "r"(b0), "r"(b1));
}

__global__ void __launch_bounds__(256) gemm_tc_kernel(
    const float* __restrict__ A, const float* __restrict__ W,
    const float* __restrict__ bias, const float* __restrict__ res,
    float* __restrict__ Cout,
    int M, int N, int K, int epi)
{
    extern __shared__ float sm_g[];
    float* As = sm_g;
    float* Bs = sm_g + 2*TCK*AS_LD;

    const float* resp = res;

    const int tid = threadIdx.x;
    const int lane = tid & 31, wid = tid >> 5;
    const int wm = (wid >> 1) * 32;
    const int wn = (wid & 1) * 32;
    const int m0 = blockIdx.y * 128, n0 = blockIdx.x * 64;
    const int gr = lane >> 2, gc = lane & 3;

    const int arow = tid >> 3;
    const int aq   = (tid & 7) * 4;
    const int wk   = tid >> 4;
    const int wq   = (tid & 15) * 4;

    const float* Aptr = A + (long long)(m0 + arow)*K + aq;
    const float* Wptr = W + (long long)wk*N + n0 + wq;
    const long long aRowStride32 = (long long)32*K;

    float4 ra[4], rw[2];
    #pragma unroll
    for (int i = 0; i < 4; i++) ra[i] = *(const float4*)(Aptr + i*aRowStride32);
    #pragma unroll
    for (int i = 0; i < 2; i++) rw[i] = *(const float4*)(Wptr + (long long)i*16*N);

    #pragma unroll
    for (int i = 0; i < 4; i++) {
        int m = arow + i*32;
        As[(aq+0)*AS_LD + m] = f2tff(ra[i].x);
        As[(aq+1)*AS_LD + m] = f2tff(ra[i].y);
        As[(aq+2)*AS_LD + m] = f2tff(ra[i].z);
        As[(aq+3)*AS_LD + m] = f2tff(ra[i].w);
    }
    #pragma unroll
    for (int i = 0; i < 2; i++) {
        int k = wk + i*16;
        float4 cv;
        cv.x = f2tff(rw[i].x); cv.y = f2tff(rw[i].y);
        cv.z = f2tff(rw[i].z); cv.w = f2tff(rw[i].w);
        *(float4*)&Bs[k*BS_LD + wq] = cv;
    }
    __syncthreads();

    float acc[2][4][4];
    #pragma unroll
    for (int mt = 0; mt < 2; mt++)
        #pragma unroll
        for (int nt = 0; nt < 4; nt++)
            #pragma unroll
            for (int j = 0; j < 4; j++) acc[mt][nt][j] = 0.f;

    int buf = 0;
    for (int k0 = 0; k0 < K; k0 += TCK) {
        const bool has_next = (k0 + TCK) < K;
        if (has_next) {
            #pragma unroll
            for (int i = 0; i < 4; i++) ra[i] = *(const float4*)(Aptr + i*aRowStride32 + k0 + TCK);
            #pragma unroll
            for (int i = 0; i < 2; i++) rw[i] = *(const float4*)(Wptr + (long long)(k0 + TCK + i*16)*N);
        }

        const float* Ab = As + buf*TCK*AS_LD;
        const float* Bb2 = Bs + buf*TCK*BS_LD;
        #pragma unroll
        for (int kk = 0; kk < TCK; kk += 8) {
            unsigned af[2][4];
            #pragma unroll
            for (int mt = 0; mt < 2; mt++) {
                int rb = wm + mt*16 + gr;
                af[mt][0] = __float_as_uint(Ab[(kk+gc  )*AS_LD + rb    ]);
                af[mt][1] = __float_as_uint(Ab[(kk+gc  )*AS_LD + rb + 8]);
                af[mt][2] = __float_as_uint(Ab[(kk+gc+4)*AS_LD + rb    ]);
                af[mt][3] = __float_as_uint(Ab[(kk+gc+4)*AS_LD + rb + 8]);
            }
            #pragma unroll
            for (int nt = 0; nt < 4; nt++) {
                int cb = wn + nt*8 + gr;
                unsigned b0 = __float_as_uint(Bb2[(kk+gc  )*BS_LD + cb]);
                unsigned b1 = __float_as_uint(Bb2[(kk+gc+4)*BS_LD + cb]);
                mma_tf32(acc[0][nt], af[0][0], af[0][1], af[0][2], af[0][3], b0, b1);
                mma_tf32(acc[1][nt], af[1][0], af[1][1], af[1][2], af[1][3], b0, b1);
            }
        }

        if (has_next) {
            int nb = buf ^ 1;
            float* An = As + nb*TCK*AS_LD;
            float* Bn = Bs + nb*TCK*BS_LD;
            #pragma unroll
            for (int i = 0; i < 4; i++) {
                int m = arow + i*32;
                An[(aq+0)*AS_LD + m] = f2tff(ra[i].x);
                An[(aq+1)*AS_LD + m] = f2tff(ra[i].y);
                An[(aq+2)*AS_LD + m] = f2tff(ra[i].z);
                An[(aq+3)*AS_LD + m] = f2tff(ra[i].w);
            }
            #pragma unroll
            for (int i = 0; i < 2; i++) {
                int k = wk + i*16;
                float4 cv;
                cv.x = f2tff(rw[i].x); cv.y = f2tff(rw[i].y);
                cv.z = f2tff(rw[i].z); cv.w = f2tff(rw[i].w);
                *(float4*)&Bn[k*BS_LD + wq] = cv;
            }
        }
        __syncthreads();
        buf ^= 1;
    }

    #pragma unroll
    for (int mt = 0; mt < 2; mt++) {
        #pragma unroll
        for (int nt = 0; nt < 4; nt++) {
            int col = n0 + wn + nt*8 + gc*2;
            float b0 = 0.f, b1 = 0.f;
            if (bias) { b0 = bias[col]; b1 = bias[col+1]; }
            #pragma unroll
            for (int half = 0; half < 2; half++) {
                int m = m0 + wm + mt*16 + gr + half*8;
                long long off = (long long)m*N + col;
                float c0 = acc[mt][nt][half*2+0] + b0;
                float c1 = acc[mt][nt][half*2+1] + b1;
                if (epi == 2) {
                    float2 rr = *(const float2*)(resp + off);
                    c0 += rr.x; c1 += rr.y;
                }
                float2 o; o.x = c0; o.y = c1;
                *(float2*)(Cout + off) = o;
            }
        }
    }
}

// ---------------- fused vattn: (0.25*sum_h linv*probs) @ vmix, tf32 MMA ------
#define VAT_AS_LD 68
#define VAT_BS_LD 196
#define VATTN_SMEM ((2*TCK*VAT_AS_LD + 2*TCK*VAT_BS_LD + 256)*4)

__global__ void __launch_bounds__(256) vattn_tc_kernel(
    const __nv_bfloat16* __restrict__ pg, const float* __restrict__ linvG,
    const float* __restrict__ vmix, float* __restrict__ va)
{
    extern __shared__ float sv[];
    float* As = sv;
    float* Bs = sv + 2*TCK*VAT_AS_LD;
    float* linv_s = Bs + 2*TCK*VAT_BS_LD;

    const int b  = blockIdx.y;
    const int i0 = blockIdx.x * 64;
    const int tid = threadIdx.x;
    const int lane = tid & 31, wid = tid >> 5;
    const int wm = (wid >> 2) * 32;
    const int wn = (wid & 3) * 48;
    const int gr = lane >> 2, gc = lane & 3;

    const size_t pstride = (size_t)Nn * Nn;
    const __nv_bfloat16* pb = pg + (size_t)b*4*pstride + (size_t)i0*Nn;
    const float* vb = vmix + (size_t)b*Nn*192;

    {
        int hh = tid >> 6, ii = tid & 63;
        linv_s[hh*64 + ii] = 0.25f * linvG[(size_t)(b*4 + hh)*Nn + i0 + ii];
    }
    __syncthreads();

    const int arow = tid >> 2;
    const int akq  = (tid & 3) * 8;
    float lr[4];
    #pragma unroll
    for (int h = 0; h < 4; h++) lr[h] = linv_s[h*64 + arow];
    const __nv_bfloat16* arp = pb + (size_t)arow*Nn + akq;

    int bk[6], bc[6];
    #pragma unroll
    for (int t = 0; t < 6; t++) {
        int idx = tid + t*256;
        bk[t] = idx / 48;
        bc[t] = (idx - bk[t]*48) * 4;
    }

    uint4 pa[4];
    float4 pbv[6];
    #pragma unroll
    for (int h = 0; h < 4; h++) pa[h] = *(const uint4*)(arp + h*pstride);
    #pragma unroll
    for (int t = 0; t < 6; t++) pbv[t] = *(const float4*)(vb + (size_t)bk[t]*192 + bc[t]);

    {
        float f[8] = {0,0,0,0,0,0,0,0};
        #pragma unroll
        for (int h = 0; h < 4; h++) {
            const __nv_bfloat162* pp2 = (const __nv_bfloat162*)&pa[h];
            float lh = lr[h];
            #pragma unroll
            for (int t = 0; t < 4; t++) {
                float2 xy = __bfloat1622float2(pp2[t]);
                f[t*2+0] += lh*xy.x; f[t*2+1] += lh*xy.y;
            }
        }
        #pragma unroll
        for (int j = 0; j < 8; j++)
            As[(akq+j)*VAT_AS_LD + arow] = f2tff(f[j]);
        #pragma unroll
        for (int t = 0; t < 6; t++) {
            float4 cv;
            cv.x = f2tff(pbv[t].x); cv.y = f2tff(pbv[t].y);
            cv.z = f2tff(pbv[t].z); cv.w = f2tff(pbv[t].w);
            *(float4*)&Bs[bk[t]*VAT_BS_LD + bc[t]] = cv;
        }
    }
    __syncthreads();

    float acc[2][6][4];
    #pragma unroll
    for (int mt = 0; mt < 2; mt++)
        #pragma unroll
        for (int nt = 0; nt < 6; nt++)
            #pragma unroll
            for (int j = 0; j < 4; j++) acc[mt][nt][j] = 0.f;

    int buf = 0;
    for (int k0 = 0; k0 < Nn; k0 += TCK) {
        const bool has_next = (k0 + TCK) < Nn;
        if (has_next) {
            #pragma unroll
            for (int h = 0; h < 4; h++) pa[h] = *(const uint4*)(arp + h*pstride + k0 + TCK);
            #pragma unroll
            for (int t = 0; t < 6; t++)
                pbv[t] = *(const float4*)(vb + (size_t)(k0 + TCK + bk[t])*192 + bc[t]);
        }

        const float* Ab  = As + buf*TCK*VAT_AS_LD;
        const float* Bb2 = Bs + buf*TCK*VAT_BS_LD;
        #pragma unroll
        for (int kk = 0; kk < TCK; kk += 8) {
            unsigned af[2][4];
            #pragma unroll
            for (int mt = 0; mt < 2; mt++) {
                int rb = wm + mt*16 + gr;
                af[mt][0] = __float_as_uint(Ab[(kk+gc  )*VAT_AS_LD + rb    ]);
                af[mt][1] = __float_as_uint(Ab[(kk+gc  )*VAT_AS_LD + rb + 8]);
                af[mt][2] = __float_as_uint(Ab[(kk+gc+4)*VAT_AS_LD + rb    ]);
                af[mt][3] = __float_as_uint(Ab[(kk+gc+4)*VAT_AS_LD + rb + 8]);
            }
            #pragma unroll
            for (int nt = 0; nt < 6; nt++) {
                int cb = wn + nt*8 + gr;
                unsigned b0 = __float_as_uint(Bb2[(kk+gc  )*VAT_BS_LD + cb]);
                unsigned b1 = __float_as_uint(Bb2[(kk+gc+4)*VAT_BS_LD + cb]);
                mma_tf32(acc[0][nt], af[0][0], af[0][1], af[0][2], af[0][3], b0, b1);
                mma_tf32(acc[1][nt], af[1][0], af[1][1], af[1][2], af[1][3], b0, b1);
            }
        }

        if (has_next) {
            int nb = buf ^ 1;
            float* An = As + nb*TCK*VAT_AS_LD;
            float* Bn = Bs + nb*TCK*VAT_BS_LD;
            float f[8] = {0,0,0,0,0,0,0,0};
            #pragma unroll
            for (int h = 0; h < 4; h++) {
                const __nv_bfloat162* pp2 = (const __nv_bfloat162*)&pa[h];
                float lh = lr[h];
                #pragma unroll
                for (int t = 0; t < 4; t++) {
                    float2 xy = __bfloat1622float2(pp2[t]);
                    f[t*2+0] += lh*xy.x; f[t*2+1] += lh*xy.y;
                }
            }
            #pragma unroll
            for (int j = 0; j < 8; j++)
                An[(akq+j)*VAT_AS_LD + arow] = f2tff(f[j]);
            #pragma unroll
            for (int t = 0; t < 6; t++) {
                float4 cv;
                cv.x = f2tff(pbv[t].x); cv.y = f2tff(pbv[t].y);
                cv.z = f2tff(pbv[t].z); cv.w = f2tff(pbv[t].w);
                *(float4*)&Bn[bk[t]*VAT_BS_LD + bc[t]] = cv;
            }
        }
        __syncthreads();
        buf ^= 1;
    }

    #pragma unroll
    for (int mt = 0; mt < 2; mt++) {
        #pragma unroll
        for (int nt = 0; nt < 6; nt++) {
            int col = wn + nt*8 + gc*2;
            #pragma unroll
            for (int half = 0; half < 2; half++) {
                int m = wm + mt*16 + gr + half*8;
                float2 o;
                o.x = acc[mt][nt][half*2+0];
                o.y = acc[mt][nt][half*2+1];
                *(float2*)(va + ((size_t)b*Nn + i0 + m)*192 + col) = o;
            }
        }
    }
}

// ---------------- small per-row channel mixes -------------------------------
__global__ void __launch_bounds__(192) vmix_kernel(
    const float* __restrict__ vn, const float* __restrict__ Wvv, float* __restrict__ out)
{
    long long row = blockIdx.x;
    int tid = threadIdx.x;
    __shared__ float vrow[192];
    vrow[tid] = vn[row*192 + tid];
    __syncthreads();
    int x = tid >> 6, e = tid & 63;
    float acc = 0.f;
    #pragma unroll 8
    for (int c = 0; c < 64; c++) acc += vrow[c*3 + x] * Wvv[c*64 + e];
    out[row*192 + e*3 + x] = acc;
}

__global__ void __launch_bounds__(192) vout_kernel(
    const float* __restrict__ vattn, const float* __restrict__ Wvo,
    const float* __restrict__ vin, float* __restrict__ outv)
{
    long long row = blockIdx.x;
    int tid = threadIdx.x;
    __shared__ float vrow[192];
    vrow[tid] = vattn[row*192 + tid];
    __syncthreads();
    int x = tid >> 6, e = tid & 63;
    float acc = 0.f;
    #pragma unroll 8
    for (int c = 0; c < 64; c++) acc += vrow[c*3 + x] * Wvo[c*64 + e];
    outv[row*192 + e*3 + x] = vin[row*192 + e*3 + x] + acc;
}

__global__ void __launch_bounds__(256) vffn_kernel(
    const float* __restrict__ vn, const float* __restrict__ Wfv1,
    const float* __restrict__ Wfv2, float* __restrict__ outv)
{
    long long row = blockIdx.x;
    int tid = threadIdx.x;
    __shared__ float vrow[192];
    __shared__ float t[3][256];
    if (tid < 192) vrow[tid] = vn[row*192 + tid];
    __syncthreads();
    #pragma unroll
    for (int x = 0; x < 3; x++) {
        float acc = 0.f;
        #pragma unroll 8
        for (int c = 0; c < 64; c++) acc += vrow[c*3 + x] * Wfv1[c*256 + tid];
        t[x][tid] = acc;
    }
    __syncthreads();
    if (tid < 192) {
        int x = tid >> 6, c = tid & 63;
        float acc = 0.f;
        #pragma unroll 8
        for (int h = 0; h < 256; h++) acc += t[x][h] * Wfv2[h*64 + c];
        outv[row*192 + c*3 + x] += acc;
    }
}

// ---------------- fused attention: tf32 MMA flash, single pass ---------------
// CTA: 64 q rows, all 4 heads, 256 threads / 8 warps (2 per head, 32 rows each).
// kv tile = 32. QK^T and P@V on tensor cores; score math on S fragments.
#define ATK 32
#define Q_LD 260
#define K_LD 260
#define V_LD 264
#define PS2_LD 36
// floats: q 64*260 | k 32*260 | v 32*264 | ps 4*64*36 | posi 256 | posm 128
#define ATTN_SMEM_FLOATS (64*Q_LD + 32*K_LD + 32*V_LD + 4*64*PS2_LD + 256 + 128)

__global__ void __launch_bounds__(256) attn_kernel(
    const float* __restrict__ qg, const float* __restrict__ kg,
    const float* __restrict__ vg, const float* __restrict__ pos,
    const float* __restrict__ wdist, const float* __restrict__ bdist,
    __nv_bfloat16* __restrict__ probsG, float* __restrict__ linvG,
    float* __restrict__ sattn)
{
    extern __shared__ float sm[];
    float* q_s  = sm;                      // [64][260] tf32
    float* k_s  = q_s + 64*Q_LD;           // [32][260] tf32
    float* v_s  = k_s + 32*K_LD;           // [32][264] tf32
    float* ps   = v_s + 32*V_LD;           // [4][64][36] tf32 probs
    float* posi = ps + 4*64*PS2_LD;        // [64][4]
    float* posm = posi + 256;              // [32][4]

    const int b  = blockIdx.y;
    const int n0 = blockIdx.x * 64;
    const int tid = threadIdx.x;
    const int lane = tid & 31, wid = tid >> 5;
    const int h  = wid >> 1;
    const int wm = (wid & 1) * 32;
    const int gr = lane >> 2, gc = lane & 3;
    const long long bofs = (long long)b * Nn;

    // load q tile (tf32) + posi
    for (int idx = tid; idx < 4096; idx += 256) {
        int i = idx >> 6, d4 = (idx & 63) << 2;
        float4 qv = *(const float4*)(qg + (bofs + n0 + i)*Ss + d4);
        float* dst = q_s + i*Q_LD + d4;
        dst[0] = f2tff(qv.x); dst[1] = f2tff(qv.y);
        dst[2] = f2tff(qv.z); dst[3] = f2tff(qv.w);
    }
    if (tid < 64) {
        const float* pp = pos + (bofs + n0 + tid)*3;
        float a = pp[0], b2 = pp[1], c = pp[2];
        posi[tid*4+0]=a; posi[tid*4+1]=b2; posi[tid*4+2]=c; posi[tid*4+3]=a*a+b2*b2+c*c;
    }
    const float wh = wdist[h], bh = bdist[h];
    __syncthreads();

    float accO[2][8][4];
    #pragma unroll
    for (int mt = 0; mt < 2; mt++)
        #pragma unroll
        for (int nt = 0; nt < 8; nt++)
            #pragma unroll
            for (int j = 0; j < 4; j++) accO[mt][nt][j] = 0.f;
    float rs[2][2] = {{0.f,0.f},{0.f,0.f}};

    __nv_bfloat16* pgbase = probsG + ((size_t)(b*4 + h)*Nn + n0)*Nn;
    float* psh = ps + h*64*PS2_LD;

    for (int t64 = 0; t64 < 64; t64++) {
        const int m0g = t64 * ATK;
        // load k/v tile (tf32) + posm
        for (int idx = tid; idx < 2048; idx += 256) {
            int m = idx >> 6, d4 = (idx & 63) << 2;
            long long gofs = (bofs + m0g + m)*Ss + d4;
            float4 kv4 = *(const float4*)(kg + gofs);
            float4 vv4 = *(const float4*)(vg + gofs);
            float* kd = k_s + m*K_LD + d4;
            kd[0]=f2tff(kv4.x); kd[1]=f2tff(kv4.y); kd[2]=f2tff(kv4.z); kd[3]=f2tff(kv4.w);
            float* vd = v_s + m*V_LD + d4;
            vd[0]=f2tff(vv4.x); vd[1]=f2tff(vv4.y); vd[2]=f2tff(vv4.z); vd[3]=f2tff(vv4.w);
        }
        if (tid < 32) {
            const float* pp = pos + (bofs + m0g + tid)*3;
            float a = pp[0], b2 = pp[1], c = pp[2];
            posm[tid*4+0]=a; posm[tid*4+1]=b2; posm[tid*4+2]=c; posm[tid*4+3]=a*a+b2*b2+c*c;
        }
        __syncthreads();

        // ---- QK^T on tensor cores: M=32 (this warp's rows), N=32 kv, K=64 ----
        float acc[2][4][4];
        #pragma unroll
        for (int mt = 0; mt < 2; mt++)
            #pragma unroll
            for (int nt = 0; nt < 4; nt++)
                #pragma unroll
                for (int j = 0; j < 4; j++) acc[mt][nt][j] = 0.f;

        #pragma unroll
        for (int kk = 0; kk < 64; kk += 8) {
            unsigned af[2][4];
            #pragma unroll
            for (int mt = 0; mt < 2; mt++) {
                const float* qp = q_s + (wm + mt*16 + gr)*Q_LD + h*64 + kk + gc;
                af[mt][0] = __float_as_uint(qp[0]);
                af[mt][1] = __float_as_uint(qp[8*Q_LD]);
                af[mt][2] = __float_as_uint(qp[4]);
                af[mt][3] = __float_as_uint(qp[8*Q_LD+4]);
            }
            #pragma unroll
            for (int nt = 0; nt < 4; nt++) {
                const float* kp = k_s + (nt*8 + gr)*K_LD + h*64 + kk + gc;
                unsigned b0 = __float_as_uint(kp[0]);
                unsigned b1 = __float_as_uint(kp[4]);
                mma_tf32(acc[0][nt], af[0][0], af[0][1], af[0][2], af[0][3], b0, b1);
                mma_tf32(acc[1][nt], af[1][0], af[1][1], af[1][2], af[1][3], b0, b1);
            }
        }

        // ---- score math on fragments -> ps (tf32) + probsG (bf16) + rs ----
        #pragma unroll
        for (int mt = 0; mt < 2; mt++) {
            int r0 = wm + mt*16 + gr;
            float4 pi0 = ((const float4*)posi)[r0];
            float4 pi1 = ((const float4*)posi)[r0+8];
            #pragma unroll
            for (int nt = 0; nt < 4; nt++) {
                int mloc = nt*8 + gc*2;
                float4 pm0 = ((const float4*)posm)[mloc];
                float4 pm1 = ((const float4*)posm)[mloc+1];
                float p4[4];
                #pragma unroll
                for (int e = 0; e < 4; e++) {
                    float4 pi = (e < 2) ? pi0 : pi1;
                    float4 pm = (e & 1) ? pm1 : pm0;
                    float d2 = pi.w + pm.w - 2.f*(pi.x*pm.x + pi.y*pm.y + pi.z*pm.z);
                    d2 = fmaxf(d2, 1e-12f);
                    float dist = d2 * rsqrtf(d2);
                    float sx = dist*wh + bh;
                    float sg = __fdividef(1.f, 1.f + __expf(sx));
                    p4[e] = __expf(acc[mt][nt][e]*0.125f) * sg;
                }
                rs[mt][0] += p4[0] + p4[1];
                rs[mt][1] += p4[2] + p4[3];
                *(float2*)(psh + r0*PS2_LD + mloc) = make_float2(f2tff(p4[0]), f2tff(p4[1]));
                *(float2*)(psh + (r0+8)*PS2_LD + mloc) = make_float2(f2tff(p4[2]), f2tff(p4[3]));
                __nv_bfloat162 q01 = __floats2bfloat162_rn(p4[0], p4[1]);
                __nv_bfloat162 q23 = __floats2bfloat162_rn(p4[2], p4[3]);
                __stcs((unsigned int*)(pgbase + (size_t)r0*Nn + m0g + mloc),
                       *(unsigned int*)&q01);
                __stcs((unsigned int*)(pgbase + (size_t)(r0+8)*Nn + m0g + mloc),
                       *(unsigned int*)&q23);
            }
        }
        __syncwarp();

        // ---- P @ V on tensor cores: M=32 rows, N=64 head cols, K=32 kv ----
        #pragma unroll
        for (int kk = 0; kk < 32; kk += 8) {
            unsigned af[2][4];
            #pragma unroll
            for (int mt = 0; mt < 2; mt++) {
                const float* pp = psh + (wm + mt*16 + gr)*PS2_LD + kk + gc;
                af[mt][0] = __float_as_uint(pp[0]);
                af[mt][1] = __float_as_uint(pp[8*PS2_LD]);
                af[mt][2] = __float_as_uint(pp[4]);
                af[mt][3] = __float_as_uint(pp[8*PS2_LD+4]);
            }
            #pragma unroll
            for (int nt = 0; nt < 8; nt++) {
                const float* vp2 = v_s + (kk+gc)*V_LD + h*64 + nt*8 + gr;
                unsigned b0 = __float_as_uint(vp2[0]);
                unsigned b1 = __float_as_uint(vp2[4*V_LD]);
                mma_tf32(accO[0][nt], af[0][0], af[0][1], af[0][2], af[0][3], b0, b1);
                mma_tf32(accO[1][nt], af[1][0], af[1][1], af[1][2], af[1][3], b0, b1);
            }
        }
        __syncthreads();
    }

    // ---- row-sum reduce over gc quad, normalize, store ----
    float linv[2][2];
    #pragma unroll
    for (int mt = 0; mt < 2; mt++)
        #pragma unroll
        for (int hh = 0; hh < 2; hh++) {
            float v = rs[mt][hh];
            v += __shfl_xor_sync(0xffffffffu, v, 1);
            v += __shfl_xor_sync(0xffffffffu, v, 2);
            linv[mt][hh] = __fdividef(1.f, v);
        }
    if (gc == 0) {
        #pragma unroll
        for (int mt = 0; mt < 2; mt++) {
            int r0 = wm + mt*16 + gr;
            linvG[(size_t)(b*4 + h)*Nn + n0 + r0]     = linv[mt][0];
            linvG[(size_t)(b*4 + h)*Nn + n0 + r0 + 8] = linv[mt][1];
        }
    }
    #pragma unroll
    for (int mt = 0; mt < 2; mt++) {
        #pragma unroll
        for (int nt = 0; nt < 8; nt++) {
            int col = h*64 + nt*8 + gc*2;
            int r0 = wm + mt*16 + gr;
            float2 o0, o1;
            o0.x = accO[mt][nt][0]*linv[mt][0];
            o0.y = accO[mt][nt][1]*linv[mt][0];
            o1.x = accO[mt][nt][2]*linv[mt][1];
            o1.y = accO[mt][nt][3]*linv[mt][1];
            *(float2*)(sattn + (bofs + n0 + r0)*Ss + col) = o0;
            *(float2*)(sattn + (bofs + n0 + r0 + 8)*Ss + col) = o1;
        }
    }
}

// ---------------- launch ------------------------------------------------------
extern "C" void kernel_launch(void* const* d_in, const int* in_sizes, int n_in,
                              void* d_out, int out_size)
{
    const float* s_in  = (const float*)d_in[0];
    const float* v_in  = (const float*)d_in[1];
    const float* pos   = (const float*)d_in[2];
    const float* Wq    = (const float*)d_in[3];
    const float* bq    = (const float*)d_in[4];
    const float* Wk    = (const float*)d_in[5];
    const float* bk    = (const float*)d_in[6];
    const float* Wv    = (const float*)d_in[7];
    const float* bv    = (const float*)d_in[8];
    const float* Wo    = (const float*)d_in[9];
    const float* bo    = (const float*)d_in[10];
    const float* wdist = (const float*)d_in[11];
    const float* bdist = (const float*)d_in[12];
    const float* Wvv   = (const float*)d_in[13];
    const float* Wvo   = (const float*)d_in[14];
    const float* g1    = (const float*)d_in[15];
    const float* be1   = (const float*)d_in[16];
    const float* vs1   = (const float*)d_in[17];
    const float* g2    = (const float*)d_in[18];
    const float* be2   = (const float*)d_in[19];
    const float* vs2   = (const float*)d_in[20];
    const float* Wf1   = (const float*)d_in[21];
    const float* bf1   = (const float*)d_in[22];
    const float* Wf2   = (const float*)d_in[23];
    const float* bf2   = (const float*)d_in[24];
    const float* Wfv1  = (const float*)d_in[25];
    const float* Wfv2  = (const float*)d_in[26];

    float* out_s = (float*)d_out;
    float* out_v = out_s + (size_t)ROWS*Ss;

    void *p_sn, *p_vn, *p_q, *p_k, *p_vp, *p_vmix, *p_pb, *p_li, *p_sa, *p_va, *p_ffn;
    cudaGetSymbolAddress(&p_sn, g_sn);
    cudaGetSymbolAddress(&p_vn, g_vn);
    cudaGetSymbolAddress(&p_q,  g_q);
    cudaGetSymbolAddress(&p_k,  g_k);
    cudaGetSymbolAddress(&p_vp, g_vp);
    cudaGetSymbolAddress(&p_vmix, g_vmix);
    cudaGetSymbolAddress(&p_pb, g_probs);
    cudaGetSymbolAddress(&p_li, g_linv);
    cudaGetSymbolAddress(&p_sa, g_sattn);
    cudaGetSymbolAddress(&p_va, g_vattn);
    cudaGetSymbolAddress(&p_ffn, g_ffn);
    float* sn   = (float*)p_sn;   float* vn   = (float*)p_vn;
    float* q    = (float*)p_q;    float* k    = (float*)p_k;
    float* vp   = (float*)p_vp;   float* vmix = (float*)p_vmix;
    __nv_bfloat16* pb = (__nv_bfloat16*)p_pb;
    float* li   = (float*)p_li;
    float* sa   = (float*)p_sa;   float* va   = (float*)p_va;
    float* ffn  = (float*)p_ffn;

    const int attn_smem = ATTN_SMEM_FLOATS * 4;
    cudaFuncSetAttribute(attn_kernel, cudaFuncAttributeMaxDynamicSharedMemorySize, attn_smem);
    cudaFuncSetAttribute(gemm_tc_kernel, cudaFuncAttributeMaxDynamicSharedMemorySize, GEMM_TC_SMEM);
    cudaFuncSetAttribute(vattn_tc_kernel, cudaFuncAttributeMaxDynamicSharedMemorySize, VATTN_SMEM);

    // 1) eq-LN #1
    eqln_kernel<<<ROWS, 256>>>(s_in, v_in, g1, be1, vs1, sn, vn);

    // 2) QKV projections (tf32 tensor cores)
    dim3 gproj(Ss/64, ROWS/128, 1);
    gemm_tc_kernel<<<gproj, 256, GEMM_TC_SMEM>>>(sn, Wq, bq, nullptr, q,  ROWS, Ss, Ss, 0);
    gemm_tc_kernel<<<gproj, 256, GEMM_TC_SMEM>>>(sn, Wk, bk, nullptr, k,  ROWS, Ss, Ss, 0);
    gemm_tc_kernel<<<gproj, 256, GEMM_TC_SMEM>>>(sn, Wv, bv, nullptr, vp, ROWS, Ss, Ss, 0);

    // 3) vector channel mix (vn @ Wvv)
    vmix_kernel<<<ROWS, 192>>>(vn, Wvv, vmix);

    // 4) fused single-pass tf32-MMA attention -> sattn, bf16 probs, linv
    attn_kernel<<<dim3(Nn/64, Bb), 256, attn_smem>>>(q, k, vp, pos, wdist, bdist, pb, li, sa);

    // 5) fused v_attn = (0.25*sum_h linv*probs) @ vmix  (tf32 MMA, reads bf16 probs)
    vattn_tc_kernel<<<dim3(Nn/64, Bb), 256, VATTN_SMEM>>>(pb, li, vmix, va);

    // 6) out_s = s_in + sattn @ Wo + bo
    gemm_tc_kernel<<<gproj, 256, GEMM_TC_SMEM>>>(sa, Wo, bo, s_in, out_s, ROWS, Ss, Ss, 2);

    // 7) out_v = v_in + v_attn @ Wvo
    vout_kernel<<<ROWS, 192>>>(va, Wvo, v_in, out_v);

    // 8) eq-LN #2
    eqln_kernel<<<ROWS, 256>>>(out_s, out_v, g2, be2, vs2, sn, vn);

    // 9) FFN (fp32 SIMT GEMM — known-good for these shapes)
    gemm_kernel<<<dim3(Ff/GBN, ROWS/GBM, 1), 256>>>(sn, Wf1, bf1, nullptr, ffn, ROWS, Ff, Ss, 1, 0, 0, 0);
    gemm_kernel<<<dim3(Ss/GBN, ROWS/GBM, 1), 256>>>(ffn, Wf2, bf2, out_s, out_s, ROWS, Ss, Ff, 2, 0, 0, 0);

    // 10) vector FFN
    vffn_kernel<<<ROWS, 256>>>(vn, Wfv1, Wfv2, out_v);
}

// round 13
// speedup vs baseline: 2.1126x; 1.1758x over previous
#include <cuda_runtime.h>
#include <cuda_bf16.h>
#include <math.h>

#define Bb   4
#define Nn   2048
#define Ss   256
#define Cc   64
#define Hh   4
#define Dd   64
#define Ff   1024
#define ROWS (Bb*Nn)          // 8192

// ---------------- scratch (static device memory; no allocations) -------------
__device__ float g_sn[ROWS*Ss];
__device__ float g_vn[ROWS*Cc*3];
__device__ float g_q[ROWS*Ss];
__device__ float g_k[ROWS*Ss];
__device__ float g_vp[ROWS*Ss];
__device__ float g_vmix[ROWS*Cc*3];
__device__ __nv_bfloat16 g_probs[(size_t)Bb*Hh*Nn*Nn];   // 134 MB unnormalized probs
__device__ float g_linv[(size_t)Bb*Hh*Nn];
__device__ float g_sattn[ROWS*Ss];
__device__ float g_vattn[ROWS*Cc*3];
__device__ float g_ffn[ROWS*Ff];

// ---------------- eq layernorm (+ optional fused vmix) -----------------------
__global__ void __launch_bounds__(256) eqln_kernel(
    const float* __restrict__ sin, const float* __restrict__ vin,
    const float* __restrict__ g, const float* __restrict__ be,
    const float* __restrict__ vsc,
    float* __restrict__ sn, float* __restrict__ vn,
    const float* __restrict__ Wvv, float* __restrict__ vmixO)
{
    long long row = blockIdx.x;
    int tid = threadIdx.x;
    __shared__ float redA[8], redB[8], norms[64], st[3], vsh[192];

    float x = sin[row*Ss + tid];
    float s1 = x, s2 = x*x;
    #pragma unroll
    for (int o = 16; o; o >>= 1) {
        s1 += __shfl_xor_sync(0xffffffffu, s1, o);
        s2 += __shfl_xor_sync(0xffffffffu, s2, o);
    }
    if ((tid & 31) == 0) { redA[tid>>5] = s1; redB[tid>>5] = s2; }

    if (tid < 64) {
        const float* vp = vin + row*192 + tid*3;
        float a = vp[0], b2 = vp[1], c = vp[2];
        norms[tid] = sqrtf(a*a + b2*b2 + c*c);
    }
    __syncthreads();
    if (tid == 0) {
        float A = 0.f, Bs2 = 0.f;
        #pragma unroll
        for (int w = 0; w < 8; w++) { A += redA[w]; Bs2 += redB[w]; }
        float mu  = A * (1.f/256.f);
        float var = Bs2 * (1.f/256.f) - mu*mu;
        st[0] = mu; st[1] = rsqrtf(var + 1e-5f);
        float t = 0.f;
        for (int c = 0; c < 64; c++) t += norms[c];
        st[2] = t * (1.f/64.f);
    }
    __syncthreads();
    sn[row*Ss + tid] = (x - st[0]) * st[1] * g[tid] + be[tid];
    if (tid < 192) {
        int c = tid / 3;
        float val = vin[row*192 + tid] / (norms[c] + 1e-5f) * st[2] * vsc[c];
        vn[row*192 + tid] = val;
        vsh[tid] = val;
    }
    if (vmixO) {
        __syncthreads();
        if (tid < 192) {
            int xx = tid >> 6, e = tid & 63;
            float acc = 0.f;
            #pragma unroll 8
            for (int c = 0; c < 64; c++) acc += vsh[c*3 + xx] * Wvv[c*64 + e];
            vmixO[row*192 + e*3 + xx] = acc;
        }
    }
}

// ---------------- tf32 tensor-core GEMM: 128x64 CTA, mma.m16n8k8 -------------
#define TCK 32
#define AS_LD 132
#define BS_LD 68
#define GEMM_TC_SMEM ((2*TCK*AS_LD + 2*TCK*BS_LD)*4)

__device__ __forceinline__ unsigned f2tf(float x) {
    unsigned r;
    asm("cvt.rna.tf32.f32 %0, %1;" : "=r"(r) : "f"(x));
    return r;
}
__device__ __forceinline__ float f2tff(float x) { return __uint_as_float(f2tf(x)); }

__device__ __forceinline__ void mma_tf32(float* c,
    unsigned a0, unsigned a1, unsigned a2, unsigned a3,
    unsigned b0, unsigned b1)
{
    asm volatile(
        "mma.sync.aligned.m16n8k8.row.col.f32.tf32.tf32.f32 "
        "{%0,%1,%2,%3}, {%4,%5,%6,%7}, {%8,%9}, {%0,%1,%2,%3};\n"
        : "+f"(c[0]), "+f"(c[1]), "+f"(c[2]), "+f"(c[3])
        : "r"(a0), "r"(a1), "r"(a2), "r"(a3), "r"(b0), "r"(b1));
}

__global__ void __launch_bounds__(256) gemm_tc_kernel(
    const float* __restrict__ A, const float* __restrict__ W,
    const float* __restrict__ bias, const float* __restrict__ res,
    float* __restrict__ Cout,
    int M, int N, int K, int epi)
{
    extern __shared__ float sm_g[];
    float* As = sm_g;
    float* Bs = sm_g + 2*TCK*AS_LD;

    const float* resp = res;

    const int tid = threadIdx.x;
    const int lane = tid & 31, wid = tid >> 5;
    const int wm = (wid >> 1) * 32;
    const int wn = (wid & 1) * 32;
    const int m0 = blockIdx.y * 128, n0 = blockIdx.x * 64;
    const int gr = lane >> 2, gc = lane & 3;

    const int arow = tid >> 3;
    const int aq   = (tid & 7) * 4;
    const int wk   = tid >> 4;
    const int wq   = (tid & 15) * 4;

    const float* Aptr = A + (long long)(m0 + arow)*K + aq;
    const float* Wptr = W + (long long)wk*N + n0 + wq;
    const long long aRowStride32 = (long long)32*K;

    float4 ra[4], rw[2];
    #pragma unroll
    for (int i = 0; i < 4; i++) ra[i] = *(const float4*)(Aptr + i*aRowStride32);
    #pragma unroll
    for (int i = 0; i < 2; i++) rw[i] = *(const float4*)(Wptr + (long long)i*16*N);

    #pragma unroll
    for (int i = 0; i < 4; i++) {
        int m = arow + i*32;
        As[(aq+0)*AS_LD + m] = f2tff(ra[i].x);
        As[(aq+1)*AS_LD + m] = f2tff(ra[i].y);
        As[(aq+2)*AS_LD + m] = f2tff(ra[i].z);
        As[(aq+3)*AS_LD + m] = f2tff(ra[i].w);
    }
    #pragma unroll
    for (int i = 0; i < 2; i++) {
        int k = wk + i*16;
        float4 cv;
        cv.x = f2tff(rw[i].x); cv.y = f2tff(rw[i].y);
        cv.z = f2tff(rw[i].z); cv.w = f2tff(rw[i].w);
        *(float4*)&Bs[k*BS_LD + wq] = cv;
    }
    __syncthreads();

    float acc[2][4][4];
    #pragma unroll
    for (int mt = 0; mt < 2; mt++)
        #pragma unroll
        for (int nt = 0; nt < 4; nt++)
            #pragma unroll
            for (int j = 0; j < 4; j++) acc[mt][nt][j] = 0.f;

    int buf = 0;
    for (int k0 = 0; k0 < K; k0 += TCK) {
        const bool has_next = (k0 + TCK) < K;
        if (has_next) {
            #pragma unroll
            for (int i = 0; i < 4; i++) ra[i] = *(const float4*)(Aptr + i*aRowStride32 + k0 + TCK);
            #pragma unroll
            for (int i = 0; i < 2; i++) rw[i] = *(const float4*)(Wptr + (long long)(k0 + TCK + i*16)*N);
        }

        const float* Ab = As + buf*TCK*AS_LD;
        const float* Bb2 = Bs + buf*TCK*BS_LD;
        #pragma unroll
        for (int kk = 0; kk < TCK; kk += 8) {
            unsigned af[2][4];
            #pragma unroll
            for (int mt = 0; mt < 2; mt++) {
                int rb = wm + mt*16 + gr;
                af[mt][0] = __float_as_uint(Ab[(kk+gc  )*AS_LD + rb    ]);
                af[mt][1] = __float_as_uint(Ab[(kk+gc  )*AS_LD + rb + 8]);
                af[mt][2] = __float_as_uint(Ab[(kk+gc+4)*AS_LD + rb    ]);
                af[mt][3] = __float_as_uint(Ab[(kk+gc+4)*AS_LD + rb + 8]);
            }
            #pragma unroll
            for (int nt = 0; nt < 4; nt++) {
                int cb = wn + nt*8 + gr;
                unsigned b0 = __float_as_uint(Bb2[(kk+gc  )*BS_LD + cb]);
                unsigned b1 = __float_as_uint(Bb2[(kk+gc+4)*BS_LD + cb]);
                mma_tf32(acc[0][nt], af[0][0], af[0][1], af[0][2], af[0][3], b0, b1);
                mma_tf32(acc[1][nt], af[1][0], af[1][1], af[1][2], af[1][3], b0, b1);
            }
        }

        if (has_next) {
            int nb = buf ^ 1;
            float* An = As + nb*TCK*AS_LD;
            float* Bn = Bs + nb*TCK*BS_LD;
            #pragma unroll
            for (int i = 0; i < 4; i++) {
                int m = arow + i*32;
                An[(aq+0)*AS_LD + m] = f2tff(ra[i].x);
                An[(aq+1)*AS_LD + m] = f2tff(ra[i].y);
                An[(aq+2)*AS_LD + m] = f2tff(ra[i].z);
                An[(aq+3)*AS_LD + m] = f2tff(ra[i].w);
            }
            #pragma unroll
            for (int i = 0; i < 2; i++) {
                int k = wk + i*16;
                float4 cv;
                cv.x = f2tff(rw[i].x); cv.y = f2tff(rw[i].y);
                cv.z = f2tff(rw[i].z); cv.w = f2tff(rw[i].w);
                *(float4*)&Bn[k*BS_LD + wq] = cv;
            }
        }
        __syncthreads();
        buf ^= 1;
    }

    #pragma unroll
    for (int mt = 0; mt < 2; mt++) {
        #pragma unroll
        for (int nt = 0; nt < 4; nt++) {
            int col = n0 + wn + nt*8 + gc*2;
            float b0 = 0.f, b1 = 0.f;
            if (bias) { b0 = bias[col]; b1 = bias[col+1]; }
            #pragma unroll
            for (int half = 0; half < 2; half++) {
                int m = m0 + wm + mt*16 + gr + half*8;
                long long off = (long long)m*N + col;
                float c0 = acc[mt][nt][half*2+0] + b0;
                float c1 = acc[mt][nt][half*2+1] + b1;
                if (epi == 1) {
                    c0 = 0.5f*c0*(1.0f + erff(c0*0.70710678118654752f));
                    c1 = 0.5f*c1*(1.0f + erff(c1*0.70710678118654752f));
                } else if (epi == 2) {
                    float2 rr = *(const float2*)(resp + off);
                    c0 += rr.x; c1 += rr.y;
                }
                float2 o; o.x = c0; o.y = c1;
                *(float2*)(Cout + off) = o;
            }
        }
    }
}

// ---------------- fused vattn: (0.25*sum_h linv*probs) @ vmix, tf32 MMA ------
#define VAT_AS_LD 68
#define VAT_BS_LD 196
#define VATTN_SMEM ((2*TCK*VAT_AS_LD + 2*TCK*VAT_BS_LD + 256)*4)

__global__ void __launch_bounds__(256) vattn_tc_kernel(
    const __nv_bfloat16* __restrict__ pg, const float* __restrict__ linvG,
    const float* __restrict__ vmix, float* __restrict__ va)
{
    extern __shared__ float sv[];
    float* As = sv;
    float* Bs = sv + 2*TCK*VAT_AS_LD;
    float* linv_s = Bs + 2*TCK*VAT_BS_LD;

    const int b  = blockIdx.y;
    const int i0 = blockIdx.x * 64;
    const int tid = threadIdx.x;
    const int lane = tid & 31, wid = tid >> 5;
    const int wm = (wid >> 2) * 32;
    const int wn = (wid & 3) * 48;
    const int gr = lane >> 2, gc = lane & 3;

    const size_t pstride = (size_t)Nn * Nn;
    const __nv_bfloat16* pb = pg + (size_t)b*4*pstride + (size_t)i0*Nn;
    const float* vb = vmix + (size_t)b*Nn*192;

    {
        int hh = tid >> 6, ii = tid & 63;
        linv_s[hh*64 + ii] = 0.25f * linvG[(size_t)(b*4 + hh)*Nn + i0 + ii];
    }
    __syncthreads();

    const int arow = tid >> 2;
    const int akq  = (tid & 3) * 8;
    float lr[4];
    #pragma unroll
    for (int h = 0; h < 4; h++) lr[h] = linv_s[h*64 + arow];
    const __nv_bfloat16* arp = pb + (size_t)arow*Nn + akq;

    int bk[6], bc[6];
    #pragma unroll
    for (int t = 0; t < 6; t++) {
        int idx = tid + t*256;
        bk[t] = idx / 48;
        bc[t] = (idx - bk[t]*48) * 4;
    }

    uint4 pa[4];
    float4 pbv[6];
    #pragma unroll
    for (int h = 0; h < 4; h++) pa[h] = *(const uint4*)(arp + h*pstride);
    #pragma unroll
    for (int t = 0; t < 6; t++) pbv[t] = *(const float4*)(vb + (size_t)bk[t]*192 + bc[t]);

    {
        float f[8] = {0,0,0,0,0,0,0,0};
        #pragma unroll
        for (int h = 0; h < 4; h++) {
            const __nv_bfloat162* pp2 = (const __nv_bfloat162*)&pa[h];
            float lh = lr[h];
            #pragma unroll
            for (int t = 0; t < 4; t++) {
                float2 xy = __bfloat1622float2(pp2[t]);
                f[t*2+0] += lh*xy.x; f[t*2+1] += lh*xy.y;
            }
        }
        #pragma unroll
        for (int j = 0; j < 8; j++)
            As[(akq+j)*VAT_AS_LD + arow] = f2tff(f[j]);
        #pragma unroll
        for (int t = 0; t < 6; t++) {
            float4 cv;
            cv.x = f2tff(pbv[t].x); cv.y = f2tff(pbv[t].y);
            cv.z = f2tff(pbv[t].z); cv.w = f2tff(pbv[t].w);
            *(float4*)&Bs[bk[t]*VAT_BS_LD + bc[t]] = cv;
        }
    }
    __syncthreads();

    float acc[2][6][4];
    #pragma unroll
    for (int mt = 0; mt < 2; mt++)
        #pragma unroll
        for (int nt = 0; nt < 6; nt++)
            #pragma unroll
            for (int j = 0; j < 4; j++) acc[mt][nt][j] = 0.f;

    int buf = 0;
    for (int k0 = 0; k0 < Nn; k0 += TCK) {
        const bool has_next = (k0 + TCK) < Nn;
        if (has_next) {
            #pragma unroll
            for (int h = 0; h < 4; h++) pa[h] = *(const uint4*)(arp + h*pstride + k0 + TCK);
            #pragma unroll
            for (int t = 0; t < 6; t++)
                pbv[t] = *(const float4*)(vb + (size_t)(k0 + TCK + bk[t])*192 + bc[t]);
        }

        const float* Ab  = As + buf*TCK*VAT_AS_LD;
        const float* Bb2 = Bs + buf*TCK*VAT_BS_LD;
        #pragma unroll
        for (int kk = 0; kk < TCK; kk += 8) {
            unsigned af[2][4];
            #pragma unroll
            for (int mt = 0; mt < 2; mt++) {
                int rb = wm + mt*16 + gr;
                af[mt][0] = __float_as_uint(Ab[(kk+gc  )*VAT_AS_LD + rb    ]);
                af[mt][1] = __float_as_uint(Ab[(kk+gc  )*VAT_AS_LD + rb + 8]);
                af[mt][2] = __float_as_uint(Ab[(kk+gc+4)*VAT_AS_LD + rb    ]);
                af[mt][3] = __float_as_uint(Ab[(kk+gc+4)*VAT_AS_LD + rb + 8]);
            }
            #pragma unroll
            for (int nt = 0; nt < 6; nt++) {
                int cb = wn + nt*8 + gr;
                unsigned b0 = __float_as_uint(Bb2[(kk+gc  )*VAT_BS_LD + cb]);
                unsigned b1 = __float_as_uint(Bb2[(kk+gc+4)*VAT_BS_LD + cb]);
                mma_tf32(acc[0][nt], af[0][0], af[0][1], af[0][2], af[0][3], b0, b1);
                mma_tf32(acc[1][nt], af[1][0], af[1][1], af[1][2], af[1][3], b0, b1);
            }
        }

        if (has_next) {
            int nb = buf ^ 1;
            float* An = As + nb*TCK*VAT_AS_LD;
            float* Bn = Bs + nb*TCK*VAT_BS_LD;
            float f[8] = {0,0,0,0,0,0,0,0};
            #pragma unroll
            for (int h = 0; h < 4; h++) {
                const __nv_bfloat162* pp2 = (const __nv_bfloat162*)&pa[h];
                float lh = lr[h];
                #pragma unroll
                for (int t = 0; t < 4; t++) {
                    float2 xy = __bfloat1622float2(pp2[t]);
                    f[t*2+0] += lh*xy.x; f[t*2+1] += lh*xy.y;
                }
            }
            #pragma unroll
            for (int j = 0; j < 8; j++)
                An[(akq+j)*VAT_AS_LD + arow] = f2tff(f[j]);
            #pragma unroll
            for (int t = 0; t < 6; t++) {
                float4 cv;
                cv.x = f2tff(pbv[t].x); cv.y = f2tff(pbv[t].y);
                cv.z = f2tff(pbv[t].z); cv.w = f2tff(pbv[t].w);
                *(float4*)&Bn[bk[t]*VAT_BS_LD + bc[t]] = cv;
            }
        }
        __syncthreads();
        buf ^= 1;
    }

    #pragma unroll
    for (int mt = 0; mt < 2; mt++) {
        #pragma unroll
        for (int nt = 0; nt < 6; nt++) {
            int col = wn + nt*8 + gc*2;
            #pragma unroll
            for (int half = 0; half < 2; half++) {
                int m = wm + mt*16 + gr + half*8;
                float2 o;
                o.x = acc[mt][nt][half*2+0];
                o.y = acc[mt][nt][half*2+1];
                *(float2*)(va + ((size_t)b*Nn + i0 + m)*192 + col) = o;
            }
        }
    }
}

// ---------------- small per-row channel mixes -------------------------------
__global__ void __launch_bounds__(192) vout_kernel(
    const float* __restrict__ vattn, const float* __restrict__ Wvo,
    const float* __restrict__ vin, float* __restrict__ outv)
{
    long long row = blockIdx.x;
    int tid = threadIdx.x;
    __shared__ float vrow[192];
    vrow[tid] = vattn[row*192 + tid];
    __syncthreads();
    int x = tid >> 6, e = tid & 63;
    float acc = 0.f;
    #pragma unroll 8
    for (int c = 0; c < 64; c++) acc += vrow[c*3 + x] * Wvo[c*64 + e];
    outv[row*192 + e*3 + x] = vin[row*192 + e*3 + x] + acc;
}

// 4 rows per CTA, register-blocked weight reuse
__global__ void __launch_bounds__(256) vffn_kernel(
    const float* __restrict__ vn, const float* __restrict__ Wfv1,
    const float* __restrict__ Wfv2, float* __restrict__ outv)
{
    long long row0 = (long long)blockIdx.x * 4;
    int tid = threadIdx.x;
    __shared__ float vrow[4][192];
    __shared__ float t[12][260];

    for (int idx = tid; idx < 768; idx += 256) {
        int r = idx / 192, j = idx - r*192;
        vrow[r][j] = vn[(row0 + r)*192 + j];
    }
    __syncthreads();

    // stage 1: thread = hidden unit h (0..255); 12 accumulators (4 rows x 3 xyz)
    {
        float acc[12];
        #pragma unroll
        for (int j = 0; j < 12; j++) acc[j] = 0.f;
        #pragma unroll 4
        for (int c = 0; c < 64; c++) {
            float w = Wfv1[c*256 + tid];
            #pragma unroll
            for (int r = 0; r < 4; r++)
                #pragma unroll
                for (int x = 0; x < 3; x++)
                    acc[r*3+x] += vrow[r][c*3+x] * w;
        }
        #pragma unroll
        for (int j = 0; j < 12; j++) t[j][tid] = acc[j];
    }
    __syncthreads();

    // stage 2: thread -> (c = tid&63, r = tid>>6); 3 outputs (xyz)
    {
        int c = tid & 63, r = tid >> 6;
        float acc[3] = {0.f, 0.f, 0.f};
        #pragma unroll 4
        for (int h = 0; h < 256; h++) {
            float w2 = Wfv2[h*64 + c];
            #pragma unroll
            for (int x = 0; x < 3; x++)
                acc[x] += t[r*3+x][h] * w2;
        }
        #pragma unroll
        for (int x = 0; x < 3; x++)
            outv[(row0 + r)*192 + c*3 + x] += acc[x];
    }
}

// ---------------- fused attention: tf32 MMA flash, single pass ---------------
#define ATK 32
#define Q_LD 260
#define K_LD 260
#define V_LD 264
#define PS2_LD 36
#define ATTN_SMEM_FLOATS (64*Q_LD + 32*K_LD + 32*V_LD + 4*64*PS2_LD + 256 + 128)

__global__ void __launch_bounds__(256) attn_kernel(
    const float* __restrict__ qg, const float* __restrict__ kg,
    const float* __restrict__ vg, const float* __restrict__ pos,
    const float* __restrict__ wdist, const float* __restrict__ bdist,
    __nv_bfloat16* __restrict__ probsG, float* __restrict__ linvG,
    float* __restrict__ sattn)
{
    extern __shared__ float sm[];
    float* q_s  = sm;
    float* k_s  = q_s + 64*Q_LD;
    float* v_s  = k_s + 32*K_LD;
    float* ps   = v_s + 32*V_LD;
    float* posi = ps + 4*64*PS2_LD;
    float* posm = posi + 256;

    const int b  = blockIdx.y;
    const int n0 = blockIdx.x * 64;
    const int tid = threadIdx.x;
    const int lane = tid & 31, wid = tid >> 5;
    const int h  = wid >> 1;
    const int wm = (wid & 1) * 32;
    const int gr = lane >> 2, gc = lane & 3;
    const long long bofs = (long long)b * Nn;

    for (int idx = tid; idx < 4096; idx += 256) {
        int i = idx >> 6, d4 = (idx & 63) << 2;
        float4 qv = *(const float4*)(qg + (bofs + n0 + i)*Ss + d4);
        float* dst = q_s + i*Q_LD + d4;
        dst[0] = f2tff(qv.x); dst[1] = f2tff(qv.y);
        dst[2] = f2tff(qv.z); dst[3] = f2tff(qv.w);
    }
    if (tid < 64) {
        const float* pp = pos + (bofs + n0 + tid)*3;
        float a = pp[0], b2 = pp[1], c = pp[2];
        posi[tid*4+0]=a; posi[tid*4+1]=b2; posi[tid*4+2]=c; posi[tid*4+3]=a*a+b2*b2+c*c;
    }
    const float wh = wdist[h], bh = bdist[h];
    __syncthreads();

    float accO[2][8][4];
    #pragma unroll
    for (int mt = 0; mt < 2; mt++)
        #pragma unroll
        for (int nt = 0; nt < 8; nt++)
            #pragma unroll
            for (int j = 0; j < 4; j++) accO[mt][nt][j] = 0.f;
    float rs[2][2] = {{0.f,0.f},{0.f,0.f}};

    __nv_bfloat16* pgbase = probsG + ((size_t)(b*4 + h)*Nn + n0)*Nn;
    float* psh = ps + h*64*PS2_LD;

    for (int t64 = 0; t64 < 64; t64++) {
        const int m0g = t64 * ATK;
        for (int idx = tid; idx < 2048; idx += 256) {
            int m = idx >> 6, d4 = (idx & 63) << 2;
            long long gofs = (bofs + m0g + m)*Ss + d4;
            float4 kv4 = *(const float4*)(kg + gofs);
            float4 vv4 = *(const float4*)(vg + gofs);
            float* kd = k_s + m*K_LD + d4;
            kd[0]=f2tff(kv4.x); kd[1]=f2tff(kv4.y); kd[2]=f2tff(kv4.z); kd[3]=f2tff(kv4.w);
            float* vd = v_s + m*V_LD + d4;
            vd[0]=f2tff(vv4.x); vd[1]=f2tff(vv4.y); vd[2]=f2tff(vv4.z); vd[3]=f2tff(vv4.w);
        }
        if (tid < 32) {
            const float* pp = pos + (bofs + m0g + tid)*3;
            float a = pp[0], b2 = pp[1], c = pp[2];
            posm[tid*4+0]=a; posm[tid*4+1]=b2; posm[tid*4+2]=c; posm[tid*4+3]=a*a+b2*b2+c*c;
        }
        __syncthreads();

        float acc[2][4][4];
        #pragma unroll
        for (int mt = 0; mt < 2; mt++)
            #pragma unroll
            for (int nt = 0; nt < 4; nt++)
                #pragma unroll
                for (int j = 0; j < 4; j++) acc[mt][nt][j] = 0.f;

        #pragma unroll
        for (int kk = 0; kk < 64; kk += 8) {
            unsigned af[2][4];
            #pragma unroll
            for (int mt = 0; mt < 2; mt++) {
                const float* qp = q_s + (wm + mt*16 + gr)*Q_LD + h*64 + kk + gc;
                af[mt][0] = __float_as_uint(qp[0]);
                af[mt][1] = __float_as_uint(qp[8*Q_LD]);
                af[mt][2] = __float_as_uint(qp[4]);
                af[mt][3] = __float_as_uint(qp[8*Q_LD+4]);
            }
            #pragma unroll
            for (int nt = 0; nt < 4; nt++) {
                const float* kp = k_s + (nt*8 + gr)*K_LD + h*64 + kk + gc;
                unsigned b0 = __float_as_uint(kp[0]);
                unsigned b1 = __float_as_uint(kp[4]);
                mma_tf32(acc[0][nt], af[0][0], af[0][1], af[0][2], af[0][3], b0, b1);
                mma_tf32(acc[1][nt], af[1][0], af[1][1], af[1][2], af[1][3], b0, b1);
            }
        }

        #pragma unroll
        for (int mt = 0; mt < 2; mt++) {
            int r0 = wm + mt*16 + gr;
            float4 pi0 = ((const float4*)posi)[r0];
            float4 pi1 = ((const float4*)posi)[r0+8];
            #pragma unroll
            for (int nt = 0; nt < 4; nt++) {
                int mloc = nt*8 + gc*2;
                float4 pm0 = ((const float4*)posm)[mloc];
                float4 pm1 = ((const float4*)posm)[mloc+1];
                float p4[4];
                #pragma unroll
                for (int e = 0; e < 4; e++) {
                    float4 pi = (e < 2) ? pi0 : pi1;
                    float4 pm = (e & 1) ? pm1 : pm0;
                    float d2 = pi.w + pm.w - 2.f*(pi.x*pm.x + pi.y*pm.y + pi.z*pm.z);
                    d2 = fmaxf(d2, 1e-12f);
                    float dist = d2 * rsqrtf(d2);
                    float sx = dist*wh + bh;
                    float sg = __fdividef(1.f, 1.f + __expf(sx));
                    p4[e] = __expf(acc[mt][nt][e]*0.125f) * sg;
                }
                rs[mt][0] += p4[0] + p4[1];
                rs[mt][1] += p4[2] + p4[3];
                *(float2*)(psh + r0*PS2_LD + mloc) = make_float2(f2tff(p4[0]), f2tff(p4[1]));
                *(float2*)(psh + (r0+8)*PS2_LD + mloc) = make_float2(f2tff(p4[2]), f2tff(p4[3]));
                __nv_bfloat162 q01 = __floats2bfloat162_rn(p4[0], p4[1]);
                __nv_bfloat162 q23 = __floats2bfloat162_rn(p4[2], p4[3]);
                __stcs((unsigned int*)(pgbase + (size_t)r0*Nn + m0g + mloc),
                       *(unsigned int*)&q01);
                __stcs((unsigned int*)(pgbase + (size_t)(r0+8)*Nn + m0g + mloc),
                       *(unsigned int*)&q23);
            }
        }
        __syncwarp();

        #pragma unroll
        for (int kk = 0; kk < 32; kk += 8) {
            unsigned af[2][4];
            #pragma unroll
            for (int mt = 0; mt < 2; mt++) {
                const float* pp = psh + (wm + mt*16 + gr)*PS2_LD + kk + gc;
                af[mt][0] = __float_as_uint(pp[0]);
                af[mt][1] = __float_as_uint(pp[8*PS2_LD]);
                af[mt][2] = __float_as_uint(pp[4]);
                af[mt][3] = __float_as_uint(pp[8*PS2_LD+4]);
            }
            #pragma unroll
            for (int nt = 0; nt < 8; nt++) {
                const float* vp2 = v_s + (kk+gc)*V_LD + h*64 + nt*8 + gr;
                unsigned b0 = __float_as_uint(vp2[0]);
                unsigned b1 = __float_as_uint(vp2[4*V_LD]);
                mma_tf32(accO[0][nt], af[0][0], af[0][1], af[0][2], af[0][3], b0, b1);
                mma_tf32(accO[1][nt], af[1][0], af[1][1], af[1][2], af[1][3], b0, b1);
            }
        }
        __syncthreads();
    }

    float linv[2][2];
    #pragma unroll
    for (int mt = 0; mt < 2; mt++)
        #pragma unroll
        for (int hh = 0; hh < 2; hh++) {
            float v = rs[mt][hh];
            v += __shfl_xor_sync(0xffffffffu, v, 1);
            v += __shfl_xor_sync(0xffffffffu, v, 2);
            linv[mt][hh] = __fdividef(1.f, v);
        }
    if (gc == 0) {
        #pragma unroll
        for (int mt = 0; mt < 2; mt++) {
            int r0 = wm + mt*16 + gr;
            linvG[(size_t)(b*4 + h)*Nn + n0 + r0]     = linv[mt][0];
            linvG[(size_t)(b*4 + h)*Nn + n0 + r0 + 8] = linv[mt][1];
        }
    }
    #pragma unroll
    for (int mt = 0; mt < 2; mt++) {
        #pragma unroll
        for (int nt = 0; nt < 8; nt++) {
            int col = h*64 + nt*8 + gc*2;
            int r0 = wm + mt*16 + gr;
            float2 o0, o1;
            o0.x = accO[mt][nt][0]*linv[mt][0];
            o0.y = accO[mt][nt][1]*linv[mt][0];
            o1.x = accO[mt][nt][2]*linv[mt][1];
            o1.y = accO[mt][nt][3]*linv[mt][1];
            *(float2*)(sattn + (bofs + n0 + r0)*Ss + col) = o0;
            *(float2*)(sattn + (bofs + n0 + r0 + 8)*Ss + col) = o1;
        }
    }
}

// ---------------- launch ------------------------------------------------------
extern "C" void kernel_launch(void* const* d_in, const int* in_sizes, int n_in,
                              void* d_out, int out_size)
{
    const float* s_in  = (const float*)d_in[0];
    const float* v_in  = (const float*)d_in[1];
    const float* pos   = (const float*)d_in[2];
    const float* Wq    = (const float*)d_in[3];
    const float* bq    = (const float*)d_in[4];
    const float* Wk    = (const float*)d_in[5];
    const float* bk    = (const float*)d_in[6];
    const float* Wv    = (const float*)d_in[7];
    const float* bv    = (const float*)d_in[8];
    const float* Wo    = (const float*)d_in[9];
    const float* bo    = (const float*)d_in[10];
    const float* wdist = (const float*)d_in[11];
    const float* bdist = (const float*)d_in[12];
    const float* Wvv   = (const float*)d_in[13];
    const float* Wvo   = (const float*)d_in[14];
    const float* g1    = (const float*)d_in[15];
    const float* be1   = (const float*)d_in[16];
    const float* vs1   = (const float*)d_in[17];
    const float* g2    = (const float*)d_in[18];
    const float* be2   = (const float*)d_in[19];
    const float* vs2   = (const float*)d_in[20];
    const float* Wf1   = (const float*)d_in[21];
    const float* bf1   = (const float*)d_in[22];
    const float* Wf2   = (const float*)d_in[23];
    const float* bf2   = (const float*)d_in[24];
    const float* Wfv1  = (const float*)d_in[25];
    const float* Wfv2  = (const float*)d_in[26];

    float* out_s = (float*)d_out;
    float* out_v = out_s + (size_t)ROWS*Ss;

    void *p_sn, *p_vn, *p_q, *p_k, *p_vp, *p_vmix, *p_pb, *p_li, *p_sa, *p_va, *p_ffn;
    cudaGetSymbolAddress(&p_sn, g_sn);
    cudaGetSymbolAddress(&p_vn, g_vn);
    cudaGetSymbolAddress(&p_q,  g_q);
    cudaGetSymbolAddress(&p_k,  g_k);
    cudaGetSymbolAddress(&p_vp, g_vp);
    cudaGetSymbolAddress(&p_vmix, g_vmix);
    cudaGetSymbolAddress(&p_pb, g_probs);
    cudaGetSymbolAddress(&p_li, g_linv);
    cudaGetSymbolAddress(&p_sa, g_sattn);
    cudaGetSymbolAddress(&p_va, g_vattn);
    cudaGetSymbolAddress(&p_ffn, g_ffn);
    float* sn   = (float*)p_sn;   float* vn   = (float*)p_vn;
    float* q    = (float*)p_q;    float* k    = (float*)p_k;
    float* vp   = (float*)p_vp;   float* vmix = (float*)p_vmix;
    __nv_bfloat16* pb = (__nv_bfloat16*)p_pb;
    float* li   = (float*)p_li;
    float* sa   = (float*)p_sa;   float* va   = (float*)p_va;
    float* ffn  = (float*)p_ffn;

    const int attn_smem = ATTN_SMEM_FLOATS * 4;
    cudaFuncSetAttribute(attn_kernel, cudaFuncAttributeMaxDynamicSharedMemorySize, attn_smem);
    cudaFuncSetAttribute(gemm_tc_kernel, cudaFuncAttributeMaxDynamicSharedMemorySize, GEMM_TC_SMEM);
    cudaFuncSetAttribute(vattn_tc_kernel, cudaFuncAttributeMaxDynamicSharedMemorySize, VATTN_SMEM);

    // 1) eq-LN #1 (+ fused vmix = vn @ Wvv)
    eqln_kernel<<<ROWS, 256>>>(s_in, v_in, g1, be1, vs1, sn, vn, Wvv, vmix);

    // 2) QKV projections (tf32 tensor cores)
    dim3 gproj(Ss/64, ROWS/128, 1);
    gemm_tc_kernel<<<gproj, 256, GEMM_TC_SMEM>>>(sn, Wq, bq, nullptr, q,  ROWS, Ss, Ss, 0);
    gemm_tc_kernel<<<gproj, 256, GEMM_TC_SMEM>>>(sn, Wk, bk, nullptr, k,  ROWS, Ss, Ss, 0);
    gemm_tc_kernel<<<gproj, 256, GEMM_TC_SMEM>>>(sn, Wv, bv, nullptr, vp, ROWS, Ss, Ss, 0);

    // 3) fused single-pass tf32-MMA attention -> sattn, bf16 probs, linv
    attn_kernel<<<dim3(Nn/64, Bb), 256, attn_smem>>>(q, k, vp, pos, wdist, bdist, pb, li, sa);

    // 4) fused v_attn = (0.25*sum_h linv*probs) @ vmix  (tf32 MMA, reads bf16 probs)
    vattn_tc_kernel<<<dim3(Nn/64, Bb), 256, VATTN_SMEM>>>(pb, li, vmix, va);

    // 5) out_s = s_in + sattn @ Wo + bo
    gemm_tc_kernel<<<gproj, 256, GEMM_TC_SMEM>>>(sa, Wo, bo, s_in, out_s, ROWS, Ss, Ss, 2);

    // 6) out_v = v_in + v_attn @ Wvo
    vout_kernel<<<ROWS, 192>>>(va, Wvo, v_in, out_v);

    // 7) eq-LN #2 (no vmix)
    eqln_kernel<<<ROWS, 256>>>(out_s, out_v, g2, be2, vs2, sn, vn, nullptr, nullptr);

    // 8) FFN (tf32 tensor cores, GELU + residual epilogues)
    gemm_tc_kernel<<<dim3(Ff/64, ROWS/128, 1), 256, GEMM_TC_SMEM>>>(sn, Wf1, bf1, nullptr, ffn, ROWS, Ff, Ss, 1);
    gemm_tc_kernel<<<dim3(Ss/64, ROWS/128, 1), 256, GEMM_TC_SMEM>>>(ffn, Wf2, bf2, out_s, out_s, ROWS, Ss, Ff, 2);

    // 9) vector FFN (4 rows per CTA)
    vffn_kernel<<<ROWS/4, 256>>>(vn, Wfv1, Wfv2, out_v);
}

// round 14
// speedup vs baseline: 2.4518x; 1.1605x over previous
#include <cuda_runtime.h>
#include <cuda_bf16.h>
#include <math.h>

#define Bb   4
#define Nn   2048
#define Ss   256
#define Cc   64
#define Hh   4
#define Dd   64
#define Ff   1024
#define ROWS (Bb*Nn)          // 8192

// ---------------- scratch (static device memory; no allocations) -------------
__device__ float g_sn[ROWS*Ss];
__device__ float g_vn[ROWS*Cc*3];
__device__ float g_q[ROWS*Ss];
__device__ float g_k[ROWS*Ss];
__device__ float g_vp[ROWS*Ss];
__device__ float g_vmix[ROWS*Cc*3];
__device__ __nv_bfloat16 g_probs[(size_t)Bb*Hh*Nn*Nn];   // 134 MB unnormalized probs
__device__ float g_linv[(size_t)Bb*Hh*Nn];
__device__ float g_sattn[ROWS*Ss];
__device__ float g_vattn[ROWS*Cc*3];
__device__ float g_ffn[ROWS*Ff];

// ---------------- eq layernorm (+ optional fused vmix) -----------------------
__global__ void __launch_bounds__(256) eqln_kernel(
    const float* __restrict__ sin, const float* __restrict__ vin,
    const float* __restrict__ g, const float* __restrict__ be,
    const float* __restrict__ vsc,
    float* __restrict__ sn, float* __restrict__ vn,
    const float* __restrict__ Wvv, float* __restrict__ vmixO)
{
    long long row = blockIdx.x;
    int tid = threadIdx.x;
    __shared__ float redA[8], redB[8], norms[64], st[3], vsh[192];

    float x = sin[row*Ss + tid];
    float s1 = x, s2 = x*x;
    #pragma unroll
    for (int o = 16; o; o >>= 1) {
        s1 += __shfl_xor_sync(0xffffffffu, s1, o);
        s2 += __shfl_xor_sync(0xffffffffu, s2, o);
    }
    if ((tid & 31) == 0) { redA[tid>>5] = s1; redB[tid>>5] = s2; }

    if (tid < 64) {
        const float* vp = vin + row*192 + tid*3;
        float a = vp[0], b2 = vp[1], c = vp[2];
        norms[tid] = sqrtf(a*a + b2*b2 + c*c);
    }
    __syncthreads();
    if (tid == 0) {
        float A = 0.f, Bs2 = 0.f;
        #pragma unroll
        for (int w = 0; w < 8; w++) { A += redA[w]; Bs2 += redB[w]; }
        float mu  = A * (1.f/256.f);
        float var = Bs2 * (1.f/256.f) - mu*mu;
        st[0] = mu; st[1] = rsqrtf(var + 1e-5f);
        float t = 0.f;
        for (int c = 0; c < 64; c++) t += norms[c];
        st[2] = t * (1.f/64.f);
    }
    __syncthreads();
    sn[row*Ss + tid] = (x - st[0]) * st[1] * g[tid] + be[tid];
    if (tid < 192) {
        int c = tid / 3;
        float val = vin[row*192 + tid] / (norms[c] + 1e-5f) * st[2] * vsc[c];
        vn[row*192 + tid] = val;
        vsh[tid] = val;
    }
    if (vmixO) {
        __syncthreads();
        if (tid < 192) {
            int xx = tid >> 6, e = tid & 63;
            float acc = 0.f;
            #pragma unroll 8
            for (int c = 0; c < 64; c++) acc += vsh[c*3 + xx] * Wvv[c*64 + e];
            vmixO[row*192 + e*3 + xx] = acc;
        }
    }
}

// ---------------- bf16 tensor-core GEMM: 128x64 CTA, mma.m16n8k16 ------------
// K-pairs stored as bf16x2 in uint32 smem words.
#define TCK 32
#define AS2_LD 132          // [16 pairs][128 m + pad] uints
#define BS2_LD 68           // [16 pairs][64 n + pad] uints
#define GEMM_TC_SMEM ((2*16*AS2_LD + 2*16*BS2_LD)*4)

__device__ __forceinline__ unsigned pkbf(float x, float y) {
    __nv_bfloat162 h = __floats2bfloat162_rn(x, y);
    return *(unsigned*)&h;
}

__device__ __forceinline__ void mma_bf16(float* c,
    unsigned a0, unsigned a1, unsigned a2, unsigned a3,
    unsigned b0, unsigned b1)
{
    asm volatile(
        "mma.sync.aligned.m16n8k16.row.col.f32.bf16.bf16.f32 "
        "{%0,%1,%2,%3}, {%4,%5,%6,%7}, {%8,%9}, {%0,%1,%2,%3};\n"
        : "+f"(c[0]), "+f"(c[1]), "+f"(c[2]), "+f"(c[3])
        : "r"(a0), "r"(a1), "r"(a2), "r"(a3), "r"(b0), "r"(b1));
}

__device__ __forceinline__ unsigned f2tf(float x) {
    unsigned r;
    asm("cvt.rna.tf32.f32 %0, %1;" : "=r"(r) : "f"(x));
    return r;
}
__device__ __forceinline__ float f2tff(float x) { return __uint_as_float(f2tf(x)); }

__device__ __forceinline__ void mma_tf32(float* c,
    unsigned a0, unsigned a1, unsigned a2, unsigned a3,
    unsigned b0, unsigned b1)
{
    asm volatile(
        "mma.sync.aligned.m16n8k8.row.col.f32.tf32.tf32.f32 "
        "{%0,%1,%2,%3}, {%4,%5,%6,%7}, {%8,%9}, {%0,%1,%2,%3};\n"
        : "+f"(c[0]), "+f"(c[1]), "+f"(c[2]), "+f"(c[3])
        : "r"(a0), "r"(a1), "r"(a2), "r"(a3), "r"(b0), "r"(b1));
}

__global__ void __launch_bounds__(256) gemm_tc_kernel(
    const float* __restrict__ A, const float* __restrict__ W,
    const float* __restrict__ bias, const float* __restrict__ res,
    float* __restrict__ Cout,
    int M, int N, int K, int epi)
{
    extern __shared__ unsigned sm_u[];
    unsigned* As = sm_u;                      // [2][16][AS2_LD]
    unsigned* Bs = sm_u + 2*16*AS2_LD;        // [2][16][BS2_LD]

    const float* resp = res;

    const int tid = threadIdx.x;
    const int lane = tid & 31, wid = tid >> 5;
    const int wm = (wid >> 1) * 32;
    const int wn = (wid & 1) * 32;
    const int m0 = blockIdx.y * 128, n0 = blockIdx.x * 64;
    const int gr = lane >> 2, gc = lane & 3;

    // loaders
    const int arow = tid >> 3;            // 0..31
    const int aq   = (tid & 7) * 4;       // k float offset
    const int ap   = (tid & 7) * 2;       // k pair offset
    const int wkp  = tid >> 4;            // 0..15 (k pair)
    const int wq   = (tid & 15) * 4;      // n offset

    const float* Aptr = A + (long long)(m0 + arow)*K + aq;
    const float* Wp0  = W + (long long)(2*wkp  )*N + n0 + wq;
    const float* Wp1  = W + (long long)(2*wkp+1)*N + n0 + wq;
    const long long aRowStride32 = (long long)32*K;

    float4 ra[4], rw0, rw1;
    #pragma unroll
    for (int i = 0; i < 4; i++) ra[i] = *(const float4*)(Aptr + i*aRowStride32);
    rw0 = *(const float4*)(Wp0);
    rw1 = *(const float4*)(Wp1);

    #pragma unroll
    for (int i = 0; i < 4; i++) {
        int m = arow + i*32;
        As[(ap+0)*AS2_LD + m] = pkbf(ra[i].x, ra[i].y);
        As[(ap+1)*AS2_LD + m] = pkbf(ra[i].z, ra[i].w);
    }
    {
        uint4 bv;
        bv.x = pkbf(rw0.x, rw1.x); bv.y = pkbf(rw0.y, rw1.y);
        bv.z = pkbf(rw0.z, rw1.z); bv.w = pkbf(rw0.w, rw1.w);
        *(uint4*)&Bs[wkp*BS2_LD + wq] = bv;
    }
    __syncthreads();

    float acc[2][4][4];
    #pragma unroll
    for (int mt = 0; mt < 2; mt++)
        #pragma unroll
        for (int nt = 0; nt < 4; nt++)
            #pragma unroll
            for (int j = 0; j < 4; j++) acc[mt][nt][j] = 0.f;

    int buf = 0;
    for (int k0 = 0; k0 < K; k0 += TCK) {
        const bool has_next = (k0 + TCK) < K;
        if (has_next) {
            #pragma unroll
            for (int i = 0; i < 4; i++) ra[i] = *(const float4*)(Aptr + i*aRowStride32 + k0 + TCK);
            rw0 = *(const float4*)(Wp0 + (long long)(k0 + TCK)*N);
            rw1 = *(const float4*)(Wp1 + (long long)(k0 + TCK)*N);
        }

        const unsigned* Ab = As + buf*16*AS2_LD;
        const unsigned* Bb2 = Bs + buf*16*BS2_LD;
        #pragma unroll
        for (int kk2 = 0; kk2 < 16; kk2 += 8) {
            unsigned af[2][4];
            #pragma unroll
            for (int mt = 0; mt < 2; mt++) {
                int rb = wm + mt*16 + gr;
                af[mt][0] = Ab[(kk2+gc  )*AS2_LD + rb    ];
                af[mt][1] = Ab[(kk2+gc  )*AS2_LD + rb + 8];
                af[mt][2] = Ab[(kk2+gc+4)*AS2_LD + rb    ];
                af[mt][3] = Ab[(kk2+gc+4)*AS2_LD + rb + 8];
            }
            #pragma unroll
            for (int nt = 0; nt < 4; nt++) {
                int cb = wn + nt*8 + gr;
                unsigned b0 = Bb2[(kk2+gc  )*BS2_LD + cb];
                unsigned b1 = Bb2[(kk2+gc+4)*BS2_LD + cb];
                mma_bf16(acc[0][nt], af[0][0], af[0][1], af[0][2], af[0][3], b0, b1);
                mma_bf16(acc[1][nt], af[1][0], af[1][1], af[1][2], af[1][3], b0, b1);
            }
        }

        if (has_next) {
            int nb = buf ^ 1;
            unsigned* An = As + nb*16*AS2_LD;
            unsigned* Bn = Bs + nb*16*BS2_LD;
            #pragma unroll
            for (int i = 0; i < 4; i++) {
                int m = arow + i*32;
                An[(ap+0)*AS2_LD + m] = pkbf(ra[i].x, ra[i].y);
                An[(ap+1)*AS2_LD + m] = pkbf(ra[i].z, ra[i].w);
            }
            uint4 bv;
            bv.x = pkbf(rw0.x, rw1.x); bv.y = pkbf(rw0.y, rw1.y);
            bv.z = pkbf(rw0.z, rw1.z); bv.w = pkbf(rw0.w, rw1.w);
            *(uint4*)&Bn[wkp*BS2_LD + wq] = bv;
        }
        __syncthreads();
        buf ^= 1;
    }

    #pragma unroll
    for (int mt = 0; mt < 2; mt++) {
        #pragma unroll
        for (int nt = 0; nt < 4; nt++) {
            int col = n0 + wn + nt*8 + gc*2;
            float b0 = 0.f, b1 = 0.f;
            if (bias) { b0 = bias[col]; b1 = bias[col+1]; }
            #pragma unroll
            for (int half = 0; half < 2; half++) {
                int m = m0 + wm + mt*16 + gr + half*8;
                long long off = (long long)m*N + col;
                float c0 = acc[mt][nt][half*2+0] + b0;
                float c1 = acc[mt][nt][half*2+1] + b1;
                if (epi == 1) {
                    c0 = 0.5f*c0*(1.0f + erff(c0*0.70710678118654752f));
                    c1 = 0.5f*c1*(1.0f + erff(c1*0.70710678118654752f));
                } else if (epi == 2) {
                    float2 rr = *(const float2*)(resp + off);
                    c0 += rr.x; c1 += rr.y;
                }
                float2 o; o.x = c0; o.y = c1;
                *(float2*)(Cout + off) = o;
            }
        }
    }
}

// ---------------- fused vattn: (0.25*sum_h linv*probs) @ vmix, bf16 MMA ------
#define VAT_AS2_LD 68       // [16 pairs][64 m + pad] uints
#define VAT_BS2_LD 196      // [16 pairs][192 n + pad] uints
#define VATTN_SMEM ((2*16*VAT_AS2_LD + 2*16*VAT_BS2_LD + 256)*4)

__global__ void __launch_bounds__(256) vattn_tc_kernel(
    const __nv_bfloat16* __restrict__ pg, const float* __restrict__ linvG,
    const float* __restrict__ vmix, float* __restrict__ va)
{
    extern __shared__ unsigned sv_u[];
    unsigned* As = sv_u;                          // [2][16][68]
    unsigned* Bs = sv_u + 2*16*VAT_AS2_LD;        // [2][16][196]
    float* linv_s = (float*)(sv_u + 2*16*VAT_AS2_LD + 2*16*VAT_BS2_LD);

    const int b  = blockIdx.y;
    const int i0 = blockIdx.x * 64;
    const int tid = threadIdx.x;
    const int lane = tid & 31, wid = tid >> 5;
    const int wm = (wid >> 2) * 32;
    const int wn = (wid & 3) * 48;
    const int gr = lane >> 2, gc = lane & 3;

    const size_t pstride = (size_t)Nn * Nn;
    const __nv_bfloat16* pb = pg + (size_t)b*4*pstride + (size_t)i0*Nn;
    const float* vb = vmix + (size_t)b*Nn*192;

    {
        int hh = tid >> 6, ii = tid & 63;
        linv_s[hh*64 + ii] = 0.25f * linvG[(size_t)(b*4 + hh)*Nn + i0 + ii];
    }
    __syncthreads();

    // A loader: row = tid>>2 (0..63), 8 k-floats = 4 pairs per thread
    const int arow = tid >> 2;
    const int akq  = (tid & 3) * 8;
    const int app  = (tid & 3) * 4;       // pair base
    float lr[4];
    #pragma unroll
    for (int h = 0; h < 4; h++) lr[h] = linv_s[h*64 + arow];
    const __nv_bfloat16* arp = pb + (size_t)arow*Nn + akq;

    // B loader: 3 groups; each = one k-pair x 4 cols
    int bk[3], bc[3];
    #pragma unroll
    for (int t = 0; t < 3; t++) {
        int idx = tid + t*256;            // 0..767 over 16 pairs x 48 col-quads
        bk[t] = idx / 48;
        bc[t] = (idx - bk[t]*48) * 4;
    }

    uint4 pa[4];
    float4 rb0[3], rb1[3];
    #pragma unroll
    for (int h = 0; h < 4; h++) pa[h] = *(const uint4*)(arp + h*pstride);
    #pragma unroll
    for (int t = 0; t < 3; t++) {
        rb0[t] = *(const float4*)(vb + (size_t)(2*bk[t]  )*192 + bc[t]);
        rb1[t] = *(const float4*)(vb + (size_t)(2*bk[t]+1)*192 + bc[t]);
    }

    {
        float f[8] = {0,0,0,0,0,0,0,0};
        #pragma unroll
        for (int h = 0; h < 4; h++) {
            const __nv_bfloat162* pp2 = (const __nv_bfloat162*)&pa[h];
            float lh = lr[h];
            #pragma unroll
            for (int t = 0; t < 4; t++) {
                float2 xy = __bfloat1622float2(pp2[t]);
                f[t*2+0] += lh*xy.x; f[t*2+1] += lh*xy.y;
            }
        }
        #pragma unroll
        for (int jj = 0; jj < 4; jj++)
            As[(app+jj)*VAT_AS2_LD + arow] = pkbf(f[2*jj], f[2*jj+1]);
        #pragma unroll
        for (int t = 0; t < 3; t++) {
            uint4 bv;
            bv.x = pkbf(rb0[t].x, rb1[t].x); bv.y = pkbf(rb0[t].y, rb1[t].y);
            bv.z = pkbf(rb0[t].z, rb1[t].z); bv.w = pkbf(rb0[t].w, rb1[t].w);
            *(uint4*)&Bs[bk[t]*VAT_BS2_LD + bc[t]] = bv;
        }
    }
    __syncthreads();

    float acc[2][6][4];
    #pragma unroll
    for (int mt = 0; mt < 2; mt++)
        #pragma unroll
        for (int nt = 0; nt < 6; nt++)
            #pragma unroll
            for (int j = 0; j < 4; j++) acc[mt][nt][j] = 0.f;

    int buf = 0;
    for (int k0 = 0; k0 < Nn; k0 += TCK) {
        const bool has_next = (k0 + TCK) < Nn;
        if (has_next) {
            #pragma unroll
            for (int h = 0; h < 4; h++) pa[h] = *(const uint4*)(arp + h*pstride + k0 + TCK);
            #pragma unroll
            for (int t = 0; t < 3; t++) {
                rb0[t] = *(const float4*)(vb + (size_t)(k0 + TCK + 2*bk[t]  )*192 + bc[t]);
                rb1[t] = *(const float4*)(vb + (size_t)(k0 + TCK + 2*bk[t]+1)*192 + bc[t]);
            }
        }

        const unsigned* Ab  = As + buf*16*VAT_AS2_LD;
        const unsigned* Bb2 = Bs + buf*16*VAT_BS2_LD;
        #pragma unroll
        for (int kk2 = 0; kk2 < 16; kk2 += 8) {
            unsigned af[2][4];
            #pragma unroll
            for (int mt = 0; mt < 2; mt++) {
                int rb = wm + mt*16 + gr;
                af[mt][0] = Ab[(kk2+gc  )*VAT_AS2_LD + rb    ];
                af[mt][1] = Ab[(kk2+gc  )*VAT_AS2_LD + rb + 8];
                af[mt][2] = Ab[(kk2+gc+4)*VAT_AS2_LD + rb    ];
                af[mt][3] = Ab[(kk2+gc+4)*VAT_AS2_LD + rb + 8];
            }
            #pragma unroll
            for (int nt = 0; nt < 6; nt++) {
                int cb = wn + nt*8 + gr;
                unsigned b0 = Bb2[(kk2+gc  )*VAT_BS2_LD + cb];
                unsigned b1 = Bb2[(kk2+gc+4)*VAT_BS2_LD + cb];
                mma_bf16(acc[0][nt], af[0][0], af[0][1], af[0][2], af[0][3], b0, b1);
                mma_bf16(acc[1][nt], af[1][0], af[1][1], af[1][2], af[1][3], b0, b1);
            }
        }

        if (has_next) {
            int nb = buf ^ 1;
            unsigned* An = As + nb*16*VAT_AS2_LD;
            unsigned* Bn = Bs + nb*16*VAT_BS2_LD;
            float f[8] = {0,0,0,0,0,0,0,0};
            #pragma unroll
            for (int h = 0; h < 4; h++) {
                const __nv_bfloat162* pp2 = (const __nv_bfloat162*)&pa[h];
                float lh = lr[h];
                #pragma unroll
                for (int t = 0; t < 4; t++) {
                    float2 xy = __bfloat1622float2(pp2[t]);
                    f[t*2+0] += lh*xy.x; f[t*2+1] += lh*xy.y;
                }
            }
            #pragma unroll
            for (int jj = 0; jj < 4; jj++)
                An[(app+jj)*VAT_AS2_LD + arow] = pkbf(f[2*jj], f[2*jj+1]);
            #pragma unroll
            for (int t = 0; t < 3; t++) {
                uint4 bv;
                bv.x = pkbf(rb0[t].x, rb1[t].x); bv.y = pkbf(rb0[t].y, rb1[t].y);
                bv.z = pkbf(rb0[t].z, rb1[t].z); bv.w = pkbf(rb0[t].w, rb1[t].w);
                *(uint4*)&Bn[bk[t]*VAT_BS2_LD + bc[t]] = bv;
            }
        }
        __syncthreads();
        buf ^= 1;
    }

    #pragma unroll
    for (int mt = 0; mt < 2; mt++) {
        #pragma unroll
        for (int nt = 0; nt < 6; nt++) {
            int col = wn + nt*8 + gc*2;
            #pragma unroll
            for (int half = 0; half < 2; half++) {
                int m = wm + mt*16 + gr + half*8;
                float2 o;
                o.x = acc[mt][nt][half*2+0];
                o.y = acc[mt][nt][half*2+1];
                *(float2*)(va + ((size_t)b*Nn + i0 + m)*192 + col) = o;
            }
        }
    }
}

// ---------------- small per-row channel mixes -------------------------------
__global__ void __launch_bounds__(192) vout_kernel(
    const float* __restrict__ vattn, const float* __restrict__ Wvo,
    const float* __restrict__ vin, float* __restrict__ outv)
{
    long long row = blockIdx.x;
    int tid = threadIdx.x;
    __shared__ float vrow[192];
    vrow[tid] = vattn[row*192 + tid];
    __syncthreads();
    int x = tid >> 6, e = tid & 63;
    float acc = 0.f;
    #pragma unroll 8
    for (int c = 0; c < 64; c++) acc += vrow[c*3 + x] * Wvo[c*64 + e];
    outv[row*192 + e*3 + x] = vin[row*192 + e*3 + x] + acc;
}

// 4 rows per CTA, register-blocked weight reuse
__global__ void __launch_bounds__(256) vffn_kernel(
    const float* __restrict__ vn, const float* __restrict__ Wfv1,
    const float* __restrict__ Wfv2, float* __restrict__ outv)
{
    long long row0 = (long long)blockIdx.x * 4;
    int tid = threadIdx.x;
    __shared__ float vrow[4][192];
    __shared__ float t[12][260];

    for (int idx = tid; idx < 768; idx += 256) {
        int r = idx / 192, j = idx - r*192;
        vrow[r][j] = vn[(row0 + r)*192 + j];
    }
    __syncthreads();

    {
        float acc[12];
        #pragma unroll
        for (int j = 0; j < 12; j++) acc[j] = 0.f;
        #pragma unroll 4
        for (int c = 0; c < 64; c++) {
            float w = Wfv1[c*256 + tid];
            #pragma unroll
            for (int r = 0; r < 4; r++)
                #pragma unroll
                for (int x = 0; x < 3; x++)
                    acc[r*3+x] += vrow[r][c*3+x] * w;
        }
        #pragma unroll
        for (int j = 0; j < 12; j++) t[j][tid] = acc[j];
    }
    __syncthreads();

    {
        int c = tid & 63, r = tid >> 6;
        float acc[3] = {0.f, 0.f, 0.f};
        #pragma unroll 4
        for (int h = 0; h < 256; h++) {
            float w2 = Wfv2[h*64 + c];
            #pragma unroll
            for (int x = 0; x < 3; x++)
                acc[x] += t[r*3+x][h] * w2;
        }
        #pragma unroll
        for (int x = 0; x < 3; x++)
            outv[(row0 + r)*192 + c*3 + x] += acc[x];
    }
}

// ---------------- fused attention: tf32 MMA flash, single pass ---------------
#define ATK 32
#define Q_LD 260
#define K_LD 260
#define V_LD 264
#define PS2_LD 36
#define ATTN_SMEM_FLOATS (64*Q_LD + 32*K_LD + 32*V_LD + 4*64*PS2_LD + 256 + 128)

__global__ void __launch_bounds__(256) attn_kernel(
    const float* __restrict__ qg, const float* __restrict__ kg,
    const float* __restrict__ vg, const float* __restrict__ pos,
    const float* __restrict__ wdist, const float* __restrict__ bdist,
    __nv_bfloat16* __restrict__ probsG, float* __restrict__ linvG,
    float* __restrict__ sattn)
{
    extern __shared__ float sm[];
    float* q_s  = sm;
    float* k_s  = q_s + 64*Q_LD;
    float* v_s  = k_s + 32*K_LD;
    float* ps   = v_s + 32*V_LD;
    float* posi = ps + 4*64*PS2_LD;
    float* posm = posi + 256;

    const int b  = blockIdx.y;
    const int n0 = blockIdx.x * 64;
    const int tid = threadIdx.x;
    const int lane = tid & 31, wid = tid >> 5;
    const int h  = wid >> 1;
    const int wm = (wid & 1) * 32;
    const int gr = lane >> 2, gc = lane & 3;
    const long long bofs = (long long)b * Nn;

    for (int idx = tid; idx < 4096; idx += 256) {
        int i = idx >> 6, d4 = (idx & 63) << 2;
        float4 qv = *(const float4*)(qg + (bofs + n0 + i)*Ss + d4);
        float* dst = q_s + i*Q_LD + d4;
        dst[0] = f2tff(qv.x); dst[1] = f2tff(qv.y);
        dst[2] = f2tff(qv.z); dst[3] = f2tff(qv.w);
    }
    if (tid < 64) {
        const float* pp = pos + (bofs + n0 + tid)*3;
        float a = pp[0], b2 = pp[1], c = pp[2];
        posi[tid*4+0]=a; posi[tid*4+1]=b2; posi[tid*4+2]=c; posi[tid*4+3]=a*a+b2*b2+c*c;
    }
    const float wh = wdist[h], bh = bdist[h];
    __syncthreads();

    float accO[2][8][4];
    #pragma unroll
    for (int mt = 0; mt < 2; mt++)
        #pragma unroll
        for (int nt = 0; nt < 8; nt++)
            #pragma unroll
            for (int j = 0; j < 4; j++) accO[mt][nt][j] = 0.f;
    float rs[2][2] = {{0.f,0.f},{0.f,0.f}};

    __nv_bfloat16* pgbase = probsG + ((size_t)(b*4 + h)*Nn + n0)*Nn;
    float* psh = ps + h*64*PS2_LD;

    for (int t64 = 0; t64 < 64; t64++) {
        const int m0g = t64 * ATK;
        for (int idx = tid; idx < 2048; idx += 256) {
            int m = idx >> 6, d4 = (idx & 63) << 2;
            long long gofs = (bofs + m0g + m)*Ss + d4;
            float4 kv4 = *(const float4*)(kg + gofs);
            float4 vv4 = *(const float4*)(vg + gofs);
            float* kd = k_s + m*K_LD + d4;
            kd[0]=f2tff(kv4.x); kd[1]=f2tff(kv4.y); kd[2]=f2tff(kv4.z); kd[3]=f2tff(kv4.w);
            float* vd = v_s + m*V_LD + d4;
            vd[0]=f2tff(vv4.x); vd[1]=f2tff(vv4.y); vd[2]=f2tff(vv4.z); vd[3]=f2tff(vv4.w);
        }
        if (tid < 32) {
            const float* pp = pos + (bofs + m0g + tid)*3;
            float a = pp[0], b2 = pp[1], c = pp[2];
            posm[tid*4+0]=a; posm[tid*4+1]=b2; posm[tid*4+2]=c; posm[tid*4+3]=a*a+b2*b2+c*c;
        }
        __syncthreads();

        float acc[2][4][4];
        #pragma unroll
        for (int mt = 0; mt < 2; mt++)
            #pragma unroll
            for (int nt = 0; nt < 4; nt++)
                #pragma unroll
                for (int j = 0; j < 4; j++) acc[mt][nt][j] = 0.f;

        #pragma unroll
        for (int kk = 0; kk < 64; kk += 8) {
            unsigned af[2][4];
            #pragma unroll
            for (int mt = 0; mt < 2; mt++) {
                const float* qp = q_s + (wm + mt*16 + gr)*Q_LD + h*64 + kk + gc;
                af[mt][0] = __float_as_uint(qp[0]);
                af[mt][1] = __float_as_uint(qp[8*Q_LD]);
                af[mt][2] = __float_as_uint(qp[4]);
                af[mt][3] = __float_as_uint(qp[8*Q_LD+4]);
            }
            #pragma unroll
            for (int nt = 0; nt < 4; nt++) {
                const float* kp = k_s + (nt*8 + gr)*K_LD + h*64 + kk + gc;
                unsigned b0 = __float_as_uint(kp[0]);
                unsigned b1 = __float_as_uint(kp[4]);
                mma_tf32(acc[0][nt], af[0][0], af[0][1], af[0][2], af[0][3], b0, b1);
                mma_tf32(acc[1][nt], af[1][0], af[1][1], af[1][2], af[1][3], b0, b1);
            }
        }

        #pragma unroll
        for (int mt = 0; mt < 2; mt++) {
            int r0 = wm + mt*16 + gr;
            float4 pi0 = ((const float4*)posi)[r0];
            float4 pi1 = ((const float4*)posi)[r0+8];
            #pragma unroll
            for (int nt = 0; nt < 4; nt++) {
                int mloc = nt*8 + gc*2;
                float4 pm0 = ((const float4*)posm)[mloc];
                float4 pm1 = ((const float4*)posm)[mloc+1];
                float p4[4];
                #pragma unroll
                for (int e = 0; e < 4; e++) {
                    float4 pi = (e < 2) ? pi0 : pi1;
                    float4 pm = (e & 1) ? pm1 : pm0;
                    float d2 = pi.w + pm.w - 2.f*(pi.x*pm.x + pi.y*pm.y + pi.z*pm.z);
                    d2 = fmaxf(d2, 1e-12f);
                    float dist = d2 * rsqrtf(d2);
                    float sx = dist*wh + bh;
                    float sg = __fdividef(1.f, 1.f + __expf(sx));
                    p4[e] = __expf(acc[mt][nt][e]*0.125f) * sg;
                }
                rs[mt][0] += p4[0] + p4[1];
                rs[mt][1] += p4[2] + p4[3];
                *(float2*)(psh + r0*PS2_LD + mloc) = make_float2(f2tff(p4[0]), f2tff(p4[1]));
                *(float2*)(psh + (r0+8)*PS2_LD + mloc) = make_float2(f2tff(p4[2]), f2tff(p4[3]));
                __nv_bfloat162 q01 = __floats2bfloat162_rn(p4[0], p4[1]);
                __nv_bfloat162 q23 = __floats2bfloat162_rn(p4[2], p4[3]);
                __stcs((unsigned int*)(pgbase + (size_t)r0*Nn + m0g + mloc),
                       *(unsigned int*)&q01);
                __stcs((unsigned int*)(pgbase + (size_t)(r0+8)*Nn + m0g + mloc),
                       *(unsigned int*)&q23);
            }
        }
        __syncwarp();

        #pragma unroll
        for (int kk = 0; kk < 32; kk += 8) {
            unsigned af[2][4];
            #pragma unroll
            for (int mt = 0; mt < 2; mt++) {
                const float* pp = psh + (wm + mt*16 + gr)*PS2_LD + kk + gc;
                af[mt][0] = __float_as_uint(pp[0]);
                af[mt][1] = __float_as_uint(pp[8*PS2_LD]);
                af[mt][2] = __float_as_uint(pp[4]);
                af[mt][3] = __float_as_uint(pp[8*PS2_LD+4]);
            }
            #pragma unroll
            for (int nt = 0; nt < 8; nt++) {
                const float* vp2 = v_s + (kk+gc)*V_LD + h*64 + nt*8 + gr;
                unsigned b0 = __float_as_uint(vp2[0]);
                unsigned b1 = __float_as_uint(vp2[4*V_LD]);
                mma_tf32(accO[0][nt], af[0][0], af[0][1], af[0][2], af[0][3], b0, b1);
                mma_tf32(accO[1][nt], af[1][0], af[1][1], af[1][2], af[1][3], b0, b1);
            }
        }
        __syncthreads();
    }

    float linv[2][2];
    #pragma unroll
    for (int mt = 0; mt < 2; mt++)
        #pragma unroll
        for (int hh = 0; hh < 2; hh++) {
            float v = rs[mt][hh];
            v += __shfl_xor_sync(0xffffffffu, v, 1);
            v += __shfl_xor_sync(0xffffffffu, v, 2);
            linv[mt][hh] = __fdividef(1.f, v);
        }
    if (gc == 0) {
        #pragma unroll
        for (int mt = 0; mt < 2; mt++) {
            int r0 = wm + mt*16 + gr;
            linvG[(size_t)(b*4 + h)*Nn + n0 + r0]     = linv[mt][0];
            linvG[(size_t)(b*4 + h)*Nn + n0 + r0 + 8] = linv[mt][1];
        }
    }
    #pragma unroll
    for (int mt = 0; mt < 2; mt++) {
        #pragma unroll
        for (int nt = 0; nt < 8; nt++) {
            int col = h*64 + nt*8 + gc*2;
            int r0 = wm + mt*16 + gr;
            float2 o0, o1;
            o0.x = accO[mt][nt][0]*linv[mt][0];
            o0.y = accO[mt][nt][1]*linv[mt][0];
            o1.x = accO[mt][nt][2]*linv[mt][1];
            o1.y = accO[mt][nt][3]*linv[mt][1];
            *(float2*)(sattn + (bofs + n0 + r0)*Ss + col) = o0;
            *(float2*)(sattn + (bofs + n0 + r0 + 8)*Ss + col) = o1;
        }
    }
}

// ---------------- launch ------------------------------------------------------
extern "C" void kernel_launch(void* const* d_in, const int* in_sizes, int n_in,
                              void* d_out, int out_size)
{
    const float* s_in  = (const float*)d_in[0];
    const float* v_in  = (const float*)d_in[1];
    const float* pos   = (const float*)d_in[2];
    const float* Wq    = (const float*)d_in[3];
    const float* bq    = (const float*)d_in[4];
    const float* Wk    = (const float*)d_in[5];
    const float* bk    = (const float*)d_in[6];
    const float* Wv    = (const float*)d_in[7];
    const float* bv    = (const float*)d_in[8];
    const float* Wo    = (const float*)d_in[9];
    const float* bo    = (const float*)d_in[10];
    const float* wdist = (const float*)d_in[11];
    const float* bdist = (const float*)d_in[12];
    const float* Wvv   = (const float*)d_in[13];
    const float* Wvo   = (const float*)d_in[14];
    const float* g1    = (const float*)d_in[15];
    const float* be1   = (const float*)d_in[16];
    const float* vs1   = (const float*)d_in[17];
    const float* g2    = (const float*)d_in[18];
    const float* be2   = (const float*)d_in[19];
    const float* vs2   = (const float*)d_in[20];
    const float* Wf1   = (const float*)d_in[21];
    const float* bf1   = (const float*)d_in[22];
    const float* Wf2   = (const float*)d_in[23];
    const float* bf2   = (const float*)d_in[24];
    const float* Wfv1  = (const float*)d_in[25];
    const float* Wfv2  = (const float*)d_in[26];

    float* out_s = (float*)d_out;
    float* out_v = out_s + (size_t)ROWS*Ss;

    void *p_sn, *p_vn, *p_q, *p_k, *p_vp, *p_vmix, *p_pb, *p_li, *p_sa, *p_va, *p_ffn;
    cudaGetSymbolAddress(&p_sn, g_sn);
    cudaGetSymbolAddress(&p_vn, g_vn);
    cudaGetSymbolAddress(&p_q,  g_q);
    cudaGetSymbolAddress(&p_k,  g_k);
    cudaGetSymbolAddress(&p_vp, g_vp);
    cudaGetSymbolAddress(&p_vmix, g_vmix);
    cudaGetSymbolAddress(&p_pb, g_probs);
    cudaGetSymbolAddress(&p_li, g_linv);
    cudaGetSymbolAddress(&p_sa, g_sattn);
    cudaGetSymbolAddress(&p_va, g_vattn);
    cudaGetSymbolAddress(&p_ffn, g_ffn);
    float* sn   = (float*)p_sn;   float* vn   = (float*)p_vn;
    float* q    = (float*)p_q;    float* k    = (float*)p_k;
    float* vp   = (float*)p_vp;   float* vmix = (float*)p_vmix;
    __nv_bfloat16* pb = (__nv_bfloat16*)p_pb;
    float* li   = (float*)p_li;
    float* sa   = (float*)p_sa;   float* va   = (float*)p_va;
    float* ffn  = (float*)p_ffn;

    const int attn_smem = ATTN_SMEM_FLOATS * 4;
    cudaFuncSetAttribute(attn_kernel, cudaFuncAttributeMaxDynamicSharedMemorySize, attn_smem);
    cudaFuncSetAttribute(gemm_tc_kernel, cudaFuncAttributeMaxDynamicSharedMemorySize, GEMM_TC_SMEM);
    cudaFuncSetAttribute(vattn_tc_kernel, cudaFuncAttributeMaxDynamicSharedMemorySize, VATTN_SMEM);

    // 1) eq-LN #1 (+ fused vmix = vn @ Wvv)
    eqln_kernel<<<ROWS, 256>>>(s_in, v_in, g1, be1, vs1, sn, vn, Wvv, vmix);

    // 2) QKV projections (bf16 tensor cores)
    dim3 gproj(Ss/64, ROWS/128, 1);
    gemm_tc_kernel<<<gproj, 256, GEMM_TC_SMEM>>>(sn, Wq, bq, nullptr, q,  ROWS, Ss, Ss, 0);
    gemm_tc_kernel<<<gproj, 256, GEMM_TC_SMEM>>>(sn, Wk, bk, nullptr, k,  ROWS, Ss, Ss, 0);
    gemm_tc_kernel<<<gproj, 256, GEMM_TC_SMEM>>>(sn, Wv, bv, nullptr, vp, ROWS, Ss, Ss, 0);

    // 3) fused single-pass tf32-MMA attention -> sattn, bf16 probs, linv
    attn_kernel<<<dim3(Nn/64, Bb), 256, attn_smem>>>(q, k, vp, pos, wdist, bdist, pb, li, sa);

    // 4) fused v_attn = (0.25*sum_h linv*probs) @ vmix  (bf16 MMA, reads bf16 probs)
    vattn_tc_kernel<<<dim3(Nn/64, Bb), 256, VATTN_SMEM>>>(pb, li, vmix, va);

    // 5) out_s = s_in + sattn @ Wo + bo
    gemm_tc_kernel<<<gproj, 256, GEMM_TC_SMEM>>>(sa, Wo, bo, s_in, out_s, ROWS, Ss, Ss, 2);

    // 6) out_v = v_in + v_attn @ Wvo
    vout_kernel<<<ROWS, 192>>>(va, Wvo, v_in, out_v);

    // 7) eq-LN #2 (no vmix)
    eqln_kernel<<<ROWS, 256>>>(out_s, out_v, g2, be2, vs2, sn, vn, nullptr, nullptr);

    // 8) FFN (bf16 tensor cores, GELU + residual epilogues)
    gemm_tc_kernel<<<dim3(Ff/64, ROWS/128, 1), 256, GEMM_TC_SMEM>>>(sn, Wf1, bf1, nullptr, ffn, ROWS, Ff, Ss, 1);
    gemm_tc_kernel<<<dim3(Ss/64, ROWS/128, 1), 256, GEMM_TC_SMEM>>>(ffn, Wf2, bf2, out_s, out_s, ROWS, Ss, Ff, 2);

    // 9) vector FFN (4 rows per CTA)
    vffn_kernel<<<ROWS/4, 256>>>(vn, Wfv1, Wfv2, out_v);
}

// round 15
// speedup vs baseline: 2.6623x; 1.0859x over previous
#include <cuda_runtime.h>
#include <cuda_bf16.h>
#include <math.h>

#define Bb   4
#define Nn   2048
#define Ss   256
#define Cc   64
#define Hh   4
#define Dd   64
#define Ff   1024
#define ROWS (Bb*Nn)          // 8192

// ---------------- scratch (static device memory; no allocations) -------------
__device__ float g_sn[ROWS*Ss];
__device__ float g_vn[ROWS*Cc*3];
__device__ float g_q[ROWS*Ss];
__device__ float g_k[ROWS*Ss];
__device__ float g_vp[ROWS*Ss];
__device__ float g_vmix[ROWS*Cc*3];
__device__ __nv_bfloat16 g_probs[(size_t)Bb*Hh*Nn*Nn];   // 134 MB unnormalized probs
__device__ float g_linv[(size_t)Bb*Hh*Nn];
__device__ float g_sattn[ROWS*Ss];
__device__ float g_vattn[ROWS*Cc*3];
__device__ float g_ffn[ROWS*Ff];

// ---------------- cp.async helpers -------------------------------------------
__device__ __forceinline__ void cp16(void* s, const void* g) {
    unsigned sa = (unsigned)__cvta_generic_to_shared(s);
    asm volatile("cp.async.cg.shared.global [%0], [%1], 16;\n" :: "r"(sa), "l"(g) : "memory");
}
#define CP_COMMIT() asm volatile("cp.async.commit_group;\n" ::: "memory")
#define CP_WAIT0()  asm volatile("cp.async.wait_group 0;\n" ::: "memory")
#define CP_WAIT1()  asm volatile("cp.async.wait_group 1;\n" ::: "memory")

// ---------------- eq layernorm (+ optional fused vmix) -----------------------
__global__ void __launch_bounds__(256) eqln_kernel(
    const float* __restrict__ sin, const float* __restrict__ vin,
    const float* __restrict__ g, const float* __restrict__ be,
    const float* __restrict__ vsc,
    float* __restrict__ sn, float* __restrict__ vn,
    const float* __restrict__ Wvv, float* __restrict__ vmixO)
{
    long long row = blockIdx.x;
    int tid = threadIdx.x;
    __shared__ float redA[8], redB[8], norms[64], st[3], vsh[192];

    float x = sin[row*Ss + tid];
    float s1 = x, s2 = x*x;
    #pragma unroll
    for (int o = 16; o; o >>= 1) {
        s1 += __shfl_xor_sync(0xffffffffu, s1, o);
        s2 += __shfl_xor_sync(0xffffffffu, s2, o);
    }
    if ((tid & 31) == 0) { redA[tid>>5] = s1; redB[tid>>5] = s2; }

    if (tid < 64) {
        const float* vp = vin + row*192 + tid*3;
        float a = vp[0], b2 = vp[1], c = vp[2];
        norms[tid] = sqrtf(a*a + b2*b2 + c*c);
    }
    __syncthreads();
    if (tid == 0) {
        float A = 0.f, Bs2 = 0.f;
        #pragma unroll
        for (int w = 0; w < 8; w++) { A += redA[w]; Bs2 += redB[w]; }
        float mu  = A * (1.f/256.f);
        float var = Bs2 * (1.f/256.f) - mu*mu;
        st[0] = mu; st[1] = rsqrtf(var + 1e-5f);
        float t = 0.f;
        for (int c = 0; c < 64; c++) t += norms[c];
        st[2] = t * (1.f/64.f);
    }
    __syncthreads();
    sn[row*Ss + tid] = (x - st[0]) * st[1] * g[tid] + be[tid];
    if (tid < 192) {
        int c = tid / 3;
        float val = vin[row*192 + tid] / (norms[c] + 1e-5f) * st[2] * vsc[c];
        vn[row*192 + tid] = val;
        vsh[tid] = val;
    }
    if (vmixO) {
        __syncthreads();
        if (tid < 192) {
            int xx = tid >> 6, e = tid & 63;
            float acc = 0.f;
            #pragma unroll 8
            for (int c = 0; c < 64; c++) acc += vsh[c*3 + xx] * Wvv[c*64 + e];
            vmixO[row*192 + e*3 + xx] = acc;
        }
    }
}

// ---------------- bf16 tensor-core GEMM: 128x64 CTA, mma.m16n8k16 ------------
#define TCK 32
#define AS2_LD 132          // [16 pairs][128 m + pad] uints
#define BS2_LD 68           // [16 pairs][64 n + pad] uints
#define GEMM_TC_SMEM ((2*16*AS2_LD + 2*16*BS2_LD)*4)

__device__ __forceinline__ unsigned pkbf(float x, float y) {
    __nv_bfloat162 h = __floats2bfloat162_rn(x, y);
    return *(unsigned*)&h;
}

__device__ __forceinline__ void mma_bf16(float* c,
    unsigned a0, unsigned a1, unsigned a2, unsigned a3,
    unsigned b0, unsigned b1)
{
    asm volatile(
        "mma.sync.aligned.m16n8k16.row.col.f32.bf16.bf16.f32 "
        "{%0,%1,%2,%3}, {%4,%5,%6,%7}, {%8,%9}, {%0,%1,%2,%3};\n"
        : "+f"(c[0]), "+f"(c[1]), "+f"(c[2]), "+f"(c[3])
        : "r"(a0), "r"(a1), "r"(a2), "r"(a3), "r"(b0), "r"(b1));
}

__device__ __forceinline__ unsigned f2tf(float x) {
    unsigned r;
    asm("cvt.rna.tf32.f32 %0, %1;" : "=r"(r) : "f"(x));
    return r;
}
__device__ __forceinline__ float f2tff(float x) { return __uint_as_float(f2tf(x)); }

__device__ __forceinline__ void mma_tf32(float* c,
    unsigned a0, unsigned a1, unsigned a2, unsigned a3,
    unsigned b0, unsigned b1)
{
    asm volatile(
        "mma.sync.aligned.m16n8k8.row.col.f32.tf32.tf32.f32 "
        "{%0,%1,%2,%3}, {%4,%5,%6,%7}, {%8,%9}, {%0,%1,%2,%3};\n"
        : "+f"(c[0]), "+f"(c[1]), "+f"(c[2]), "+f"(c[3])
        : "r"(a0), "r"(a1), "r"(a2), "r"(a3), "r"(b0), "r"(b1));
}

__device__ __forceinline__ void gemm_tc_body(
    const float* __restrict__ A, const float* __restrict__ W,
    const float* __restrict__ bias, const float* __restrict__ resp,
    float* __restrict__ Cout,
    int N, int K, int epi, unsigned* sm_u)
{
    unsigned* As = sm_u;
    unsigned* Bs = sm_u + 2*16*AS2_LD;

    const int tid = threadIdx.x;
    const int lane = tid & 31, wid = tid >> 5;
    const int wm = (wid >> 1) * 32;
    const int wn = (wid & 1) * 32;
    const int m0 = blockIdx.y * 128, n0 = blockIdx.x * 64;
    const int gr = lane >> 2, gc = lane & 3;

    const int arow = tid >> 3;
    const int aq   = (tid & 7) * 4;
    const int ap   = (tid & 7) * 2;
    const int wkp  = tid >> 4;
    const int wq   = (tid & 15) * 4;

    const float* Aptr = A + (long long)(m0 + arow)*K + aq;
    const float* Wp0  = W + (long long)(2*wkp  )*N + n0 + wq;
    const float* Wp1  = W + (long long)(2*wkp+1)*N + n0 + wq;
    const long long aRowStride32 = (long long)32*K;

    float4 ra[4], rw0, rw1;
    #pragma unroll
    for (int i = 0; i < 4; i++) ra[i] = *(const float4*)(Aptr + i*aRowStride32);
    rw0 = *(const float4*)(Wp0);
    rw1 = *(const float4*)(Wp1);

    #pragma unroll
    for (int i = 0; i < 4; i++) {
        int m = arow + i*32;
        As[(ap+0)*AS2_LD + m] = pkbf(ra[i].x, ra[i].y);
        As[(ap+1)*AS2_LD + m] = pkbf(ra[i].z, ra[i].w);
    }
    {
        uint4 bv;
        bv.x = pkbf(rw0.x, rw1.x); bv.y = pkbf(rw0.y, rw1.y);
        bv.z = pkbf(rw0.z, rw1.z); bv.w = pkbf(rw0.w, rw1.w);
        *(uint4*)&Bs[wkp*BS2_LD + wq] = bv;
    }
    __syncthreads();

    float acc[2][4][4];
    #pragma unroll
    for (int mt = 0; mt < 2; mt++)
        #pragma unroll
        for (int nt = 0; nt < 4; nt++)
            #pragma unroll
            for (int j = 0; j < 4; j++) acc[mt][nt][j] = 0.f;

    int buf = 0;
    for (int k0 = 0; k0 < K; k0 += TCK) {
        const bool has_next = (k0 + TCK) < K;
        if (has_next) {
            #pragma unroll
            for (int i = 0; i < 4; i++) ra[i] = *(const float4*)(Aptr + i*aRowStride32 + k0 + TCK);
            rw0 = *(const float4*)(Wp0 + (long long)(k0 + TCK)*N);
            rw1 = *(const float4*)(Wp1 + (long long)(k0 + TCK)*N);
        }

        const unsigned* Ab = As + buf*16*AS2_LD;
        const unsigned* Bb2 = Bs + buf*16*BS2_LD;
        #pragma unroll
        for (int kk2 = 0; kk2 < 16; kk2 += 8) {
            unsigned af[2][4];
            #pragma unroll
            for (int mt = 0; mt < 2; mt++) {
                int rb = wm + mt*16 + gr;
                af[mt][0] = Ab[(kk2+gc  )*AS2_LD + rb    ];
                af[mt][1] = Ab[(kk2+gc  )*AS2_LD + rb + 8];
                af[mt][2] = Ab[(kk2+gc+4)*AS2_LD + rb    ];
                af[mt][3] = Ab[(kk2+gc+4)*AS2_LD + rb + 8];
            }
            #pragma unroll
            for (int nt = 0; nt < 4; nt++) {
                int cb = wn + nt*8 + gr;
                unsigned b0 = Bb2[(kk2+gc  )*BS2_LD + cb];
                unsigned b1 = Bb2[(kk2+gc+4)*BS2_LD + cb];
                mma_bf16(acc[0][nt], af[0][0], af[0][1], af[0][2], af[0][3], b0, b1);
                mma_bf16(acc[1][nt], af[1][0], af[1][1], af[1][2], af[1][3], b0, b1);
            }
        }

        if (has_next) {
            int nb = buf ^ 1;
            unsigned* An = As + nb*16*AS2_LD;
            unsigned* Bn = Bs + nb*16*BS2_LD;
            #pragma unroll
            for (int i = 0; i < 4; i++) {
                int m = arow + i*32;
                An[(ap+0)*AS2_LD + m] = pkbf(ra[i].x, ra[i].y);
                An[(ap+1)*AS2_LD + m] = pkbf(ra[i].z, ra[i].w);
            }
            uint4 bv;
            bv.x = pkbf(rw0.x, rw1.x); bv.y = pkbf(rw0.y, rw1.y);
            bv.z = pkbf(rw0.z, rw1.z); bv.w = pkbf(rw0.w, rw1.w);
            *(uint4*)&Bn[wkp*BS2_LD + wq] = bv;
        }
        __syncthreads();
        buf ^= 1;
    }

    #pragma unroll
    for (int mt = 0; mt < 2; mt++) {
        #pragma unroll
        for (int nt = 0; nt < 4; nt++) {
            int col = n0 + wn + nt*8 + gc*2;
            float b0 = 0.f, b1 = 0.f;
            if (bias) { b0 = bias[col]; b1 = bias[col+1]; }
            #pragma unroll
            for (int half = 0; half < 2; half++) {
                int m = m0 + wm + mt*16 + gr + half*8;
                long long off = (long long)m*N + col;
                float c0 = acc[mt][nt][half*2+0] + b0;
                float c1 = acc[mt][nt][half*2+1] + b1;
                if (epi == 1) {
                    c0 = 0.5f*c0*(1.0f + erff(c0*0.70710678118654752f));
                    c1 = 0.5f*c1*(1.0f + erff(c1*0.70710678118654752f));
                } else if (epi == 2) {
                    float2 rr = *(const float2*)(resp + off);
                    c0 += rr.x; c1 += rr.y;
                }
                float2 o; o.x = c0; o.y = c1;
                *(float2*)(Cout + off) = o;
            }
        }
    }
}

__global__ void __launch_bounds__(256) gemm_tc_kernel(
    const float* __restrict__ A, const float* __restrict__ W,
    const float* __restrict__ bias, const float* __restrict__ res,
    float* __restrict__ Cout,
    int M, int N, int K, int epi)
{
    extern __shared__ unsigned sm_u[];
    gemm_tc_body(A, W, bias, res, Cout, N, K, epi, sm_u);
}

// QKV batched: blockIdx.z selects projection -> 3x the grid, one launch
__global__ void __launch_bounds__(256) qkv_tc_kernel(
    const float* __restrict__ A,
    const float* __restrict__ Wq, const float* __restrict__ bq, float* __restrict__ qO,
    const float* __restrict__ Wk, const float* __restrict__ bk, float* __restrict__ kO,
    const float* __restrict__ Wv, const float* __restrict__ bv, float* __restrict__ vO)
{
    extern __shared__ unsigned sm_u[];
    const float* W; const float* b; float* C;
    if (blockIdx.z == 0)      { W = Wq; b = bq; C = qO; }
    else if (blockIdx.z == 1) { W = Wk; b = bk; C = kO; }
    else                      { W = Wv; b = bv; C = vO; }
    gemm_tc_body(A, W, b, nullptr, C, Ss, Ss, 0, sm_u);
}

// ---------------- fused vattn: (0.25*sum_h linv*probs) @ vmix, bf16 MMA ------
#define VAT_AS2_LD 68
#define VAT_BS2_LD 196
#define VATTN_SMEM ((2*16*VAT_AS2_LD + 2*16*VAT_BS2_LD + 256)*4)

__global__ void __launch_bounds__(256) vattn_tc_kernel(
    const __nv_bfloat16* __restrict__ pg, const float* __restrict__ linvG,
    const float* __restrict__ vmix, float* __restrict__ va)
{
    extern __shared__ unsigned sv_u[];
    unsigned* As = sv_u;
    unsigned* Bs = sv_u + 2*16*VAT_AS2_LD;
    float* linv_s = (float*)(sv_u + 2*16*VAT_AS2_LD + 2*16*VAT_BS2_LD);

    const int b  = blockIdx.y;
    const int i0 = blockIdx.x * 64;
    const int tid = threadIdx.x;
    const int lane = tid & 31, wid = tid >> 5;
    const int wm = (wid >> 2) * 32;
    const int wn = (wid & 3) * 48;
    const int gr = lane >> 2, gc = lane & 3;

    const size_t pstride = (size_t)Nn * Nn;
    const __nv_bfloat16* pb = pg + (size_t)b*4*pstride + (size_t)i0*Nn;
    const float* vb = vmix + (size_t)b*Nn*192;

    {
        int hh = tid >> 6, ii = tid & 63;
        linv_s[hh*64 + ii] = 0.25f * linvG[(size_t)(b*4 + hh)*Nn + i0 + ii];
    }
    __syncthreads();

    const int arow = tid >> 2;
    const int akq  = (tid & 3) * 8;
    const int app  = (tid & 3) * 4;
    float lr[4];
    #pragma unroll
    for (int h = 0; h < 4; h++) lr[h] = linv_s[h*64 + arow];
    const __nv_bfloat16* arp = pb + (size_t)arow*Nn + akq;

    int bk[3], bc[3];
    #pragma unroll
    for (int t = 0; t < 3; t++) {
        int idx = tid + t*256;
        bk[t] = idx / 48;
        bc[t] = (idx - bk[t]*48) * 4;
    }

    uint4 pa[4];
    float4 rb0[3], rb1[3];
    #pragma unroll
    for (int h = 0; h < 4; h++) pa[h] = *(const uint4*)(arp + h*pstride);
    #pragma unroll
    for (int t = 0; t < 3; t++) {
        rb0[t] = *(const float4*)(vb + (size_t)(2*bk[t]  )*192 + bc[t]);
        rb1[t] = *(const float4*)(vb + (size_t)(2*bk[t]+1)*192 + bc[t]);
    }

    {
        float f[8] = {0,0,0,0,0,0,0,0};
        #pragma unroll
        for (int h = 0; h < 4; h++) {
            const __nv_bfloat162* pp2 = (const __nv_bfloat162*)&pa[h];
            float lh = lr[h];
            #pragma unroll
            for (int t = 0; t < 4; t++) {
                float2 xy = __bfloat1622float2(pp2[t]);
                f[t*2+0] += lh*xy.x; f[t*2+1] += lh*xy.y;
            }
        }
        #pragma unroll
        for (int jj = 0; jj < 4; jj++)
            As[(app+jj)*VAT_AS2_LD + arow] = pkbf(f[2*jj], f[2*jj+1]);
        #pragma unroll
        for (int t = 0; t < 3; t++) {
            uint4 bv;
            bv.x = pkbf(rb0[t].x, rb1[t].x); bv.y = pkbf(rb0[t].y, rb1[t].y);
            bv.z = pkbf(rb0[t].z, rb1[t].z); bv.w = pkbf(rb0[t].w, rb1[t].w);
            *(uint4*)&Bs[bk[t]*VAT_BS2_LD + bc[t]] = bv;
        }
    }
    __syncthreads();

    float acc[2][6][4];
    #pragma unroll
    for (int mt = 0; mt < 2; mt++)
        #pragma unroll
        for (int nt = 0; nt < 6; nt++)
            #pragma unroll
            for (int j = 0; j < 4; j++) acc[mt][nt][j] = 0.f;

    int buf = 0;
    for (int k0 = 0; k0 < Nn; k0 += TCK) {
        const bool has_next = (k0 + TCK) < Nn;
        if (has_next) {
            #pragma unroll
            for (int h = 0; h < 4; h++) pa[h] = *(const uint4*)(arp + h*pstride + k0 + TCK);
            #pragma unroll
            for (int t = 0; t < 3; t++) {
                rb0[t] = *(const float4*)(vb + (size_t)(k0 + TCK + 2*bk[t]  )*192 + bc[t]);
                rb1[t] = *(const float4*)(vb + (size_t)(k0 + TCK + 2*bk[t]+1)*192 + bc[t]);
            }
        }

        const unsigned* Ab  = As + buf*16*VAT_AS2_LD;
        const unsigned* Bb2 = Bs + buf*16*VAT_BS2_LD;
        #pragma unroll
        for (int kk2 = 0; kk2 < 16; kk2 += 8) {
            unsigned af[2][4];
            #pragma unroll
            for (int mt = 0; mt < 2; mt++) {
                int rb = wm + mt*16 + gr;
                af[mt][0] = Ab[(kk2+gc  )*VAT_AS2_LD + rb    ];
                af[mt][1] = Ab[(kk2+gc  )*VAT_AS2_LD + rb + 8];
                af[mt][2] = Ab[(kk2+gc+4)*VAT_AS2_LD + rb    ];
                af[mt][3] = Ab[(kk2+gc+4)*VAT_AS2_LD + rb + 8];
            }
            #pragma unroll
            for (int nt = 0; nt < 6; nt++) {
                int cb = wn + nt*8 + gr;
                unsigned b0 = Bb2[(kk2+gc  )*VAT_BS2_LD + cb];
                unsigned b1 = Bb2[(kk2+gc+4)*VAT_BS2_LD + cb];
                mma_bf16(acc[0][nt], af[0][0], af[0][1], af[0][2], af[0][3], b0, b1);
                mma_bf16(acc[1][nt], af[1][0], af[1][1], af[1][2], af[1][3], b0, b1);
            }
        }

        if (has_next) {
            int nb = buf ^ 1;
            unsigned* An = As + nb*16*VAT_AS2_LD;
            unsigned* Bn = Bs + nb*16*VAT_BS2_LD;
            float f[8] = {0,0,0,0,0,0,0,0};
            #pragma unroll
            for (int h = 0; h < 4; h++) {
                const __nv_bfloat162* pp2 = (const __nv_bfloat162*)&pa[h];
                float lh = lr[h];
                #pragma unroll
                for (int t = 0; t < 4; t++) {
                    float2 xy = __bfloat1622float2(pp2[t]);
                    f[t*2+0] += lh*xy.x; f[t*2+1] += lh*xy.y;
                }
            }
            #pragma unroll
            for (int jj = 0; jj < 4; jj++)
                An[(app+jj)*VAT_AS2_LD + arow] = pkbf(f[2*jj], f[2*jj+1]);
            #pragma unroll
            for (int t = 0; t < 3; t++) {
                uint4 bv;
                bv.x = pkbf(rb0[t].x, rb1[t].x); bv.y = pkbf(rb0[t].y, rb1[t].y);
                bv.z = pkbf(rb0[t].z, rb1[t].z); bv.w = pkbf(rb0[t].w, rb1[t].w);
                *(uint4*)&Bn[bk[t]*VAT_BS2_LD + bc[t]] = bv;
            }
        }
        __syncthreads();
        buf ^= 1;
    }

    #pragma unroll
    for (int mt = 0; mt < 2; mt++) {
        #pragma unroll
        for (int nt = 0; nt < 6; nt++) {
            int col = wn + nt*8 + gc*2;
            #pragma unroll
            for (int half = 0; half < 2; half++) {
                int m = wm + mt*16 + gr + half*8;
                float2 o;
                o.x = acc[mt][nt][half*2+0];
                o.y = acc[mt][nt][half*2+1];
                *(float2*)(va + ((size_t)b*Nn + i0 + m)*192 + col) = o;
            }
        }
    }
}

// ---------------- small per-row channel mixes -------------------------------
__global__ void __launch_bounds__(192) vout_kernel(
    const float* __restrict__ vattn, const float* __restrict__ Wvo,
    const float* __restrict__ vin, float* __restrict__ outv)
{
    long long row = blockIdx.x;
    int tid = threadIdx.x;
    __shared__ float vrow[192];
    vrow[tid] = vattn[row*192 + tid];
    __syncthreads();
    int x = tid >> 6, e = tid & 63;
    float acc = 0.f;
    #pragma unroll 8
    for (int c = 0; c < 64; c++) acc += vrow[c*3 + x] * Wvo[c*64 + e];
    outv[row*192 + e*3 + x] = vin[row*192 + e*3 + x] + acc;
}

// 4 rows per CTA, register-blocked weight reuse
__global__ void __launch_bounds__(256) vffn_kernel(
    const float* __restrict__ vn, const float* __restrict__ Wfv1,
    const float* __restrict__ Wfv2, float* __restrict__ outv)
{
    long long row0 = (long long)blockIdx.x * 4;
    int tid = threadIdx.x;
    __shared__ float vrow[4][192];
    __shared__ float t[12][260];

    for (int idx = tid; idx < 768; idx += 256) {
        int r = idx / 192, j = idx - r*192;
        vrow[r][j] = vn[(row0 + r)*192 + j];
    }
    __syncthreads();

    {
        float acc[12];
        #pragma unroll
        for (int j = 0; j < 12; j++) acc[j] = 0.f;
        #pragma unroll 4
        for (int c = 0; c < 64; c++) {
            float w = Wfv1[c*256 + tid];
            #pragma unroll
            for (int r = 0; r < 4; r++)
                #pragma unroll
                for (int x = 0; x < 3; x++)
                    acc[r*3+x] += vrow[r][c*3+x] * w;
        }
        #pragma unroll
        for (int j = 0; j < 12; j++) t[j][tid] = acc[j];
    }
    __syncthreads();

    {
        int c = tid & 63, r = tid >> 6;
        float acc[3] = {0.f, 0.f, 0.f};
        #pragma unroll 4
        for (int h = 0; h < 256; h++) {
            float w2 = Wfv2[h*64 + c];
            #pragma unroll
            for (int x = 0; x < 3; x++)
                acc[x] += t[r*3+x][h] * w2;
        }
        #pragma unroll
        for (int x = 0; x < 3; x++)
            outv[(row0 + r)*192 + c*3 + x] += acc[x];
    }
}

// ---------------- fused attention: tf32 MMA flash, cp.async pipeline ---------
// k double-buffered (prefetched 1 tile ahead); v single-buffered, issued at tile
// start and awaited just before PV; posm prefetched 1 tile ahead.
#define ATK 32
#define Q_LD 260
#define K_LD 260
#define V_LD 264
#define PS2_LD 36
// floats: q 64*260 | k 2*32*260 | v 32*264 | ps 4*64*36 | posi 256 | posm 2*128
#define ATTN_SMEM_FLOATS (64*Q_LD + 2*32*K_LD + 32*V_LD + 4*64*PS2_LD + 256 + 256)

__global__ void __launch_bounds__(256) attn_kernel(
    const float* __restrict__ qg, const float* __restrict__ kg,
    const float* __restrict__ vg, const float* __restrict__ pos,
    const float* __restrict__ wdist, const float* __restrict__ bdist,
    __nv_bfloat16* __restrict__ probsG, float* __restrict__ linvG,
    float* __restrict__ sattn)
{
    extern __shared__ float sm[];
    float* q_s  = sm;                        // [64][260] tf32 (RN cvt)
    float* k_s  = q_s + 64*Q_LD;             // [2][32][260] raw fp32
    float* v_s  = k_s + 2*32*K_LD;           // [32][264] raw fp32
    float* ps   = v_s + 32*V_LD;             // [4][64][36]
    float* posi = ps + 4*64*PS2_LD;          // [64][4]
    float* posm = posi + 256;                // [2][32][4]

    const int b  = blockIdx.y;
    const int n0 = blockIdx.x * 64;
    const int tid = threadIdx.x;
    const int lane = tid & 31, wid = tid >> 5;
    const int h  = wid >> 1;
    const int wm = (wid & 1) * 32;
    const int gr = lane >> 2, gc = lane & 3;
    const long long bofs = (long long)b * Nn;

    // q tile (RN tf32 cvt) + posi
    for (int idx = tid; idx < 4096; idx += 256) {
        int i = idx >> 6, d4 = (idx & 63) << 2;
        float4 qv = *(const float4*)(qg + (bofs + n0 + i)*Ss + d4);
        float* dst = q_s + i*Q_LD + d4;
        dst[0] = f2tff(qv.x); dst[1] = f2tff(qv.y);
        dst[2] = f2tff(qv.z); dst[3] = f2tff(qv.w);
    }
    if (tid < 64) {
        const float* pp = pos + (bofs + n0 + tid)*3;
        float a = pp[0], b2 = pp[1], c = pp[2];
        posi[tid*4+0]=a; posi[tid*4+1]=b2; posi[tid*4+2]=c; posi[tid*4+3]=a*a+b2*b2+c*c;
    }
    const float wh = wdist[h], bh = bdist[h];

    float accO[2][8][4];
    #pragma unroll
    for (int mt = 0; mt < 2; mt++)
        #pragma unroll
        for (int nt = 0; nt < 8; nt++)
            #pragma unroll
            for (int j = 0; j < 4; j++) accO[mt][nt][j] = 0.f;
    float rs[2][2] = {{0.f,0.f},{0.f,0.f}};

    __nv_bfloat16* pgbase = probsG + ((size_t)(b*4 + h)*Nn + n0)*Nn;
    float* psh = ps + h*64*PS2_LD;

    // prologue: cp.async k(0) -> buf0, posm(0)
    {
        const float* kgp = kg + bofs*Ss;
        for (int idx = tid; idx < 2048; idx += 256) {
            int m = idx >> 6, d4 = (idx & 63) << 2;
            cp16(k_s + m*K_LD + d4, kgp + (long long)m*Ss + d4);
        }
        CP_COMMIT();
        if (tid < 32) {
            const float* pp = pos + (bofs + tid)*3;
            float a = pp[0], b2 = pp[1], c = pp[2];
            posm[tid*4+0]=a; posm[tid*4+1]=b2; posm[tid*4+2]=c; posm[tid*4+3]=a*a+b2*b2+c*c;
        }
    }

    for (int t64 = 0; t64 < 64; t64++) {
        const int m0g = t64 * ATK;
        const int kb = t64 & 1;
        const bool more = (t64 + 1) < 64;

        CP_WAIT0();                       // k(t) complete
        __syncthreads();                  // k(t), posm(t) visible; PV(t-1) done by all

        // issue v(t) (group V_t)
        {
            const float* vgp = vg + (bofs + m0g)*(long long)Ss;
            for (int idx = tid; idx < 2048; idx += 256) {
                int m = idx >> 6, d4 = (idx & 63) << 2;
                cp16(v_s + m*V_LD + d4, vgp + (long long)m*Ss + d4);
            }
            CP_COMMIT();
        }
        // issue k(t+1) (group K_{t+1}) + posm(t+1)
        if (more) {
            const float* kgp = kg + (bofs + m0g + ATK)*(long long)Ss;
            float* kd = k_s + (kb^1)*32*K_LD;
            for (int idx = tid; idx < 2048; idx += 256) {
                int m = idx >> 6, d4 = (idx & 63) << 2;
                cp16(kd + m*K_LD + d4, kgp + (long long)m*Ss + d4);
            }
            CP_COMMIT();
            if (tid < 32) {
                const float* pp = pos + (bofs + m0g + ATK + tid)*3;
                float a = pp[0], b2 = pp[1], c = pp[2];
                float* pm = posm + (kb^1)*128;
                pm[tid*4+0]=a; pm[tid*4+1]=b2; pm[tid*4+2]=c; pm[tid*4+3]=a*a+b2*b2+c*c;
            }
        }

        const float* kbuf = k_s + kb*32*K_LD;
        const float* pmv_buf = posm + kb*128;

        // ---- QK^T tf32 MMA: M=32, N=32 kv, K=64 ----
        float acc[2][4][4];
        #pragma unroll
        for (int mt = 0; mt < 2; mt++)
            #pragma unroll
            for (int nt = 0; nt < 4; nt++)
                #pragma unroll
                for (int j = 0; j < 4; j++) acc[mt][nt][j] = 0.f;

        #pragma unroll
        for (int kk = 0; kk < 64; kk += 8) {
            unsigned af[2][4];
            #pragma unroll
            for (int mt = 0; mt < 2; mt++) {
                const float* qp = q_s + (wm + mt*16 + gr)*Q_LD + h*64 + kk + gc;
                af[mt][0] = __float_as_uint(qp[0]);
                af[mt][1] = __float_as_uint(qp[8*Q_LD]);
                af[mt][2] = __float_as_uint(qp[4]);
                af[mt][3] = __float_as_uint(qp[8*Q_LD+4]);
            }
            #pragma unroll
            for (int nt = 0; nt < 4; nt++) {
                const float* kp = kbuf + (nt*8 + gr)*K_LD + h*64 + kk + gc;
                unsigned b0 = __float_as_uint(kp[0]);
                unsigned b1 = __float_as_uint(kp[4]);
                mma_tf32(acc[0][nt], af[0][0], af[0][1], af[0][2], af[0][3], b0, b1);
                mma_tf32(acc[1][nt], af[1][0], af[1][1], af[1][2], af[1][3], b0, b1);
            }
        }

        // ---- score math -> ps (tf32) + probsG (bf16) + rs ----
        #pragma unroll
        for (int mt = 0; mt < 2; mt++) {
            int r0 = wm + mt*16 + gr;
            float4 pi0 = ((const float4*)posi)[r0];
            float4 pi1 = ((const float4*)posi)[r0+8];
            #pragma unroll
            for (int nt = 0; nt < 4; nt++) {
                int mloc = nt*8 + gc*2;
                float4 pm0 = ((const float4*)pmv_buf)[mloc];
                float4 pm1 = ((const float4*)pmv_buf)[mloc+1];
                float p4[4];
                #pragma unroll
                for (int e = 0; e < 4; e++) {
                    float4 pi = (e < 2) ? pi0 : pi1;
                    float4 pm = (e & 1) ? pm1 : pm0;
                    float d2 = pi.w + pm.w - 2.f*(pi.x*pm.x + pi.y*pm.y + pi.z*pm.z);
                    d2 = fmaxf(d2, 1e-12f);
                    float dist = d2 * rsqrtf(d2);
                    float sx = dist*wh + bh;
                    float sg = __fdividef(1.f, 1.f + __expf(sx));
                    p4[e] = __expf(acc[mt][nt][e]*0.125f) * sg;
                }
                rs[mt][0] += p4[0] + p4[1];
                rs[mt][1] += p4[2] + p4[3];
                *(float2*)(psh + r0*PS2_LD + mloc) = make_float2(f2tff(p4[0]), f2tff(p4[1]));
                *(float2*)(psh + (r0+8)*PS2_LD + mloc) = make_float2(f2tff(p4[2]), f2tff(p4[3]));
                __nv_bfloat162 q01 = __floats2bfloat162_rn(p4[0], p4[1]);
                __nv_bfloat162 q23 = __floats2bfloat162_rn(p4[2], p4[3]);
                __stcs((unsigned int*)(pgbase + (size_t)r0*Nn + m0g + mloc),
                       *(unsigned int*)&q01);
                __stcs((unsigned int*)(pgbase + (size_t)(r0+8)*Nn + m0g + mloc),
                       *(unsigned int*)&q23);
            }
        }

        // wait for v(t): allow K_{t+1} to stay in flight
        if (more) { CP_WAIT1(); } else { CP_WAIT0(); }
        __syncthreads();                  // v(t) + all warps' ps visible

        // ---- P @ V tf32 MMA: M=32, N=64 head cols, K=32 kv ----
        #pragma unroll
        for (int kk = 0; kk < 32; kk += 8) {
            unsigned af[2][4];
            #pragma unroll
            for (int mt = 0; mt < 2; mt++) {
                const float* pp = psh + (wm + mt*16 + gr)*PS2_LD + kk + gc;
                af[mt][0] = __float_as_uint(pp[0]);
                af[mt][1] = __float_as_uint(pp[8*PS2_LD]);
                af[mt][2] = __float_as_uint(pp[4]);
                af[mt][3] = __float_as_uint(pp[8*PS2_LD+4]);
            }
            #pragma unroll
            for (int nt = 0; nt < 8; nt++) {
                const float* vp2 = v_s + (kk+gc)*V_LD + h*64 + nt*8 + gr;
                unsigned b0 = __float_as_uint(vp2[0]);
                unsigned b1 = __float_as_uint(vp2[4*V_LD]);
                mma_tf32(accO[0][nt], af[0][0], af[0][1], af[0][2], af[0][3], b0, b1);
                mma_tf32(accO[1][nt], af[1][0], af[1][1], af[1][2], af[1][3], b0, b1);
            }
        }
    }

    float linv[2][2];
    #pragma unroll
    for (int mt = 0; mt < 2; mt++)
        #pragma unroll
        for (int hh = 0; hh < 2; hh++) {
            float v = rs[mt][hh];
            v += __shfl_xor_sync(0xffffffffu, v, 1);
            v += __shfl_xor_sync(0xffffffffu, v, 2);
            linv[mt][hh] = __fdividef(1.f, v);
        }
    if (gc == 0) {
        #pragma unroll
        for (int mt = 0; mt < 2; mt++) {
            int r0 = wm + mt*16 + gr;
            linvG[(size_t)(b*4 + h)*Nn + n0 + r0]     = linv[mt][0];
            linvG[(size_t)(b*4 + h)*Nn + n0 + r0 + 8] = linv[mt][1];
        }
    }
    #pragma unroll
    for (int mt = 0; mt < 2; mt++) {
        #pragma unroll
        for (int nt = 0; nt < 8; nt++) {
            int col = h*64 + nt*8 + gc*2;
            int r0 = wm + mt*16 + gr;
            float2 o0, o1;
            o0.x = accO[mt][nt][0]*linv[mt][0];
            o0.y = accO[mt][nt][1]*linv[mt][0];
            o1.x = accO[mt][nt][2]*linv[mt][1];
            o1.y = accO[mt][nt][3]*linv[mt][1];
            *(float2*)(sattn + (bofs + n0 + r0)*Ss + col) = o0;
            *(float2*)(sattn + (bofs + n0 + r0 + 8)*Ss + col) = o1;
        }
    }
}

// ---------------- launch ------------------------------------------------------
extern "C" void kernel_launch(void* const* d_in, const int* in_sizes, int n_in,
                              void* d_out, int out_size)
{
    const float* s_in  = (const float*)d_in[0];
    const float* v_in  = (const float*)d_in[1];
    const float* pos   = (const float*)d_in[2];
    const float* Wq    = (const float*)d_in[3];
    const float* bq    = (const float*)d_in[4];
    const float* Wk    = (const float*)d_in[5];
    const float* bk    = (const float*)d_in[6];
    const float* Wv    = (const float*)d_in[7];
    const float* bv    = (const float*)d_in[8];
    const float* Wo    = (const float*)d_in[9];
    const float* bo    = (const float*)d_in[10];
    const float* wdist = (const float*)d_in[11];
    const float* bdist = (const float*)d_in[12];
    const float* Wvv   = (const float*)d_in[13];
    const float* Wvo   = (const float*)d_in[14];
    const float* g1    = (const float*)d_in[15];
    const float* be1   = (const float*)d_in[16];
    const float* vs1   = (const float*)d_in[17];
    const float* g2    = (const float*)d_in[18];
    const float* be2   = (const float*)d_in[19];
    const float* vs2   = (const float*)d_in[20];
    const float* Wf1   = (const float*)d_in[21];
    const float* bf1   = (const float*)d_in[22];
    const float* Wf2   = (const float*)d_in[23];
    const float* bf2   = (const float*)d_in[24];
    const float* Wfv1  = (const float*)d_in[25];
    const float* Wfv2  = (const float*)d_in[26];

    float* out_s = (float*)d_out;
    float* out_v = out_s + (size_t)ROWS*Ss;

    void *p_sn, *p_vn, *p_q, *p_k, *p_vp, *p_vmix, *p_pb, *p_li, *p_sa, *p_va, *p_ffn;
    cudaGetSymbolAddress(&p_sn, g_sn);
    cudaGetSymbolAddress(&p_vn, g_vn);
    cudaGetSymbolAddress(&p_q,  g_q);
    cudaGetSymbolAddress(&p_k,  g_k);
    cudaGetSymbolAddress(&p_vp, g_vp);
    cudaGetSymbolAddress(&p_vmix, g_vmix);
    cudaGetSymbolAddress(&p_pb, g_probs);
    cudaGetSymbolAddress(&p_li, g_linv);
    cudaGetSymbolAddress(&p_sa, g_sattn);
    cudaGetSymbolAddress(&p_va, g_vattn);
    cudaGetSymbolAddress(&p_ffn, g_ffn);
    float* sn   = (float*)p_sn;   float* vn   = (float*)p_vn;
    float* q    = (float*)p_q;    float* k    = (float*)p_k;
    float* vp   = (float*)p_vp;   float* vmix = (float*)p_vmix;
    __nv_bfloat16* pb = (__nv_bfloat16*)p_pb;
    float* li   = (float*)p_li;
    float* sa   = (float*)p_sa;   float* va   = (float*)p_va;
    float* ffn  = (float*)p_ffn;

    const int attn_smem = ATTN_SMEM_FLOATS * 4;
    cudaFuncSetAttribute(attn_kernel, cudaFuncAttributeMaxDynamicSharedMemorySize, attn_smem);
    cudaFuncSetAttribute(gemm_tc_kernel, cudaFuncAttributeMaxDynamicSharedMemorySize, GEMM_TC_SMEM);
    cudaFuncSetAttribute(qkv_tc_kernel, cudaFuncAttributeMaxDynamicSharedMemorySize, GEMM_TC_SMEM);
    cudaFuncSetAttribute(vattn_tc_kernel, cudaFuncAttributeMaxDynamicSharedMemorySize, VATTN_SMEM);

    // 1) eq-LN #1 (+ fused vmix = vn @ Wvv)
    eqln_kernel<<<ROWS, 256>>>(s_in, v_in, g1, be1, vs1, sn, vn, Wvv, vmix);

    // 2) QKV projections, single batched launch (bf16 tensor cores)
    qkv_tc_kernel<<<dim3(Ss/64, ROWS/128, 3), 256, GEMM_TC_SMEM>>>(
        sn, Wq, bq, q, Wk, bk, k, Wv, bv, vp);

    // 3) fused single-pass tf32-MMA attention (cp.async pipelined)
    attn_kernel<<<dim3(Nn/64, Bb), 256, attn_smem>>>(q, k, vp, pos, wdist, bdist, pb, li, sa);

    // 4) fused v_attn = (0.25*sum_h linv*probs) @ vmix  (bf16 MMA, reads bf16 probs)
    vattn_tc_kernel<<<dim3(Nn/64, Bb), 256, VATTN_SMEM>>>(pb, li, vmix, va);

    // 5) out_s = s_in + sattn @ Wo + bo
    gemm_tc_kernel<<<dim3(Ss/64, ROWS/128, 1), 256, GEMM_TC_SMEM>>>(sa, Wo, bo, s_in, out_s, ROWS, Ss, Ss, 2);

    // 6) out_v = v_in + v_attn @ Wvo
    vout_kernel<<<ROWS, 192>>>(va, Wvo, v_in, out_v);

    // 7) eq-LN #2 (no vmix)
    eqln_kernel<<<ROWS, 256>>>(out_s, out_v, g2, be2, vs2, sn, vn, nullptr, nullptr);

    // 8) FFN (bf16 tensor cores, GELU + residual epilogues)
    gemm_tc_kernel<<<dim3(Ff/64, ROWS/128, 1), 256, GEMM_TC_SMEM>>>(sn, Wf1, bf1, nullptr, ffn, ROWS, Ff, Ss, 1);
    gemm_tc_kernel<<<dim3(Ss/64, ROWS/128, 1), 256, GEMM_TC_SMEM>>>(ffn, Wf2, bf2, out_s, out_s, ROWS, Ss, Ff, 2);

    // 9) vector FFN (4 rows per CTA)
    vffn_kernel<<<ROWS/4, 256>>>(vn, Wfv1, Wfv2, out_v);
}